// round 10
// baseline (speedup 1.0000x reference)
#include <cuda_runtime.h>
#include <cuda_fp16.h>
#include <cstdint>

#define BB   16
#define NNN  32
#define SS   128
#define DD   512
#define HH   8
#define NTOK (BB*NNN*SS)          // 65536
#define YSIZE  (NTOK*DD)          // 33554432

// ---------------- scratch ----------------
__device__ __half g_whi[4ull*DD*DD];      // weights hi
__device__ __half g_wlo[4ull*DD*DD];      // weights lo
__device__ __half g_qh[(size_t)NTOK*DD];  // Q proj hi
__device__ __half g_ql[(size_t)NTOK*DD];  // Q proj lo
__device__ __half g_kf[(size_t)NTOK*DD];  // K proj single
__device__ __half g_vf[(size_t)NTOK*DD];  // V proj single
__device__ __half g_resf[(size_t)NTOK*DD];// attn result single
__device__ __half g_outp[(size_t)NTOK*DD];// FC result f16
__device__ int    g_flag_float, g_flag_not01;

// ---------------- mask dtype detection ----------------
__global__ void detect_reset() { g_flag_float = 0; g_flag_not01 = 0; }
__global__ __launch_bounds__(256) void detect_scan(const uint4* __restrict__ mw) {
    int i = blockIdx.x * 256 + threadIdx.x;
    uint4 w = mw[i];
    int isf = (w.x == 0x3f800000u) | (w.y == 0x3f800000u) | (w.z == 0x3f800000u) | (w.w == 0x3f800000u);
    int n01 = ((w.x > 1u) & (w.x != 0x3f800000u)) | ((w.y > 1u) & (w.y != 0x3f800000u))
            | ((w.z > 1u) & (w.z != 0x3f800000u)) | ((w.w > 1u) & (w.w != 0x3f800000u));
    int bf = __syncthreads_or(isf);
    int bn = __syncthreads_or(n01);
    if (threadIdx.x == 0) {
        if (bf) atomicOr(&g_flag_float, 1);
        if (bn) atomicOr(&g_flag_not01, 1);
    }
}

// ---------------- helpers ----------------
__device__ __forceinline__ unsigned pack_f16(float lo, float hi) {
    __half2 h = __floats2half2_rn(lo, hi);
    return *(unsigned*)&h;
}
__device__ __forceinline__ float f16lo(unsigned u) { return __low2float(*(__half2*)&u); }
__device__ __forceinline__ float f16hi(unsigned u) { return __high2float(*(__half2*)&u); }

__device__ __forceinline__ void mma16816(float c[4],
    unsigned a0, unsigned a1, unsigned a2, unsigned a3, unsigned b0, unsigned b1)
{
    asm volatile(
        "mma.sync.aligned.m16n8k16.row.col.f32.f16.f16.f32 "
        "{%0,%1,%2,%3}, {%4,%5,%6,%7}, {%8,%9}, {%0,%1,%2,%3};"
        : "+f"(c[0]), "+f"(c[1]), "+f"(c[2]), "+f"(c[3])
        : "r"(a0), "r"(a1), "r"(a2), "r"(a3), "r"(b0), "r"(b1));
}
__device__ __forceinline__ void cpa16(uint32_t s, const void* g) {
    asm volatile("cp.async.cg.shared.global [%0], [%1], 16;" :: "r"(s), "l"(g));
}
__device__ __forceinline__ void ldsm4(unsigned& r0, unsigned& r1, unsigned& r2, unsigned& r3, uint32_t a) {
    asm volatile("ldmatrix.sync.aligned.m8n8.x4.shared.b16 {%0,%1,%2,%3}, [%4];"
        : "=r"(r0), "=r"(r1), "=r"(r2), "=r"(r3) : "r"(a));
}
__device__ __forceinline__ void ldsm4t(unsigned& r0, unsigned& r1, unsigned& r2, unsigned& r3, uint32_t a) {
    asm volatile("ldmatrix.sync.aligned.m8n8.x4.trans.shared.b16 {%0,%1,%2,%3}, [%4];"
        : "=r"(r0), "=r"(r1), "=r"(r2), "=r"(r3) : "r"(a));
}
__device__ __forceinline__ void stcs2(float* p, float a, float b) {
    asm volatile("st.global.cs.v2.f32 [%0], {%1,%2};" :: "l"(p), "f"(a), "f"(b) : "memory");
}

// ---------------- fp32 -> f16 hi/lo (4 weights merged) ----------------
__global__ __launch_bounds__(256) void split4_kernel(
    const float* __restrict__ s0, const float* __restrict__ s1,
    const float* __restrict__ s2, const float* __restrict__ s3,
    __half* __restrict__ hi, __half* __restrict__ lo, int n4)
{
    int b = blockIdx.x;
    int sel = b / (n4 / 256);
    int i = (b % (n4 / 256)) * 256 + threadIdx.x;
    const float* src = sel == 0 ? s0 : (sel == 1 ? s1 : (sel == 2 ? s2 : s3));
    float4 v = ((const float4*)src)[i];
    unsigned h01 = pack_f16(v.x, v.y), h23 = pack_f16(v.z, v.w);
    unsigned l01 = pack_f16(v.x - f16lo(h01), v.y - f16hi(h01));
    unsigned l23 = pack_f16(v.z - f16lo(h23), v.w - f16hi(h23));
    size_t o = (size_t)sel * n4 + i;
    ((uint2*)hi)[o] = make_uint2(h01, h23);
    ((uint2*)lo)[o] = make_uint2(l01, l23);
}

// ---------------- GEMM stage layout ----------------
// Stage: A f16 @0 (8KB), Bh @8192, Bl @16384 (128 rows x 32 f16, 64B rows, swizzle ch^((row>>1)&3))
#define GSTG 24576
#define GEMM_SMEM (3*GSTG)
#define NE_C ((size_t)NTOK * DD)
#define WE_C ((size_t)DD * DD)

// merged QKV projection with fused fp32->f16 A conversion.
// grid (12, M/128); px = bx>>2 (0=Q,1=K,2=V), n-tile = bx&3.
__global__ __launch_bounds__(256, 2) void qkv_gemm(
    const float* __restrict__ Qf, const float* __restrict__ Kf, const float* __restrict__ Vf,
    const __half* __restrict__ whi, const __half* __restrict__ wlo,
    __half* __restrict__ qh, __half* __restrict__ ql,
    __half* __restrict__ kf, __half* __restrict__ vf)
{
    extern __shared__ char gsm[];
    const int tid = threadIdx.x;
    const int lane = tid & 31, wid = tid >> 5;
    const int wm = wid & 1, wn = wid >> 1;
    const int g = lane >> 2, q = lane & 3;
    const int lrow = (lane & 7) + ((lane >> 3) & 1) * 8;
    const int lch  = lane >> 4;
    const int px = blockIdx.x >> 2;
    const int n0 = (blockIdx.x & 3) * 128, m0 = blockIdx.y * 128;
    const int K = DD, N = DD;
    uint32_t sb = (uint32_t)__cvta_generic_to_shared(gsm);

    const float*  Afp = px == 0 ? Qf : (px == 1 ? Kf : Vf);
    const __half* Bhi = whi + (size_t)px * WE_C;
    const __half* Blo = wlo + (size_t)px * WE_C;

    // per-thread A addressing: idx = tid + j*256; row = idx>>3, c4 = idx&7 (float4 granule)
    const int arow[4] = { (tid + 0) >> 3, (tid + 256) >> 3, (tid + 512) >> 3, (tid + 768) >> 3 };
    const int ac4 = tid & 7;
    // STS byte offset within stage (granule ch = ac4>>1, half = ac4&1)
    uint32_t asts[4];
#pragma unroll
    for (int j = 0; j < 4; j++)
        asts[j] = arow[j] * 64 + ((((ac4 >> 1) ^ ((arow[j] >> 1) & 3))) << 4) + (ac4 & 1) * 8;

    uint2 aregs[4];

    auto ldgA = [&](int grp) {
        int k0 = grp << 5;
#pragma unroll
        for (int j = 0; j < 4; j++) {
            float4 v = *(const float4*)(Afp + (size_t)(m0 + arow[j]) * K + k0 + ac4 * 4);
            aregs[j] = make_uint2(pack_f16(v.x, v.y), pack_f16(v.z, v.w));
        }
    };
    auto stsA = [&](int grp) {
        char* stg = gsm + (grp % 3) * GSTG;
#pragma unroll
        for (int j = 0; j < 4; j++)
            *(uint2*)(stg + asts[j]) = aregs[j];
    };
    auto issueB = [&](int grp) {
        int k0 = grp << 5;
        uint32_t stg = sb + (grp % 3) * GSTG;
#pragma unroll
        for (int j = 0; j < 4; j++) {
            int idx = tid + (j & 1) * 256;
            int sub = j >> 1;                // 0: Bh, 1: Bl
            int row = idx >> 2, ch = idx & 3;
            const __half* gp = (sub == 0 ? Bhi : Blo) + (size_t)(n0 + row) * K + k0 + ch * 8;
            cpa16(stg + 8192 + sub * 8192 + row * 64 + (((ch ^ ((row >> 1) & 3))) << 4), gp);
        }
        asm volatile("cp.async.commit_group;");
    };

    float acc[4][4][4] = {};
    const int nIter = K >> 5;   // 16

    // prologue
    ldgA(0); stsA(0);
    issueB(0);
    ldgA(1);                    // held in regs, stored at iter 0
    issueB(1);

    for (int it = 0; it < nIter; it++) {
        if (it < nIter - 1) asm volatile("cp.async.wait_group 1;");
        else                asm volatile("cp.async.wait_group 0;");
        __syncthreads();
        if (it + 1 < nIter) stsA(it + 1);
        if (it + 2 < nIter) { ldgA(it + 2); issueB(it + 2); }
        uint32_t bufb = sb + (it % 3) * GSTG;
#pragma unroll
        for (int kb = 0; kb < 32; kb += 16) {
            int c0 = kb >> 3;
            unsigned af[4][4];
#pragma unroll
            for (int i = 0; i < 4; i++) {
                int row = wm * 64 + i * 16 + lrow;
                uint32_t a = bufb + row * 64 + ((((c0 + lch) ^ ((row >> 1) & 3))) << 4);
                ldsm4(af[i][0], af[i][1], af[i][2], af[i][3], a);
            }
            unsigned bh[2][4], bl[2][4];
#pragma unroll
            for (int p = 0; p < 2; p++) {
                int row = wn * 32 + p * 16 + lrow;
                uint32_t b = bufb + 8192 + row * 64 + ((((c0 + lch) ^ ((row >> 1) & 3))) << 4);
                ldsm4(bh[p][0], bh[p][1], bh[p][2], bh[p][3], b);
                ldsm4(bl[p][0], bl[p][1], bl[p][2], bl[p][3], b + 8192);
            }
#pragma unroll
            for (int j = 0; j < 4; j++) {
                int p = j >> 1, o = j & 1;
                unsigned b0h = bh[p][o], b1h = bh[p][o + 2];
                unsigned b0l = bl[p][o], b1l = bl[p][o + 2];
#pragma unroll
                for (int i = 0; i < 4; i++) {
                    mma16816(acc[i][j], af[i][0], af[i][1], af[i][2], af[i][3], b0h, b1h);
                    mma16816(acc[i][j], af[i][0], af[i][1], af[i][2], af[i][3], b0l, b1l);
                }
            }
        }
    }

    __half* Chi = px == 0 ? qh : (px == 1 ? kf : vf);
#pragma unroll
    for (int i = 0; i < 4; i++) {
#pragma unroll
        for (int j = 0; j < 4; j++) {
            int row = m0 + wm * 64 + i * 16 + g;
            int col = n0 + wn * 32 + j * 8 + 2 * q;
            unsigned h01 = pack_f16(acc[i][j][0], acc[i][j][1]);
            unsigned h23 = pack_f16(acc[i][j][2], acc[i][j][3]);
            *(unsigned*)&Chi[(size_t)row * N + col]       = h01;
            *(unsigned*)&Chi[(size_t)(row + 8) * N + col] = h23;
            if (px == 0) {
                unsigned l01 = pack_f16(acc[i][j][0] - f16lo(h01), acc[i][j][1] - f16hi(h01));
                unsigned l23 = pack_f16(acc[i][j][2] - f16lo(h23), acc[i][j][3] - f16hi(h23));
                *(unsigned*)&ql[(size_t)row * N + col]       = l01;
                *(unsigned*)&ql[(size_t)(row + 8) * N + col] = l23;
            }
        }
    }
}

// FC GEMM: A already f16 (resf), single f16 out
__global__ __launch_bounds__(256, 2) void fc_gemm(
    const __half* __restrict__ Af,
    const __half* __restrict__ Bhi, const __half* __restrict__ Blo,
    __half* __restrict__ Chi)
{
    extern __shared__ char gsm[];
    const int tid = threadIdx.x;
    const int lane = tid & 31, wid = tid >> 5;
    const int wm = wid & 1, wn = wid >> 1;
    const int g = lane >> 2, q = lane & 3;
    const int lrow = (lane & 7) + ((lane >> 3) & 1) * 8;
    const int lch  = lane >> 4;
    const int n0 = blockIdx.x * 128, m0 = blockIdx.y * 128;
    const int K = DD, N = DD;
    uint32_t sb = (uint32_t)__cvta_generic_to_shared(gsm);

    auto issue = [&](int grp) {
        int k0 = grp << 5;
        uint32_t stg = sb + (grp % 3) * GSTG;
#pragma unroll
        for (int j = 0; j < 6; j++) {
            int idx = tid + j * 256;
            int sub = j >> 1;
            int t2 = idx & 511;
            int row = t2 >> 2, ch = t2 & 3;
            const __half* gp;
            if (sub == 0)      gp = Af  + (size_t)(m0 + row) * K + k0 + ch * 8;
            else if (sub == 1) gp = Bhi + (size_t)(n0 + row) * K + k0 + ch * 8;
            else               gp = Blo + (size_t)(n0 + row) * K + k0 + ch * 8;
            cpa16(stg + sub * 8192 + row * 64 + (((ch ^ ((row >> 1) & 3))) << 4), gp);
        }
        asm volatile("cp.async.commit_group;");
    };

    float acc[4][4][4] = {};
    const int nIter = K >> 5;
    issue(0); issue(1);

    for (int it = 0; it < nIter; it++) {
        if (it < nIter - 1) asm volatile("cp.async.wait_group 1;");
        else                asm volatile("cp.async.wait_group 0;");
        __syncthreads();
        if (it + 2 < nIter) issue(it + 2);
        uint32_t bufb = sb + (it % 3) * GSTG;
#pragma unroll
        for (int kb = 0; kb < 32; kb += 16) {
            int c0 = kb >> 3;
            unsigned af[4][4];
#pragma unroll
            for (int i = 0; i < 4; i++) {
                int row = wm * 64 + i * 16 + lrow;
                uint32_t a = bufb + row * 64 + ((((c0 + lch) ^ ((row >> 1) & 3))) << 4);
                ldsm4(af[i][0], af[i][1], af[i][2], af[i][3], a);
            }
            unsigned bh[2][4], bl[2][4];
#pragma unroll
            for (int p = 0; p < 2; p++) {
                int row = wn * 32 + p * 16 + lrow;
                uint32_t b = bufb + 8192 + row * 64 + ((((c0 + lch) ^ ((row >> 1) & 3))) << 4);
                ldsm4(bh[p][0], bh[p][1], bh[p][2], bh[p][3], b);
                ldsm4(bl[p][0], bl[p][1], bl[p][2], bl[p][3], b + 8192);
            }
#pragma unroll
            for (int j = 0; j < 4; j++) {
                int p = j >> 1, o = j & 1;
                unsigned b0h = bh[p][o], b1h = bh[p][o + 2];
                unsigned b0l = bl[p][o], b1l = bl[p][o + 2];
#pragma unroll
                for (int i = 0; i < 4; i++) {
                    mma16816(acc[i][j], af[i][0], af[i][1], af[i][2], af[i][3], b0h, b1h);
                    mma16816(acc[i][j], af[i][0], af[i][1], af[i][2], af[i][3], b0l, b1l);
                }
            }
        }
    }

#pragma unroll
    for (int i = 0; i < 4; i++) {
#pragma unroll
        for (int j = 0; j < 4; j++) {
            int row = m0 + wm * 64 + i * 16 + g;
            int col = n0 + wn * 32 + j * 8 + 2 * q;
            *(unsigned*)&Chi[(size_t)row * N + col]       = pack_f16(acc[i][j][0], acc[i][j][1]);
            *(unsigned*)&Chi[(size_t)(row + 8) * N + col] = pack_f16(acc[i][j][2], acc[i][j][3]);
        }
    }
}

// ---------------- attention: 128 q-rows/CTA, register softmax ----------------
#define AK_OFF  0
#define AV_OFF  16384
#define AQH_OFF 32768
#define AQL_OFF 49152
#define AP_OFF  32768
#define AM_OFF  65536
#define ASTM_OFF 81920
#define ASTS_OFF 83968
#define ATTN_SMEM 86016

__global__ __launch_bounds__(256, 2) void attn_mma(
    const __half* __restrict__ qhi, const __half* __restrict__ qlo,
    const __half* __restrict__ kf, const __half* __restrict__ vf,
    const void* __restrict__ mask, float* __restrict__ attn_out,
    __half* __restrict__ resf)
{
    extern __shared__ char smc[];
    uint32_t sb = (uint32_t)__cvta_generic_to_shared(smc);
    float* stM = (float*)(smc + ASTM_OFF);
    float* stS = (float*)(smc + ASTS_OFF);

    const int tid = threadIdx.x;
    const int lane = tid & 31, wid = tid >> 5;
    const int g = lane >> 2, q = lane & 3;
    const int lrow = (lane & 7) + ((lane >> 3) & 1) * 8;
    const int lch  = lane >> 4;
    const int h  = blockIdx.x & 7;
    const int bn = blockIdx.x >> 3;
    const int kind = g_flag_not01 ? 2 : (g_flag_float ? 1 : 0);

    const size_t base = (size_t)bn * 128 * DD + (size_t)h * 64;

    // group 0: K, Qh, Ql
    {
#pragma unroll
        for (int t = 0; t < 4; t++) {
            int idx = tid + t * 256;
            int row = idx >> 3, ch = idx & 7;
            uint32_t sw = row * 128 + (((ch ^ (row & 7))) << 4);
            size_t go = base + (size_t)row * DD + ch * 8;
            cpa16(sb + AK_OFF  + sw, kf  + go);
            cpa16(sb + AQH_OFF + sw, qhi + go);
            cpa16(sb + AQL_OFF + sw, qlo + go);
        }
        asm volatile("cp.async.commit_group;");
    }
    // group 1: V (+ mask if u8)
    {
#pragma unroll
        for (int t = 0; t < 4; t++) {
            int idx = tid + t * 256;
            int row = idx >> 3, ch = idx & 7;
            uint32_t sw = row * 128 + (((ch ^ (row & 7))) << 4);
            cpa16(sb + AV_OFF + sw, vf + base + (size_t)row * DD + ch * 8);
        }
        if (kind == 2) {
#pragma unroll
            for (int t = 0; t < 4; t++) {
                int idx = tid + t * 256;
                int row = idx >> 3, ch = idx & 7;
                cpa16(sb + AM_OFF + row * 128 + ch * 16,
                      (const unsigned char*)mask + (size_t)bn * 16384 + (size_t)row * 128 + ch * 16);
            }
        }
        asm volatile("cp.async.commit_group;");
    }
    asm volatile("cp.async.wait_group 1;");
    __syncthreads();

    const int wm = wid & 1, wn = wid >> 1;

    // QK^T
    float acc[4][4][4] = {};
#pragma unroll
    for (int kb = 0; kb < 64; kb += 16) {
        int c0 = kb >> 3;
        unsigned ah[4][4], al[4][4];
#pragma unroll
        for (int i = 0; i < 4; i++) {
            int row = wm * 64 + i * 16 + lrow;
            uint32_t a = sb + AQH_OFF + row * 128 + ((((c0 + lch) ^ (row & 7))) << 4);
            ldsm4(ah[i][0], ah[i][1], ah[i][2], ah[i][3], a);
            ldsm4(al[i][0], al[i][1], al[i][2], al[i][3], a + 16384);
        }
        unsigned bk[2][4];
#pragma unroll
        for (int p = 0; p < 2; p++) {
            int row = wn * 32 + p * 16 + lrow;
            uint32_t b = sb + AK_OFF + row * 128 + ((((c0 + lch) ^ (row & 7))) << 4);
            ldsm4(bk[p][0], bk[p][1], bk[p][2], bk[p][3], b);
        }
#pragma unroll
        for (int j = 0; j < 4; j++) {
            int p = j >> 1, o = j & 1;
            unsigned b0 = bk[p][o], b1 = bk[p][o + 2];
#pragma unroll
            for (int i = 0; i < 4; i++) {
                mma16816(acc[i][j], ah[i][0], ah[i][1], ah[i][2], ah[i][3], b0, b1);
                mma16816(acc[i][j], al[i][0], al[i][1], al[i][2], al[i][3], b0, b1);
            }
        }
    }

    asm volatile("cp.async.wait_group 0;");
    __syncthreads();

    // mask + scale
#pragma unroll
    for (int i = 0; i < 4; i++) {
#pragma unroll
        for (int hf = 0; hf < 2; hf++) {
            int r = wm * 64 + i * 16 + g + hf * 8;
#pragma unroll
            for (int j = 0; j < 4; j++) {
                int c = wn * 32 + j * 8 + 2 * q;
                float m0, m1;
                if (kind == 2) {
                    uchar2 mk = *(const uchar2*)(smc + AM_OFF + r * 128 + c);
                    m0 = mk.x ? 0.f : -1e9f; m1 = mk.y ? 0.f : -1e9f;
                } else if (kind == 1) {
                    float2 mk = *(const float2*)((const float*)mask + (size_t)bn * 16384 + (size_t)r * 128 + c);
                    m0 = (mk.x != 0.f) ? 0.f : -1e9f; m1 = (mk.y != 0.f) ? 0.f : -1e9f;
                } else {
                    int2 mk = *(const int2*)((const int*)mask + (size_t)bn * 16384 + (size_t)r * 128 + c);
                    m0 = mk.x ? 0.f : -1e9f; m1 = mk.y ? 0.f : -1e9f;
                }
                acc[i][j][2 * hf]     = acc[i][j][2 * hf]     * 0.125f + m0;
                acc[i][j][2 * hf + 1] = acc[i][j][2 * hf + 1] * 0.125f + m1;
            }
        }
    }

    // row max
#pragma unroll
    for (int i = 0; i < 4; i++)
#pragma unroll
        for (int hf = 0; hf < 2; hf++) {
            float m = -3.4e38f;
#pragma unroll
            for (int j = 0; j < 4; j++)
                m = fmaxf(m, fmaxf(acc[i][j][2 * hf], acc[i][j][2 * hf + 1]));
            m = fmaxf(m, __shfl_xor_sync(0xffffffffu, m, 1));
            m = fmaxf(m, __shfl_xor_sync(0xffffffffu, m, 2));
            if (q == 0) stM[(wm * 64 + i * 16 + g + hf * 8) * 4 + wn] = m;
        }
    __syncthreads();

    float inv[4][2];
#pragma unroll
    for (int i = 0; i < 4; i++)
#pragma unroll
        for (int hf = 0; hf < 2; hf++) {
            int r = wm * 64 + i * 16 + g + hf * 8;
            float gm = fmaxf(fmaxf(stM[r * 4], stM[r * 4 + 1]), fmaxf(stM[r * 4 + 2], stM[r * 4 + 3]));
            float s = 0.f;
#pragma unroll
            for (int j = 0; j < 4; j++) {
                float e0 = __expf(acc[i][j][2 * hf]     - gm);
                float e1 = __expf(acc[i][j][2 * hf + 1] - gm);
                acc[i][j][2 * hf] = e0; acc[i][j][2 * hf + 1] = e1;
                s += e0 + e1;
            }
            s += __shfl_xor_sync(0xffffffffu, s, 1);
            s += __shfl_xor_sync(0xffffffffu, s, 2);
            if (q == 0) stS[r * 4 + wn] = s;
        }
    __syncthreads();

#pragma unroll
    for (int i = 0; i < 4; i++)
#pragma unroll
        for (int hf = 0; hf < 2; hf++) {
            int r = wm * 64 + i * 16 + g + hf * 8;
            inv[i][hf] = 1.0f / (stS[r * 4] + stS[r * 4 + 1] + stS[r * 4 + 2] + stS[r * 4 + 3]);
        }

    // normalize + attn_out (streaming) + P f16 pack
    {
        float* aout = attn_out + ((size_t)(bn * 8 + h)) * 16384;
#pragma unroll
        for (int i = 0; i < 4; i++)
#pragma unroll
            for (int hf = 0; hf < 2; hf++) {
                int r = wm * 64 + i * 16 + g + hf * 8;
                float iv = inv[i][hf];
#pragma unroll
                for (int j = 0; j < 4; j++) {
                    int c = wn * 32 + j * 8 + 2 * q;
                    float p0 = acc[i][j][2 * hf] * iv;
                    float p1 = acc[i][j][2 * hf + 1] * iv;
                    stcs2(&aout[(size_t)r * 128 + c], p0, p1);
                    uint32_t off = r * 256 + ((((c >> 3) ^ (r & 7))) << 4) + (c & 7) * 2;
                    *(unsigned*)(smc + AP_OFF + off) = pack_f16(p0, p1);
                }
            }
    }
    __syncthreads();

    // P @ V
    float ao[4][2][4] = {};
#pragma unroll
    for (int kb = 0; kb < 8; kb++) {
        int c0 = kb * 2;
        unsigned ph[4][4];
#pragma unroll
        for (int i = 0; i < 4; i++) {
            int row = wm * 64 + i * 16 + lrow;
            uint32_t a = sb + AP_OFF + row * 256 + ((((c0 + lch) ^ (row & 7))) << 4);
            ldsm4(ph[i][0], ph[i][1], ph[i][2], ph[i][3], a);
        }
        int vrow = kb * 16 + lrow;
        uint32_t vb = sb + AV_OFF + vrow * 128 + ((((wn * 2 + lch) ^ (vrow & 7))) << 4);
        unsigned vv[4];
        ldsm4t(vv[0], vv[1], vv[2], vv[3], vb);
#pragma unroll
        for (int j = 0; j < 2; j++) {
            unsigned b0 = vv[2 * j], b1 = vv[2 * j + 1];
#pragma unroll
            for (int i = 0; i < 4; i++)
                mma16816(ao[i][j], ph[i][0], ph[i][1], ph[i][2], ph[i][3], b0, b1);
        }
    }

#pragma unroll
    for (int i = 0; i < 4; i++)
#pragma unroll
        for (int j = 0; j < 2; j++) {
            int row = wm * 64 + i * 16 + g;
            int col = h * 64 + wn * 16 + j * 8 + 2 * q;
            size_t o0 = ((size_t)(bn * 128 + row)) * DD + col;
            size_t o1 = o0 + 8ull * DD;
            *(unsigned*)&resf[o0] = pack_f16(ao[i][j][0], ao[i][j][1]);
            *(unsigned*)&resf[o1] = pack_f16(ao[i][j][2], ao[i][j][3]);
        }
}

// ---------------- residual + LayerNorm: warp per row ----------------
__global__ __launch_bounds__(256) void ln_kernel(
    const __half* __restrict__ O, const float* __restrict__ X,
    const float* __restrict__ gamma, const float* __restrict__ beta,
    float* __restrict__ Y)
{
    const int lane = threadIdx.x & 31, w = threadIdx.x >> 5;
    const size_t row = (size_t)blockIdx.x * 8 + w;
    const size_t base = row * DD;

    float x[16];
    float s = 0.f, s2 = 0.f;
#pragma unroll
    for (int c = 0; c < 4; c++) {
        int col = c * 128 + lane * 4;
        uint2 o2 = *(const uint2*)&O[base + col];
        float4 xf = *(const float4*)&X[base + col];
        float v0 = f16lo(o2.x) + xf.x;
        float v1 = f16hi(o2.x) + xf.y;
        float v2 = f16lo(o2.y) + xf.z;
        float v3 = f16hi(o2.y) + xf.w;
        x[c * 4 + 0] = v0; x[c * 4 + 1] = v1; x[c * 4 + 2] = v2; x[c * 4 + 3] = v3;
        s  += v0 + v1 + v2 + v3;
        s2 += v0 * v0 + v1 * v1 + v2 * v2 + v3 * v3;
    }
#pragma unroll
    for (int o = 16; o; o >>= 1) {
        s  += __shfl_xor_sync(0xffffffffu, s,  o);
        s2 += __shfl_xor_sync(0xffffffffu, s2, o);
    }
    float mean = s * (1.0f / DD);
    float var  = s2 * (1.0f / DD) - mean * mean;
    float inv  = rsqrtf(var + 1e-5f);

#pragma unroll
    for (int c = 0; c < 4; c++) {
        int col = c * 128 + lane * 4;
        float4 gm = *(const float4*)&gamma[col];
        float4 bt = *(const float4*)&beta[col];
        float4 yv;
        yv.x = (x[c * 4 + 0] - mean) * inv * gm.x + bt.x;
        yv.y = (x[c * 4 + 1] - mean) * inv * gm.y + bt.y;
        yv.z = (x[c * 4 + 2] - mean) * inv * gm.z + bt.z;
        yv.w = (x[c * 4 + 3] - mean) * inv * gm.w + bt.w;
        *(float4*)&Y[base + col] = yv;
    }
}

// ---------------- launch ----------------
extern "C" void kernel_launch(void* const* d_in, const int* in_sizes, int n_in,
                              void* d_out, int out_size)
{
    const float* Q     = (const float*)d_in[0];
    const float* K     = (const float*)d_in[1];
    const float* V     = (const float*)d_in[2];
    const void*  mask  = d_in[3];
    const float* WQ    = (const float*)d_in[4];
    const float* WK    = (const float*)d_in[5];
    const float* WV    = (const float*)d_in[6];
    const float* Wfc   = (const float*)d_in[7];
    const float* gamma = (const float*)d_in[8];
    const float* beta  = (const float*)d_in[9];

    float* y    = (float*)d_out;
    float* attn = y + (size_t)YSIZE;

    void *p;
    cudaGetSymbolAddress(&p, g_whi);  __half* whi  = (__half*)p;
    cudaGetSymbolAddress(&p, g_wlo);  __half* wlo  = (__half*)p;
    cudaGetSymbolAddress(&p, g_qh);   __half* qh   = (__half*)p;
    cudaGetSymbolAddress(&p, g_ql);   __half* ql   = (__half*)p;
    cudaGetSymbolAddress(&p, g_kf);   __half* kf   = (__half*)p;
    cudaGetSymbolAddress(&p, g_vf);   __half* vfp  = (__half*)p;
    cudaGetSymbolAddress(&p, g_resf); __half* resf = (__half*)p;
    cudaGetSymbolAddress(&p, g_outp); __half* outp = (__half*)p;

    cudaFuncSetAttribute(qkv_gemm, cudaFuncAttributeMaxDynamicSharedMemorySize, GEMM_SMEM);
    cudaFuncSetAttribute(fc_gemm,  cudaFuncAttributeMaxDynamicSharedMemorySize, GEMM_SMEM);
    cudaFuncSetAttribute(attn_mma, cudaFuncAttributeMaxDynamicSharedMemorySize, ATTN_SMEM);

    detect_reset<<<1, 1>>>();
    detect_scan<<<64, 256>>>((const uint4*)mask);

    const int w4 = (int)(WE_C / 4);
    split4_kernel<<<4 * (w4 / 256), 256>>>(WQ, WK, WV, Wfc, whi, wlo, w4);

    qkv_gemm<<<dim3(12, NTOK / 128), 256, GEMM_SMEM>>>(Q, K, V, whi, wlo, qh, ql, kf, vfp);

    attn_mma<<<BB * NNN * HH, 256, ATTN_SMEM>>>(qh, ql, kf, vfp, mask, attn, resf);

    fc_gemm<<<dim3(4, NTOK / 128), 256, GEMM_SMEM>>>(resf, whi + 3 * WE_C, wlo + 3 * WE_C, outp);

    ln_kernel<<<NTOK / 8, 256>>>(outp, Q, gamma, beta, y);
}

// round 11
// speedup vs baseline: 1.0375x; 1.0375x over previous
#include <cuda_runtime.h>
#include <cuda_fp16.h>
#include <cstdint>

#define BB   16
#define NNN  32
#define SS   128
#define DD   512
#define HH   8
#define NTOK (BB*NNN*SS)          // 65536
#define YSIZE  (NTOK*DD)          // 33554432

// ---------------- scratch ----------------
__device__ __half g_inf[3ull*NTOK*DD];    // inputs Q,K,V single f16
__device__ __half g_whi[4ull*DD*DD];      // weights hi
__device__ __half g_wlo[4ull*DD*DD];      // weights lo
__device__ __half g_qh[(size_t)NTOK*DD];  // Q proj hi
__device__ __half g_ql[(size_t)NTOK*DD];  // Q proj lo
__device__ __half g_kf[(size_t)NTOK*DD];  // K proj single
__device__ __half g_vf[(size_t)NTOK*DD];  // V proj single
__device__ __half g_resf[(size_t)NTOK*DD];// attn result single
__device__ __half g_outp[(size_t)NTOK*DD];// FC result f16
__device__ int    g_flag_float, g_flag_not01;

// ---------------- mask dtype detection ----------------
__global__ void detect_reset() { g_flag_float = 0; g_flag_not01 = 0; }
__global__ __launch_bounds__(256) void detect_scan(const uint4* __restrict__ mw) {
    int i = blockIdx.x * 256 + threadIdx.x;
    uint4 w = mw[i];
    int isf = (w.x == 0x3f800000u) | (w.y == 0x3f800000u) | (w.z == 0x3f800000u) | (w.w == 0x3f800000u);
    int n01 = ((w.x > 1u) & (w.x != 0x3f800000u)) | ((w.y > 1u) & (w.y != 0x3f800000u))
            | ((w.z > 1u) & (w.z != 0x3f800000u)) | ((w.w > 1u) & (w.w != 0x3f800000u));
    int bf = __syncthreads_or(isf);
    int bn = __syncthreads_or(n01);
    if (threadIdx.x == 0) {
        if (bf) atomicOr(&g_flag_float, 1);
        if (bn) atomicOr(&g_flag_not01, 1);
    }
}

// ---------------- helpers ----------------
__device__ __forceinline__ unsigned pack_f16(float lo, float hi) {
    __half2 h = __floats2half2_rn(lo, hi);
    return *(unsigned*)&h;
}
__device__ __forceinline__ float f16lo(unsigned u) { return __low2float(*(__half2*)&u); }
__device__ __forceinline__ float f16hi(unsigned u) { return __high2float(*(__half2*)&u); }

__device__ __forceinline__ void mma16816(float c[4],
    unsigned a0, unsigned a1, unsigned a2, unsigned a3, unsigned b0, unsigned b1)
{
    asm volatile(
        "mma.sync.aligned.m16n8k16.row.col.f32.f16.f16.f32 "
        "{%0,%1,%2,%3}, {%4,%5,%6,%7}, {%8,%9}, {%0,%1,%2,%3};"
        : "+f"(c[0]), "+f"(c[1]), "+f"(c[2]), "+f"(c[3])
        : "r"(a0), "r"(a1), "r"(a2), "r"(a3), "r"(b0), "r"(b1));
}
__device__ __forceinline__ void cpa16(uint32_t s, const void* g) {
    asm volatile("cp.async.cg.shared.global [%0], [%1], 16;" :: "r"(s), "l"(g));
}
__device__ __forceinline__ void ldsm4(unsigned& r0, unsigned& r1, unsigned& r2, unsigned& r3, uint32_t a) {
    asm volatile("ldmatrix.sync.aligned.m8n8.x4.shared.b16 {%0,%1,%2,%3}, [%4];"
        : "=r"(r0), "=r"(r1), "=r"(r2), "=r"(r3) : "r"(a));
}
__device__ __forceinline__ void ldsm4t(unsigned& r0, unsigned& r1, unsigned& r2, unsigned& r3, uint32_t a) {
    asm volatile("ldmatrix.sync.aligned.m8n8.x4.trans.shared.b16 {%0,%1,%2,%3}, [%4];"
        : "=r"(r0), "=r"(r1), "=r"(r2), "=r"(r3) : "r"(a));
}
__device__ __forceinline__ void stcs2(float* p, float a, float b) {
    asm volatile("st.global.cs.v2.f32 [%0], {%1,%2};" :: "l"(p), "f"(a), "f"(b) : "memory");
}

// ---------------- fp32 -> f16 single (3 inputs merged) ----------------
__global__ __launch_bounds__(256) void conv3_kernel(
    const float* __restrict__ s0, const float* __restrict__ s1, const float* __restrict__ s2,
    __half* __restrict__ dst, int n4)
{
    int b = blockIdx.x;
    int sel = b / (n4 / 256);
    int i = (b % (n4 / 256)) * 256 + threadIdx.x;
    const float* src = sel == 0 ? s0 : (sel == 1 ? s1 : s2);
    float4 v = ((const float4*)src)[i];
    ((uint2*)dst)[(size_t)sel * n4 + i] = make_uint2(pack_f16(v.x, v.y), pack_f16(v.z, v.w));
}

// ---------------- fp32 -> f16 hi/lo (4 weights merged) ----------------
__global__ __launch_bounds__(256) void split4_kernel(
    const float* __restrict__ s0, const float* __restrict__ s1,
    const float* __restrict__ s2, const float* __restrict__ s3,
    __half* __restrict__ hi, __half* __restrict__ lo, int n4)
{
    int b = blockIdx.x;
    int sel = b / (n4 / 256);
    int i = (b % (n4 / 256)) * 256 + threadIdx.x;
    const float* src = sel == 0 ? s0 : (sel == 1 ? s1 : (sel == 2 ? s2 : s3));
    float4 v = ((const float4*)src)[i];
    unsigned h01 = pack_f16(v.x, v.y), h23 = pack_f16(v.z, v.w);
    unsigned l01 = pack_f16(v.x - f16lo(h01), v.y - f16hi(h01));
    unsigned l23 = pack_f16(v.z - f16lo(h23), v.w - f16hi(h23));
    size_t o = (size_t)sel * n4 + i;
    ((uint2*)hi)[o] = make_uint2(h01, h23);
    ((uint2*)lo)[o] = make_uint2(l01, l23);
}

// ---------------- GEMM core ----------------
// Stage: A @0, Bh @8192, Bl @16384 (128 rows x 32 f16, 64B rows, swizzle ch^((row>>1)&3))
#define GSTG 24576
#define GEMM_SMEM (3*GSTG)
#define NE_C ((size_t)NTOK * DD)
#define WE_C ((size_t)DD * DD)

// merged QKV projection: grid (12, M/128); px = bx>>2, n-tile = bx&3
__global__ __launch_bounds__(256, 2) void qkv_gemm(
    const __half* __restrict__ inf,
    const __half* __restrict__ whi, const __half* __restrict__ wlo,
    __half* __restrict__ qh, __half* __restrict__ ql,
    __half* __restrict__ kf, __half* __restrict__ vf)
{
    extern __shared__ __half gsm[];
    const int tid = threadIdx.x;
    const int lane = tid & 31, wid = tid >> 5;
    const int wm = wid & 1, wn = wid >> 1;
    const int g = lane >> 2, q = lane & 3;
    const int lrow = (lane & 7) + ((lane >> 3) & 1) * 8;
    const int lch  = lane >> 4;
    const int px = blockIdx.x >> 2;
    const int n0 = (blockIdx.x & 3) * 128, m0 = blockIdx.y * 128;
    const int K = DD, N = DD;
    uint32_t sb = (uint32_t)__cvta_generic_to_shared(gsm);

    const __half* Af  = inf + (size_t)px * NE_C;
    const __half* Bhi = whi + (size_t)px * WE_C;
    const __half* Blo = wlo + (size_t)px * WE_C;

    auto issue = [&](int grp) {
        int k0 = grp << 5;
        uint32_t stg = sb + (grp % 3) * GSTG;
#pragma unroll
        for (int j = 0; j < 6; j++) {
            int idx = tid + j * 256;
            int sub = j >> 1;
            int t2 = idx & 511;
            int row = t2 >> 2, ch = t2 & 3;
            const __half* gp;
            if (sub == 0)      gp = Af  + (size_t)(m0 + row) * K + k0 + ch * 8;
            else if (sub == 1) gp = Bhi + (size_t)(n0 + row) * K + k0 + ch * 8;
            else               gp = Blo + (size_t)(n0 + row) * K + k0 + ch * 8;
            cpa16(stg + sub * 8192 + row * 64 + (((ch ^ ((row >> 1) & 3))) << 4), gp);
        }
        asm volatile("cp.async.commit_group;");
    };

    float acc[4][4][4] = {};
    const int nIter = K >> 5;
    issue(0); issue(1);

    for (int it = 0; it < nIter; it++) {
        if (it < nIter - 1) asm volatile("cp.async.wait_group 1;");
        else                asm volatile("cp.async.wait_group 0;");
        __syncthreads();
        if (it + 2 < nIter) issue(it + 2);
        uint32_t bufb = sb + (it % 3) * GSTG;
#pragma unroll
        for (int kb = 0; kb < 32; kb += 16) {
            int c0 = kb >> 3;
            unsigned af[4][4];
#pragma unroll
            for (int i = 0; i < 4; i++) {
                int row = wm * 64 + i * 16 + lrow;
                uint32_t a = bufb + row * 64 + ((((c0 + lch) ^ ((row >> 1) & 3))) << 4);
                ldsm4(af[i][0], af[i][1], af[i][2], af[i][3], a);
            }
            unsigned bh[2][4], bl[2][4];
#pragma unroll
            for (int p = 0; p < 2; p++) {
                int row = wn * 32 + p * 16 + lrow;
                uint32_t b = bufb + 8192 + row * 64 + ((((c0 + lch) ^ ((row >> 1) & 3))) << 4);
                ldsm4(bh[p][0], bh[p][1], bh[p][2], bh[p][3], b);
                ldsm4(bl[p][0], bl[p][1], bl[p][2], bl[p][3], b + 8192);
            }
            // hi pass (16 independent MMAs), then lo pass — kills acc RAW stalls
#pragma unroll
            for (int j = 0; j < 4; j++) {
                int p = j >> 1, o = j & 1;
                unsigned b0 = bh[p][o], b1 = bh[p][o + 2];
#pragma unroll
                for (int i = 0; i < 4; i++)
                    mma16816(acc[i][j], af[i][0], af[i][1], af[i][2], af[i][3], b0, b1);
            }
#pragma unroll
            for (int j = 0; j < 4; j++) {
                int p = j >> 1, o = j & 1;
                unsigned b0 = bl[p][o], b1 = bl[p][o + 2];
#pragma unroll
                for (int i = 0; i < 4; i++)
                    mma16816(acc[i][j], af[i][0], af[i][1], af[i][2], af[i][3], b0, b1);
            }
        }
    }

    __half* Chi = px == 0 ? qh : (px == 1 ? kf : vf);
#pragma unroll
    for (int i = 0; i < 4; i++) {
#pragma unroll
        for (int j = 0; j < 4; j++) {
            int row = m0 + wm * 64 + i * 16 + g;
            int col = n0 + wn * 32 + j * 8 + 2 * q;
            unsigned h01 = pack_f16(acc[i][j][0], acc[i][j][1]);
            unsigned h23 = pack_f16(acc[i][j][2], acc[i][j][3]);
            *(unsigned*)&Chi[(size_t)row * N + col]       = h01;
            *(unsigned*)&Chi[(size_t)(row + 8) * N + col] = h23;
            if (px == 0) {
                unsigned l01 = pack_f16(acc[i][j][0] - f16lo(h01), acc[i][j][1] - f16hi(h01));
                unsigned l23 = pack_f16(acc[i][j][2] - f16lo(h23), acc[i][j][3] - f16hi(h23));
                *(unsigned*)&ql[(size_t)row * N + col]       = l01;
                *(unsigned*)&ql[(size_t)(row + 8) * N + col] = l23;
            }
        }
    }
}

// FC GEMM: single f16 out
__global__ __launch_bounds__(256, 2) void fc_gemm(
    const __half* __restrict__ Af,
    const __half* __restrict__ Bhi, const __half* __restrict__ Blo,
    __half* __restrict__ Chi)
{
    extern __shared__ __half gsm[];
    const int tid = threadIdx.x;
    const int lane = tid & 31, wid = tid >> 5;
    const int wm = wid & 1, wn = wid >> 1;
    const int g = lane >> 2, q = lane & 3;
    const int lrow = (lane & 7) + ((lane >> 3) & 1) * 8;
    const int lch  = lane >> 4;
    const int n0 = blockIdx.x * 128, m0 = blockIdx.y * 128;
    const int K = DD, N = DD;
    uint32_t sb = (uint32_t)__cvta_generic_to_shared(gsm);

    auto issue = [&](int grp) {
        int k0 = grp << 5;
        uint32_t stg = sb + (grp % 3) * GSTG;
#pragma unroll
        for (int j = 0; j < 6; j++) {
            int idx = tid + j * 256;
            int sub = j >> 1;
            int t2 = idx & 511;
            int row = t2 >> 2, ch = t2 & 3;
            const __half* gp;
            if (sub == 0)      gp = Af  + (size_t)(m0 + row) * K + k0 + ch * 8;
            else if (sub == 1) gp = Bhi + (size_t)(n0 + row) * K + k0 + ch * 8;
            else               gp = Blo + (size_t)(n0 + row) * K + k0 + ch * 8;
            cpa16(stg + sub * 8192 + row * 64 + (((ch ^ ((row >> 1) & 3))) << 4), gp);
        }
        asm volatile("cp.async.commit_group;");
    };

    float acc[4][4][4] = {};
    const int nIter = K >> 5;
    issue(0); issue(1);

    for (int it = 0; it < nIter; it++) {
        if (it < nIter - 1) asm volatile("cp.async.wait_group 1;");
        else                asm volatile("cp.async.wait_group 0;");
        __syncthreads();
        if (it + 2 < nIter) issue(it + 2);
        uint32_t bufb = sb + (it % 3) * GSTG;
#pragma unroll
        for (int kb = 0; kb < 32; kb += 16) {
            int c0 = kb >> 3;
            unsigned af[4][4];
#pragma unroll
            for (int i = 0; i < 4; i++) {
                int row = wm * 64 + i * 16 + lrow;
                uint32_t a = bufb + row * 64 + ((((c0 + lch) ^ ((row >> 1) & 3))) << 4);
                ldsm4(af[i][0], af[i][1], af[i][2], af[i][3], a);
            }
            unsigned bh[2][4], bl[2][4];
#pragma unroll
            for (int p = 0; p < 2; p++) {
                int row = wn * 32 + p * 16 + lrow;
                uint32_t b = bufb + 8192 + row * 64 + ((((c0 + lch) ^ ((row >> 1) & 3))) << 4);
                ldsm4(bh[p][0], bh[p][1], bh[p][2], bh[p][3], b);
                ldsm4(bl[p][0], bl[p][1], bl[p][2], bl[p][3], b + 8192);
            }
#pragma unroll
            for (int j = 0; j < 4; j++) {
                int p = j >> 1, o = j & 1;
                unsigned b0 = bh[p][o], b1 = bh[p][o + 2];
#pragma unroll
                for (int i = 0; i < 4; i++)
                    mma16816(acc[i][j], af[i][0], af[i][1], af[i][2], af[i][3], b0, b1);
            }
#pragma unroll
            for (int j = 0; j < 4; j++) {
                int p = j >> 1, o = j & 1;
                unsigned b0 = bl[p][o], b1 = bl[p][o + 2];
#pragma unroll
                for (int i = 0; i < 4; i++)
                    mma16816(acc[i][j], af[i][0], af[i][1], af[i][2], af[i][3], b0, b1);
            }
        }
    }

#pragma unroll
    for (int i = 0; i < 4; i++) {
#pragma unroll
        for (int j = 0; j < 4; j++) {
            int row = m0 + wm * 64 + i * 16 + g;
            int col = n0 + wn * 32 + j * 8 + 2 * q;
            *(unsigned*)&Chi[(size_t)row * N + col]       = pack_f16(acc[i][j][0], acc[i][j][1]);
            *(unsigned*)&Chi[(size_t)(row + 8) * N + col] = pack_f16(acc[i][j][2], acc[i][j][3]);
        }
    }
}

// ---------------- attention: 128 q-rows/CTA, register softmax ----------------
#define AK_OFF  0
#define AV_OFF  16384
#define AQH_OFF 32768
#define AQL_OFF 49152
#define AP_OFF  32768
#define AM_OFF  65536
#define ASTM_OFF 81920
#define ASTS_OFF 83968
#define ATTN_SMEM 86016

__global__ __launch_bounds__(256, 2) void attn_mma(
    const __half* __restrict__ qhi, const __half* __restrict__ qlo,
    const __half* __restrict__ kf, const __half* __restrict__ vf,
    const void* __restrict__ mask, float* __restrict__ attn_out,
    __half* __restrict__ resf)
{
    extern __shared__ char smc[];
    uint32_t sb = (uint32_t)__cvta_generic_to_shared(smc);
    float* stM = (float*)(smc + ASTM_OFF);
    float* stS = (float*)(smc + ASTS_OFF);

    const int tid = threadIdx.x;
    const int lane = tid & 31, wid = tid >> 5;
    const int g = lane >> 2, q = lane & 3;
    const int lrow = (lane & 7) + ((lane >> 3) & 1) * 8;
    const int lch  = lane >> 4;
    const int h  = blockIdx.x & 7;
    const int bn = blockIdx.x >> 3;
    const int kind = g_flag_not01 ? 2 : (g_flag_float ? 1 : 0);

    const size_t base = (size_t)bn * 128 * DD + (size_t)h * 64;

    // group 0: K, Qh, Ql
    {
#pragma unroll
        for (int t = 0; t < 4; t++) {
            int idx = tid + t * 256;
            int row = idx >> 3, ch = idx & 7;
            uint32_t sw = row * 128 + (((ch ^ (row & 7))) << 4);
            size_t go = base + (size_t)row * DD + ch * 8;
            cpa16(sb + AK_OFF  + sw, kf  + go);
            cpa16(sb + AQH_OFF + sw, qhi + go);
            cpa16(sb + AQL_OFF + sw, qlo + go);
        }
        asm volatile("cp.async.commit_group;");
    }
    // group 1: V (+ mask if u8)
    {
#pragma unroll
        for (int t = 0; t < 4; t++) {
            int idx = tid + t * 256;
            int row = idx >> 3, ch = idx & 7;
            uint32_t sw = row * 128 + (((ch ^ (row & 7))) << 4);
            cpa16(sb + AV_OFF + sw, vf + base + (size_t)row * DD + ch * 8);
        }
        if (kind == 2) {
#pragma unroll
            for (int t = 0; t < 4; t++) {
                int idx = tid + t * 256;
                int row = idx >> 3, ch = idx & 7;
                cpa16(sb + AM_OFF + row * 128 + ch * 16,
                      (const unsigned char*)mask + (size_t)bn * 16384 + (size_t)row * 128 + ch * 16);
            }
        }
        asm volatile("cp.async.commit_group;");
    }
    asm volatile("cp.async.wait_group 1;");
    __syncthreads();

    const int wm = wid & 1, wn = wid >> 1;

    // QK^T — hi pass then lo pass per kb
    float acc[4][4][4] = {};
#pragma unroll
    for (int kb = 0; kb < 64; kb += 16) {
        int c0 = kb >> 3;
        unsigned ah[4][4], al[4][4];
#pragma unroll
        for (int i = 0; i < 4; i++) {
            int row = wm * 64 + i * 16 + lrow;
            uint32_t a = sb + AQH_OFF + row * 128 + ((((c0 + lch) ^ (row & 7))) << 4);
            ldsm4(ah[i][0], ah[i][1], ah[i][2], ah[i][3], a);
            ldsm4(al[i][0], al[i][1], al[i][2], al[i][3], a + 16384);
        }
        unsigned bk[2][4];
#pragma unroll
        for (int p = 0; p < 2; p++) {
            int row = wn * 32 + p * 16 + lrow;
            uint32_t b = sb + AK_OFF + row * 128 + ((((c0 + lch) ^ (row & 7))) << 4);
            ldsm4(bk[p][0], bk[p][1], bk[p][2], bk[p][3], b);
        }
#pragma unroll
        for (int j = 0; j < 4; j++) {
            int p = j >> 1, o = j & 1;
            unsigned b0 = bk[p][o], b1 = bk[p][o + 2];
#pragma unroll
            for (int i = 0; i < 4; i++)
                mma16816(acc[i][j], ah[i][0], ah[i][1], ah[i][2], ah[i][3], b0, b1);
        }
#pragma unroll
        for (int j = 0; j < 4; j++) {
            int p = j >> 1, o = j & 1;
            unsigned b0 = bk[p][o], b1 = bk[p][o + 2];
#pragma unroll
            for (int i = 0; i < 4; i++)
                mma16816(acc[i][j], al[i][0], al[i][1], al[i][2], al[i][3], b0, b1);
        }
    }

    asm volatile("cp.async.wait_group 0;");
    __syncthreads();

    // mask + scale
#pragma unroll
    for (int i = 0; i < 4; i++) {
#pragma unroll
        for (int hf = 0; hf < 2; hf++) {
            int r = wm * 64 + i * 16 + g + hf * 8;
#pragma unroll
            for (int j = 0; j < 4; j++) {
                int c = wn * 32 + j * 8 + 2 * q;
                float m0, m1;
                if (kind == 2) {
                    uchar2 mk = *(const uchar2*)(smc + AM_OFF + r * 128 + c);
                    m0 = mk.x ? 0.f : -1e9f; m1 = mk.y ? 0.f : -1e9f;
                } else if (kind == 1) {
                    float2 mk = *(const float2*)((const float*)mask + (size_t)bn * 16384 + (size_t)r * 128 + c);
                    m0 = (mk.x != 0.f) ? 0.f : -1e9f; m1 = (mk.y != 0.f) ? 0.f : -1e9f;
                } else {
                    int2 mk = *(const int2*)((const int*)mask + (size_t)bn * 16384 + (size_t)r * 128 + c);
                    m0 = mk.x ? 0.f : -1e9f; m1 = mk.y ? 0.f : -1e9f;
                }
                acc[i][j][2 * hf]     = acc[i][j][2 * hf]     * 0.125f + m0;
                acc[i][j][2 * hf + 1] = acc[i][j][2 * hf + 1] * 0.125f + m1;
            }
        }
    }

    // row max
#pragma unroll
    for (int i = 0; i < 4; i++)
#pragma unroll
        for (int hf = 0; hf < 2; hf++) {
            float m = -3.4e38f;
#pragma unroll
            for (int j = 0; j < 4; j++)
                m = fmaxf(m, fmaxf(acc[i][j][2 * hf], acc[i][j][2 * hf + 1]));
            m = fmaxf(m, __shfl_xor_sync(0xffffffffu, m, 1));
            m = fmaxf(m, __shfl_xor_sync(0xffffffffu, m, 2));
            if (q == 0) stM[(wm * 64 + i * 16 + g + hf * 8) * 4 + wn] = m;
        }
    __syncthreads();

    float inv[4][2];
#pragma unroll
    for (int i = 0; i < 4; i++)
#pragma unroll
        for (int hf = 0; hf < 2; hf++) {
            int r = wm * 64 + i * 16 + g + hf * 8;
            float gm = fmaxf(fmaxf(stM[r * 4], stM[r * 4 + 1]), fmaxf(stM[r * 4 + 2], stM[r * 4 + 3]));
            float s = 0.f;
#pragma unroll
            for (int j = 0; j < 4; j++) {
                float e0 = __expf(acc[i][j][2 * hf]     - gm);
                float e1 = __expf(acc[i][j][2 * hf + 1] - gm);
                acc[i][j][2 * hf] = e0; acc[i][j][2 * hf + 1] = e1;
                s += e0 + e1;
            }
            s += __shfl_xor_sync(0xffffffffu, s, 1);
            s += __shfl_xor_sync(0xffffffffu, s, 2);
            if (q == 0) stS[r * 4 + wn] = s;
        }
    __syncthreads();

#pragma unroll
    for (int i = 0; i < 4; i++)
#pragma unroll
        for (int hf = 0; hf < 2; hf++) {
            int r = wm * 64 + i * 16 + g + hf * 8;
            inv[i][hf] = 1.0f / (stS[r * 4] + stS[r * 4 + 1] + stS[r * 4 + 2] + stS[r * 4 + 3]);
        }

    // normalize + attn_out (streaming) + P f16 pack
    {
        float* aout = attn_out + ((size_t)(bn * 8 + h)) * 16384;
#pragma unroll
        for (int i = 0; i < 4; i++)
#pragma unroll
            for (int hf = 0; hf < 2; hf++) {
                int r = wm * 64 + i * 16 + g + hf * 8;
                float iv = inv[i][hf];
#pragma unroll
                for (int j = 0; j < 4; j++) {
                    int c = wn * 32 + j * 8 + 2 * q;
                    float p0 = acc[i][j][2 * hf] * iv;
                    float p1 = acc[i][j][2 * hf + 1] * iv;
                    stcs2(&aout[(size_t)r * 128 + c], p0, p1);
                    uint32_t off = r * 256 + ((((c >> 3) ^ (r & 7))) << 4) + (c & 7) * 2;
                    *(unsigned*)(smc + AP_OFF + off) = pack_f16(p0, p1);
                }
            }
    }
    __syncthreads();

    // P @ V
    float ao[4][2][4] = {};
#pragma unroll
    for (int kb = 0; kb < 8; kb++) {
        int c0 = kb * 2;
        unsigned ph[4][4];
#pragma unroll
        for (int i = 0; i < 4; i++) {
            int row = wm * 64 + i * 16 + lrow;
            uint32_t a = sb + AP_OFF + row * 256 + ((((c0 + lch) ^ (row & 7))) << 4);
            ldsm4(ph[i][0], ph[i][1], ph[i][2], ph[i][3], a);
        }
        int vrow = kb * 16 + lrow;
        uint32_t vb = sb + AV_OFF + vrow * 128 + ((((wn * 2 + lch) ^ (vrow & 7))) << 4);
        unsigned vv[4];
        ldsm4t(vv[0], vv[1], vv[2], vv[3], vb);
#pragma unroll
        for (int j = 0; j < 2; j++) {
            unsigned b0 = vv[2 * j], b1 = vv[2 * j + 1];
#pragma unroll
            for (int i = 0; i < 4; i++)
                mma16816(ao[i][j], ph[i][0], ph[i][1], ph[i][2], ph[i][3], b0, b1);
        }
    }

#pragma unroll
    for (int i = 0; i < 4; i++)
#pragma unroll
        for (int j = 0; j < 2; j++) {
            int row = wm * 64 + i * 16 + g;
            int col = h * 64 + wn * 16 + j * 8 + 2 * q;
            size_t o0 = ((size_t)(bn * 128 + row)) * DD + col;
            size_t o1 = o0 + 8ull * DD;
            *(unsigned*)&resf[o0] = pack_f16(ao[i][j][0], ao[i][j][1]);
            *(unsigned*)&resf[o1] = pack_f16(ao[i][j][2], ao[i][j][3]);
        }
}

// ---------------- residual + LayerNorm: warp per row ----------------
__global__ __launch_bounds__(256) void ln_kernel(
    const __half* __restrict__ O, const float* __restrict__ X,
    const float* __restrict__ gamma, const float* __restrict__ beta,
    float* __restrict__ Y)
{
    const int lane = threadIdx.x & 31, w = threadIdx.x >> 5;
    const size_t row = (size_t)blockIdx.x * 8 + w;
    const size_t base = row * DD;

    float x[16];
    float s = 0.f, s2 = 0.f;
#pragma unroll
    for (int c = 0; c < 4; c++) {
        int col = c * 128 + lane * 4;
        uint2 o2 = *(const uint2*)&O[base + col];
        float4 xf = *(const float4*)&X[base + col];
        float v0 = f16lo(o2.x) + xf.x;
        float v1 = f16hi(o2.x) + xf.y;
        float v2 = f16lo(o2.y) + xf.z;
        float v3 = f16hi(o2.y) + xf.w;
        x[c * 4 + 0] = v0; x[c * 4 + 1] = v1; x[c * 4 + 2] = v2; x[c * 4 + 3] = v3;
        s  += v0 + v1 + v2 + v3;
        s2 += v0 * v0 + v1 * v1 + v2 * v2 + v3 * v3;
    }
#pragma unroll
    for (int o = 16; o; o >>= 1) {
        s  += __shfl_xor_sync(0xffffffffu, s,  o);
        s2 += __shfl_xor_sync(0xffffffffu, s2, o);
    }
    float mean = s * (1.0f / DD);
    float var  = s2 * (1.0f / DD) - mean * mean;
    float inv  = rsqrtf(var + 1e-5f);

#pragma unroll
    for (int c = 0; c < 4; c++) {
        int col = c * 128 + lane * 4;
        float4 gm = *(const float4*)&gamma[col];
        float4 bt = *(const float4*)&beta[col];
        float4 yv;
        yv.x = (x[c * 4 + 0] - mean) * inv * gm.x + bt.x;
        yv.y = (x[c * 4 + 1] - mean) * inv * gm.y + bt.y;
        yv.z = (x[c * 4 + 2] - mean) * inv * gm.z + bt.z;
        yv.w = (x[c * 4 + 3] - mean) * inv * gm.w + bt.w;
        *(float4*)&Y[base + col] = yv;
    }
}

// ---------------- launch ----------------
extern "C" void kernel_launch(void* const* d_in, const int* in_sizes, int n_in,
                              void* d_out, int out_size)
{
    const float* Q     = (const float*)d_in[0];
    const float* K     = (const float*)d_in[1];
    const float* V     = (const float*)d_in[2];
    const void*  mask  = d_in[3];
    const float* WQ    = (const float*)d_in[4];
    const float* WK    = (const float*)d_in[5];
    const float* WV    = (const float*)d_in[6];
    const float* Wfc   = (const float*)d_in[7];
    const float* gamma = (const float*)d_in[8];
    const float* beta  = (const float*)d_in[9];

    float* y    = (float*)d_out;
    float* attn = y + (size_t)YSIZE;

    void *p;
    cudaGetSymbolAddress(&p, g_inf);  __half* inf  = (__half*)p;
    cudaGetSymbolAddress(&p, g_whi);  __half* whi  = (__half*)p;
    cudaGetSymbolAddress(&p, g_wlo);  __half* wlo  = (__half*)p;
    cudaGetSymbolAddress(&p, g_qh);   __half* qh   = (__half*)p;
    cudaGetSymbolAddress(&p, g_ql);   __half* ql   = (__half*)p;
    cudaGetSymbolAddress(&p, g_kf);   __half* kf   = (__half*)p;
    cudaGetSymbolAddress(&p, g_vf);   __half* vfp  = (__half*)p;
    cudaGetSymbolAddress(&p, g_resf); __half* resf = (__half*)p;
    cudaGetSymbolAddress(&p, g_outp); __half* outp = (__half*)p;

    cudaFuncSetAttribute(qkv_gemm, cudaFuncAttributeMaxDynamicSharedMemorySize, GEMM_SMEM);
    cudaFuncSetAttribute(fc_gemm,  cudaFuncAttributeMaxDynamicSharedMemorySize, GEMM_SMEM);
    cudaFuncSetAttribute(attn_mma, cudaFuncAttributeMaxDynamicSharedMemorySize, ATTN_SMEM);

    detect_reset<<<1, 1>>>();
    detect_scan<<<64, 256>>>((const uint4*)mask);

    const int n4 = (int)(NE_C / 4);
    conv3_kernel<<<3 * (n4 / 256), 256>>>(Q, K, V, inf, n4);
    const int w4 = (int)(WE_C / 4);
    split4_kernel<<<4 * (w4 / 256), 256>>>(WQ, WK, WV, Wfc, whi, wlo, w4);

    qkv_gemm<<<dim3(12, NTOK / 128), 256, GEMM_SMEM>>>(inf, whi, wlo, qh, ql, kf, vfp);

    attn_mma<<<BB * NNN * HH, 256, ATTN_SMEM>>>(qh, ql, kf, vfp, mask, attn, resf);

    fc_gemm<<<dim3(4, NTOK / 128), 256, GEMM_SMEM>>>(resf, whi + 3 * WE_C, wlo + 3 * WE_C, outp);

    ln_kernel<<<NTOK / 8, 256>>>(outp, Q, gamma, beta, y);
}

// round 12
// speedup vs baseline: 1.2996x; 1.2526x over previous
#include <cuda_runtime.h>
#include <cuda_fp16.h>
#include <cstdint>

#define BB   16
#define NNN  32
#define SS   128
#define DD   512
#define HH   8
#define NTOK (BB*NNN*SS)          // 65536
#define YSIZE  (NTOK*DD)          // 33554432

// ---------------- scratch ----------------
__device__ __half g_inf[3ull*NTOK*DD];    // inputs Q,K,V single f16
__device__ __half g_whi[4ull*DD*DD];      // weights hi
__device__ __half g_wlo[(size_t)DD*DD];   // W_Q lo only (others don't need it)
__device__ __half g_qh[(size_t)NTOK*DD];  // Q proj hi
__device__ __half g_ql[(size_t)NTOK*DD];  // Q proj lo
__device__ __half g_kf[(size_t)NTOK*DD];  // K proj single
__device__ __half g_vf[(size_t)NTOK*DD];  // V proj single
__device__ __half g_resf[(size_t)NTOK*DD];// attn result single
__device__ __half g_outp[(size_t)NTOK*DD];// FC result f16
__device__ int    g_flag_float, g_flag_not01;

// ---------------- mask dtype detection ----------------
__global__ void detect_reset() { g_flag_float = 0; g_flag_not01 = 0; }
__global__ __launch_bounds__(256) void detect_scan(const uint4* __restrict__ mw) {
    int i = blockIdx.x * 256 + threadIdx.x;
    uint4 w = mw[i];
    int isf = (w.x == 0x3f800000u) | (w.y == 0x3f800000u) | (w.z == 0x3f800000u) | (w.w == 0x3f800000u);
    int n01 = ((w.x > 1u) & (w.x != 0x3f800000u)) | ((w.y > 1u) & (w.y != 0x3f800000u))
            | ((w.z > 1u) & (w.z != 0x3f800000u)) | ((w.w > 1u) & (w.w != 0x3f800000u));
    int bf = __syncthreads_or(isf);
    int bn = __syncthreads_or(n01);
    if (threadIdx.x == 0) {
        if (bf) atomicOr(&g_flag_float, 1);
        if (bn) atomicOr(&g_flag_not01, 1);
    }
}

// ---------------- helpers ----------------
__device__ __forceinline__ unsigned pack_f16(float lo, float hi) {
    __half2 h = __floats2half2_rn(lo, hi);
    return *(unsigned*)&h;
}
__device__ __forceinline__ float f16lo(unsigned u) { return __low2float(*(__half2*)&u); }
__device__ __forceinline__ float f16hi(unsigned u) { return __high2float(*(__half2*)&u); }

__device__ __forceinline__ void mma16816(float c[4],
    unsigned a0, unsigned a1, unsigned a2, unsigned a3, unsigned b0, unsigned b1)
{
    asm volatile(
        "mma.sync.aligned.m16n8k16.row.col.f32.f16.f16.f32 "
        "{%0,%1,%2,%3}, {%4,%5,%6,%7}, {%8,%9}, {%0,%1,%2,%3};"
        : "+f"(c[0]), "+f"(c[1]), "+f"(c[2]), "+f"(c[3])
        : "r"(a0), "r"(a1), "r"(a2), "r"(a3), "r"(b0), "r"(b1));
}
__device__ __forceinline__ void cpa16(uint32_t s, const void* g) {
    asm volatile("cp.async.cg.shared.global [%0], [%1], 16;" :: "r"(s), "l"(g));
}
__device__ __forceinline__ void ldsm4(unsigned& r0, unsigned& r1, unsigned& r2, unsigned& r3, uint32_t a) {
    asm volatile("ldmatrix.sync.aligned.m8n8.x4.shared.b16 {%0,%1,%2,%3}, [%4];"
        : "=r"(r0), "=r"(r1), "=r"(r2), "=r"(r3) : "r"(a));
}
__device__ __forceinline__ void ldsm4t(unsigned& r0, unsigned& r1, unsigned& r2, unsigned& r3, uint32_t a) {
    asm volatile("ldmatrix.sync.aligned.m8n8.x4.trans.shared.b16 {%0,%1,%2,%3}, [%4];"
        : "=r"(r0), "=r"(r1), "=r"(r2), "=r"(r3) : "r"(a));
}
__device__ __forceinline__ void stcs2(float* p, float a, float b) {
    asm volatile("st.global.cs.v2.f32 [%0], {%1,%2};" :: "l"(p), "f"(a), "f"(b) : "memory");
}

// ---------------- fp32 -> f16 single (3 inputs merged) ----------------
__global__ __launch_bounds__(256) void conv3_kernel(
    const float* __restrict__ s0, const float* __restrict__ s1, const float* __restrict__ s2,
    __half* __restrict__ dst, int n4)
{
    int b = blockIdx.x;
    int sel = b / (n4 / 256);
    int i = (b % (n4 / 256)) * 256 + threadIdx.x;
    const float* src = sel == 0 ? s0 : (sel == 1 ? s1 : s2);
    float4 v = ((const float4*)src)[i];
    ((uint2*)dst)[(size_t)sel * n4 + i] = make_uint2(pack_f16(v.x, v.y), pack_f16(v.z, v.w));
}

// ---------------- weights: all 4 -> hi; W_Q also -> lo ----------------
__global__ __launch_bounds__(256) void wsplit_kernel(
    const float* __restrict__ s0, const float* __restrict__ s1,
    const float* __restrict__ s2, const float* __restrict__ s3,
    __half* __restrict__ hi, __half* __restrict__ lo, int n4)
{
    int b = blockIdx.x;
    int sel = b / (n4 / 256);
    int i = (b % (n4 / 256)) * 256 + threadIdx.x;
    const float* src = sel == 0 ? s0 : (sel == 1 ? s1 : (sel == 2 ? s2 : s3));
    float4 v = ((const float4*)src)[i];
    unsigned h01 = pack_f16(v.x, v.y), h23 = pack_f16(v.z, v.w);
    size_t o = (size_t)sel * n4 + i;
    ((uint2*)hi)[o] = make_uint2(h01, h23);
    if (sel == 0) {
        unsigned l01 = pack_f16(v.x - f16lo(h01), v.y - f16hi(h01));
        unsigned l23 = pack_f16(v.z - f16lo(h23), v.w - f16hi(h23));
        ((uint2*)lo)[i] = make_uint2(l01, l23);
    }
}

// ---------------- GEMM cores ----------------
#define GSTG 24576
#define GEMM_SMEM (3*GSTG)
#define FSTG 16384
#define FC_SMEM (3*FSTG)
#define NE_C ((size_t)NTOK * DD)
#define WE_C ((size_t)DD * DD)

// merged QKV projection: grid (12, M/128); px = bx>>2, n-tile = bx&3
// px==0 (Q): hi+lo weight passes, split output. px 1/2 (K/V): hi only, single output.
__global__ __launch_bounds__(256, 2) void qkv_gemm(
    const __half* __restrict__ inf,
    const __half* __restrict__ whi, const __half* __restrict__ wlo,
    __half* __restrict__ qh, __half* __restrict__ ql,
    __half* __restrict__ kf, __half* __restrict__ vf)
{
    extern __shared__ __half gsm[];
    const int tid = threadIdx.x;
    const int lane = tid & 31, wid = tid >> 5;
    const int wm = wid & 1, wn = wid >> 1;
    const int g = lane >> 2, q = lane & 3;
    const int lrow = (lane & 7) + ((lane >> 3) & 1) * 8;
    const int lch  = lane >> 4;
    const int px = blockIdx.x >> 2;
    const int n0 = (blockIdx.x & 3) * 128, m0 = blockIdx.y * 128;
    const int K = DD, N = DD;
    uint32_t sb = (uint32_t)__cvta_generic_to_shared(gsm);

    const __half* Af  = inf + (size_t)px * NE_C;
    const __half* Bhi = whi + (size_t)px * WE_C;

    auto issue = [&](int grp) {
        int k0 = grp << 5;
        uint32_t stg = sb + (grp % 3) * GSTG;
#pragma unroll
        for (int j = 0; j < 6; j++) {
            int sub = j >> 1;
            if (sub == 2 && px != 0) break;   // K/V: no lo plane
            int idx = tid + j * 256;
            int t2 = idx & 511;
            int row = t2 >> 2, ch = t2 & 3;
            const __half* gp;
            if (sub == 0)      gp = Af  + (size_t)(m0 + row) * K + k0 + ch * 8;
            else if (sub == 1) gp = Bhi + (size_t)(n0 + row) * K + k0 + ch * 8;
            else               gp = wlo + (size_t)(n0 + row) * K + k0 + ch * 8;
            cpa16(stg + sub * 8192 + row * 64 + (((ch ^ ((row >> 1) & 3))) << 4), gp);
        }
        asm volatile("cp.async.commit_group;");
    };

    float acc[4][4][4] = {};
    const int nIter = K >> 5;
    issue(0); issue(1);

    for (int it = 0; it < nIter; it++) {
        if (it < nIter - 1) asm volatile("cp.async.wait_group 1;");
        else                asm volatile("cp.async.wait_group 0;");
        __syncthreads();
        if (it + 2 < nIter) issue(it + 2);
        uint32_t bufb = sb + (it % 3) * GSTG;
#pragma unroll
        for (int kb = 0; kb < 32; kb += 16) {
            int c0 = kb >> 3;
            unsigned af[4][4];
#pragma unroll
            for (int i = 0; i < 4; i++) {
                int row = wm * 64 + i * 16 + lrow;
                uint32_t a = bufb + row * 64 + ((((c0 + lch) ^ ((row >> 1) & 3))) << 4);
                ldsm4(af[i][0], af[i][1], af[i][2], af[i][3], a);
            }
            unsigned bh[2][4];
#pragma unroll
            for (int p = 0; p < 2; p++) {
                int row = wn * 32 + p * 16 + lrow;
                uint32_t b = bufb + 8192 + row * 64 + ((((c0 + lch) ^ ((row >> 1) & 3))) << 4);
                ldsm4(bh[p][0], bh[p][1], bh[p][2], bh[p][3], b);
            }
#pragma unroll
            for (int j = 0; j < 4; j++) {
                int p = j >> 1, o = j & 1;
                unsigned b0 = bh[p][o], b1 = bh[p][o + 2];
#pragma unroll
                for (int i = 0; i < 4; i++)
                    mma16816(acc[i][j], af[i][0], af[i][1], af[i][2], af[i][3], b0, b1);
            }
            if (px == 0) {
                unsigned bl[2][4];
#pragma unroll
                for (int p = 0; p < 2; p++) {
                    int row = wn * 32 + p * 16 + lrow;
                    uint32_t b = bufb + 16384 + row * 64 + ((((c0 + lch) ^ ((row >> 1) & 3))) << 4);
                    ldsm4(bl[p][0], bl[p][1], bl[p][2], bl[p][3], b);
                }
#pragma unroll
                for (int j = 0; j < 4; j++) {
                    int p = j >> 1, o = j & 1;
                    unsigned b0 = bl[p][o], b1 = bl[p][o + 2];
#pragma unroll
                    for (int i = 0; i < 4; i++)
                        mma16816(acc[i][j], af[i][0], af[i][1], af[i][2], af[i][3], b0, b1);
                }
            }
        }
    }

    __half* Chi = px == 0 ? qh : (px == 1 ? kf : vf);
#pragma unroll
    for (int i = 0; i < 4; i++) {
#pragma unroll
        for (int j = 0; j < 4; j++) {
            int row = m0 + wm * 64 + i * 16 + g;
            int col = n0 + wn * 32 + j * 8 + 2 * q;
            unsigned h01 = pack_f16(acc[i][j][0], acc[i][j][1]);
            unsigned h23 = pack_f16(acc[i][j][2], acc[i][j][3]);
            *(unsigned*)&Chi[(size_t)row * N + col]       = h01;
            *(unsigned*)&Chi[(size_t)(row + 8) * N + col] = h23;
            if (px == 0) {
                unsigned l01 = pack_f16(acc[i][j][0] - f16lo(h01), acc[i][j][1] - f16hi(h01));
                unsigned l23 = pack_f16(acc[i][j][2] - f16lo(h23), acc[i][j][3] - f16hi(h23));
                *(unsigned*)&ql[(size_t)row * N + col]       = l01;
                *(unsigned*)&ql[(size_t)(row + 8) * N + col] = l23;
            }
        }
    }
}

// FC GEMM: A single f16, B hi only, single f16 out
__global__ __launch_bounds__(256, 2) void fc_gemm(
    const __half* __restrict__ Af,
    const __half* __restrict__ Bhi,
    __half* __restrict__ Chi)
{
    extern __shared__ __half gsm[];
    const int tid = threadIdx.x;
    const int lane = tid & 31, wid = tid >> 5;
    const int wm = wid & 1, wn = wid >> 1;
    const int g = lane >> 2, q = lane & 3;
    const int lrow = (lane & 7) + ((lane >> 3) & 1) * 8;
    const int lch  = lane >> 4;
    const int n0 = blockIdx.x * 128, m0 = blockIdx.y * 128;
    const int K = DD, N = DD;
    uint32_t sb = (uint32_t)__cvta_generic_to_shared(gsm);

    auto issue = [&](int grp) {
        int k0 = grp << 5;
        uint32_t stg = sb + (grp % 3) * FSTG;
#pragma unroll
        for (int j = 0; j < 4; j++) {
            int idx = tid + j * 256;
            int sub = j >> 1;               // 0: A, 1: Bh
            int t2 = idx & 511;
            int row = t2 >> 2, ch = t2 & 3;
            const __half* gp = (sub == 0 ? Af + (size_t)(m0 + row) * K
                                         : Bhi + (size_t)(n0 + row) * K) + k0 + ch * 8;
            cpa16(stg + sub * 8192 + row * 64 + (((ch ^ ((row >> 1) & 3))) << 4), gp);
        }
        asm volatile("cp.async.commit_group;");
    };

    float acc[4][4][4] = {};
    const int nIter = K >> 5;
    issue(0); issue(1);

    for (int it = 0; it < nIter; it++) {
        if (it < nIter - 1) asm volatile("cp.async.wait_group 1;");
        else                asm volatile("cp.async.wait_group 0;");
        __syncthreads();
        if (it + 2 < nIter) issue(it + 2);
        uint32_t bufb = sb + (it % 3) * FSTG;
#pragma unroll
        for (int kb = 0; kb < 32; kb += 16) {
            int c0 = kb >> 3;
            unsigned af[4][4];
#pragma unroll
            for (int i = 0; i < 4; i++) {
                int row = wm * 64 + i * 16 + lrow;
                uint32_t a = bufb + row * 64 + ((((c0 + lch) ^ ((row >> 1) & 3))) << 4);
                ldsm4(af[i][0], af[i][1], af[i][2], af[i][3], a);
            }
            unsigned bh[2][4];
#pragma unroll
            for (int p = 0; p < 2; p++) {
                int row = wn * 32 + p * 16 + lrow;
                uint32_t b = bufb + 8192 + row * 64 + ((((c0 + lch) ^ ((row >> 1) & 3))) << 4);
                ldsm4(bh[p][0], bh[p][1], bh[p][2], bh[p][3], b);
            }
#pragma unroll
            for (int j = 0; j < 4; j++) {
                int p = j >> 1, o = j & 1;
                unsigned b0 = bh[p][o], b1 = bh[p][o + 2];
#pragma unroll
                for (int i = 0; i < 4; i++)
                    mma16816(acc[i][j], af[i][0], af[i][1], af[i][2], af[i][3], b0, b1);
            }
        }
    }

#pragma unroll
    for (int i = 0; i < 4; i++) {
#pragma unroll
        for (int j = 0; j < 4; j++) {
            int row = m0 + wm * 64 + i * 16 + g;
            int col = n0 + wn * 32 + j * 8 + 2 * q;
            *(unsigned*)&Chi[(size_t)row * N + col]       = pack_f16(acc[i][j][0], acc[i][j][1]);
            *(unsigned*)&Chi[(size_t)(row + 8) * N + col] = pack_f16(acc[i][j][2], acc[i][j][3]);
        }
    }
}

// ---------------- attention: 128 q-rows/CTA, register softmax ----------------
#define AK_OFF  0
#define AV_OFF  16384
#define AQH_OFF 32768
#define AQL_OFF 49152
#define AP_OFF  32768
#define AM_OFF  65536
#define ASTM_OFF 81920
#define ASTS_OFF 83968
#define ATTN_SMEM 86016

__global__ __launch_bounds__(256, 2) void attn_mma(
    const __half* __restrict__ qhi, const __half* __restrict__ qlo,
    const __half* __restrict__ kf, const __half* __restrict__ vf,
    const void* __restrict__ mask, float* __restrict__ attn_out,
    __half* __restrict__ resf)
{
    extern __shared__ char smc[];
    uint32_t sb = (uint32_t)__cvta_generic_to_shared(smc);
    float* stM = (float*)(smc + ASTM_OFF);
    float* stS = (float*)(smc + ASTS_OFF);

    const int tid = threadIdx.x;
    const int lane = tid & 31, wid = tid >> 5;
    const int g = lane >> 2, q = lane & 3;
    const int lrow = (lane & 7) + ((lane >> 3) & 1) * 8;
    const int lch  = lane >> 4;
    const int h  = blockIdx.x & 7;
    const int bn = blockIdx.x >> 3;
    const int kind = g_flag_not01 ? 2 : (g_flag_float ? 1 : 0);

    const size_t base = (size_t)bn * 128 * DD + (size_t)h * 64;

    // group 0: K, Qh, Ql
    {
#pragma unroll
        for (int t = 0; t < 4; t++) {
            int idx = tid + t * 256;
            int row = idx >> 3, ch = idx & 7;
            uint32_t sw = row * 128 + (((ch ^ (row & 7))) << 4);
            size_t go = base + (size_t)row * DD + ch * 8;
            cpa16(sb + AK_OFF  + sw, kf  + go);
            cpa16(sb + AQH_OFF + sw, qhi + go);
            cpa16(sb + AQL_OFF + sw, qlo + go);
        }
        asm volatile("cp.async.commit_group;");
    }
    // group 1: V (+ mask if u8)
    {
#pragma unroll
        for (int t = 0; t < 4; t++) {
            int idx = tid + t * 256;
            int row = idx >> 3, ch = idx & 7;
            uint32_t sw = row * 128 + (((ch ^ (row & 7))) << 4);
            cpa16(sb + AV_OFF + sw, vf + base + (size_t)row * DD + ch * 8);
        }
        if (kind == 2) {
#pragma unroll
            for (int t = 0; t < 4; t++) {
                int idx = tid + t * 256;
                int row = idx >> 3, ch = idx & 7;
                cpa16(sb + AM_OFF + row * 128 + ch * 16,
                      (const unsigned char*)mask + (size_t)bn * 16384 + (size_t)row * 128 + ch * 16);
            }
        }
        asm volatile("cp.async.commit_group;");
    }
    asm volatile("cp.async.wait_group 1;");
    __syncthreads();

    const int wm = wid & 1, wn = wid >> 1;

    // QK^T — hi pass then lo pass per kb
    float acc[4][4][4] = {};
#pragma unroll
    for (int kb = 0; kb < 64; kb += 16) {
        int c0 = kb >> 3;
        unsigned ah[4][4], al[4][4];
#pragma unroll
        for (int i = 0; i < 4; i++) {
            int row = wm * 64 + i * 16 + lrow;
            uint32_t a = sb + AQH_OFF + row * 128 + ((((c0 + lch) ^ (row & 7))) << 4);
            ldsm4(ah[i][0], ah[i][1], ah[i][2], ah[i][3], a);
            ldsm4(al[i][0], al[i][1], al[i][2], al[i][3], a + 16384);
        }
        unsigned bk[2][4];
#pragma unroll
        for (int p = 0; p < 2; p++) {
            int row = wn * 32 + p * 16 + lrow;
            uint32_t b = sb + AK_OFF + row * 128 + ((((c0 + lch) ^ (row & 7))) << 4);
            ldsm4(bk[p][0], bk[p][1], bk[p][2], bk[p][3], b);
        }
#pragma unroll
        for (int j = 0; j < 4; j++) {
            int p = j >> 1, o = j & 1;
            unsigned b0 = bk[p][o], b1 = bk[p][o + 2];
#pragma unroll
            for (int i = 0; i < 4; i++)
                mma16816(acc[i][j], ah[i][0], ah[i][1], ah[i][2], ah[i][3], b0, b1);
        }
#pragma unroll
        for (int j = 0; j < 4; j++) {
            int p = j >> 1, o = j & 1;
            unsigned b0 = bk[p][o], b1 = bk[p][o + 2];
#pragma unroll
            for (int i = 0; i < 4; i++)
                mma16816(acc[i][j], al[i][0], al[i][1], al[i][2], al[i][3], b0, b1);
        }
    }

    asm volatile("cp.async.wait_group 0;");
    __syncthreads();

    // mask + scale
#pragma unroll
    for (int i = 0; i < 4; i++) {
#pragma unroll
        for (int hf = 0; hf < 2; hf++) {
            int r = wm * 64 + i * 16 + g + hf * 8;
#pragma unroll
            for (int j = 0; j < 4; j++) {
                int c = wn * 32 + j * 8 + 2 * q;
                float m0, m1;
                if (kind == 2) {
                    uchar2 mk = *(const uchar2*)(smc + AM_OFF + r * 128 + c);
                    m0 = mk.x ? 0.f : -1e9f; m1 = mk.y ? 0.f : -1e9f;
                } else if (kind == 1) {
                    float2 mk = *(const float2*)((const float*)mask + (size_t)bn * 16384 + (size_t)r * 128 + c);
                    m0 = (mk.x != 0.f) ? 0.f : -1e9f; m1 = (mk.y != 0.f) ? 0.f : -1e9f;
                } else {
                    int2 mk = *(const int2*)((const int*)mask + (size_t)bn * 16384 + (size_t)r * 128 + c);
                    m0 = mk.x ? 0.f : -1e9f; m1 = mk.y ? 0.f : -1e9f;
                }
                acc[i][j][2 * hf]     = acc[i][j][2 * hf]     * 0.125f + m0;
                acc[i][j][2 * hf + 1] = acc[i][j][2 * hf + 1] * 0.125f + m1;
            }
        }
    }

    // row max
#pragma unroll
    for (int i = 0; i < 4; i++)
#pragma unroll
        for (int hf = 0; hf < 2; hf++) {
            float m = -3.4e38f;
#pragma unroll
            for (int j = 0; j < 4; j++)
                m = fmaxf(m, fmaxf(acc[i][j][2 * hf], acc[i][j][2 * hf + 1]));
            m = fmaxf(m, __shfl_xor_sync(0xffffffffu, m, 1));
            m = fmaxf(m, __shfl_xor_sync(0xffffffffu, m, 2));
            if (q == 0) stM[(wm * 64 + i * 16 + g + hf * 8) * 4 + wn] = m;
        }
    __syncthreads();

    float inv[4][2];
#pragma unroll
    for (int i = 0; i < 4; i++)
#pragma unroll
        for (int hf = 0; hf < 2; hf++) {
            int r = wm * 64 + i * 16 + g + hf * 8;
            float gm = fmaxf(fmaxf(stM[r * 4], stM[r * 4 + 1]), fmaxf(stM[r * 4 + 2], stM[r * 4 + 3]));
            float s = 0.f;
#pragma unroll
            for (int j = 0; j < 4; j++) {
                float e0 = __expf(acc[i][j][2 * hf]     - gm);
                float e1 = __expf(acc[i][j][2 * hf + 1] - gm);
                acc[i][j][2 * hf] = e0; acc[i][j][2 * hf + 1] = e1;
                s += e0 + e1;
            }
            s += __shfl_xor_sync(0xffffffffu, s, 1);
            s += __shfl_xor_sync(0xffffffffu, s, 2);
            if (q == 0) stS[r * 4 + wn] = s;
        }
    __syncthreads();

#pragma unroll
    for (int i = 0; i < 4; i++)
#pragma unroll
        for (int hf = 0; hf < 2; hf++) {
            int r = wm * 64 + i * 16 + g + hf * 8;
            inv[i][hf] = 1.0f / (stS[r * 4] + stS[r * 4 + 1] + stS[r * 4 + 2] + stS[r * 4 + 3]);
        }

    // normalize + attn_out (streaming) + P f16 pack
    {
        float* aout = attn_out + ((size_t)(bn * 8 + h)) * 16384;
#pragma unroll
        for (int i = 0; i < 4; i++)
#pragma unroll
            for (int hf = 0; hf < 2; hf++) {
                int r = wm * 64 + i * 16 + g + hf * 8;
                float iv = inv[i][hf];
#pragma unroll
                for (int j = 0; j < 4; j++) {
                    int c = wn * 32 + j * 8 + 2 * q;
                    float p0 = acc[i][j][2 * hf] * iv;
                    float p1 = acc[i][j][2 * hf + 1] * iv;
                    stcs2(&aout[(size_t)r * 128 + c], p0, p1);
                    uint32_t off = r * 256 + ((((c >> 3) ^ (r & 7))) << 4) + (c & 7) * 2;
                    *(unsigned*)(smc + AP_OFF + off) = pack_f16(p0, p1);
                }
            }
    }
    __syncthreads();

    // P @ V
    float ao[4][2][4] = {};
#pragma unroll
    for (int kb = 0; kb < 8; kb++) {
        int c0 = kb * 2;
        unsigned ph[4][4];
#pragma unroll
        for (int i = 0; i < 4; i++) {
            int row = wm * 64 + i * 16 + lrow;
            uint32_t a = sb + AP_OFF + row * 256 + ((((c0 + lch) ^ (row & 7))) << 4);
            ldsm4(ph[i][0], ph[i][1], ph[i][2], ph[i][3], a);
        }
        int vrow = kb * 16 + lrow;
        uint32_t vb = sb + AV_OFF + vrow * 128 + ((((wn * 2 + lch) ^ (vrow & 7))) << 4);
        unsigned vv[4];
        ldsm4t(vv[0], vv[1], vv[2], vv[3], vb);
#pragma unroll
        for (int j = 0; j < 2; j++) {
            unsigned b0 = vv[2 * j], b1 = vv[2 * j + 1];
#pragma unroll
            for (int i = 0; i < 4; i++)
                mma16816(ao[i][j], ph[i][0], ph[i][1], ph[i][2], ph[i][3], b0, b1);
        }
    }

#pragma unroll
    for (int i = 0; i < 4; i++)
#pragma unroll
        for (int j = 0; j < 2; j++) {
            int row = wm * 64 + i * 16 + g;
            int col = h * 64 + wn * 16 + j * 8 + 2 * q;
            size_t o0 = ((size_t)(bn * 128 + row)) * DD + col;
            size_t o1 = o0 + 8ull * DD;
            *(unsigned*)&resf[o0] = pack_f16(ao[i][j][0], ao[i][j][1]);
            *(unsigned*)&resf[o1] = pack_f16(ao[i][j][2], ao[i][j][3]);
        }
}

// ---------------- residual + LayerNorm: warp per row ----------------
__global__ __launch_bounds__(256) void ln_kernel(
    const __half* __restrict__ O, const float* __restrict__ X,
    const float* __restrict__ gamma, const float* __restrict__ beta,
    float* __restrict__ Y)
{
    const int lane = threadIdx.x & 31, w = threadIdx.x >> 5;
    const size_t row = (size_t)blockIdx.x * 8 + w;
    const size_t base = row * DD;

    float x[16];
    float s = 0.f, s2 = 0.f;
#pragma unroll
    for (int c = 0; c < 4; c++) {
        int col = c * 128 + lane * 4;
        uint2 o2 = *(const uint2*)&O[base + col];
        float4 xf = *(const float4*)&X[base + col];
        float v0 = f16lo(o2.x) + xf.x;
        float v1 = f16hi(o2.x) + xf.y;
        float v2 = f16lo(o2.y) + xf.z;
        float v3 = f16hi(o2.y) + xf.w;
        x[c * 4 + 0] = v0; x[c * 4 + 1] = v1; x[c * 4 + 2] = v2; x[c * 4 + 3] = v3;
        s  += v0 + v1 + v2 + v3;
        s2 += v0 * v0 + v1 * v1 + v2 * v2 + v3 * v3;
    }
#pragma unroll
    for (int o = 16; o; o >>= 1) {
        s  += __shfl_xor_sync(0xffffffffu, s,  o);
        s2 += __shfl_xor_sync(0xffffffffu, s2, o);
    }
    float mean = s * (1.0f / DD);
    float var  = s2 * (1.0f / DD) - mean * mean;
    float inv  = rsqrtf(var + 1e-5f);

#pragma unroll
    for (int c = 0; c < 4; c++) {
        int col = c * 128 + lane * 4;
        float4 gm = *(const float4*)&gamma[col];
        float4 bt = *(const float4*)&beta[col];
        float4 yv;
        yv.x = (x[c * 4 + 0] - mean) * inv * gm.x + bt.x;
        yv.y = (x[c * 4 + 1] - mean) * inv * gm.y + bt.y;
        yv.z = (x[c * 4 + 2] - mean) * inv * gm.z + bt.z;
        yv.w = (x[c * 4 + 3] - mean) * inv * gm.w + bt.w;
        *(float4*)&Y[base + col] = yv;
    }
}

// ---------------- launch ----------------
extern "C" void kernel_launch(void* const* d_in, const int* in_sizes, int n_in,
                              void* d_out, int out_size)
{
    const float* Q     = (const float*)d_in[0];
    const float* K     = (const float*)d_in[1];
    const float* V     = (const float*)d_in[2];
    const void*  mask  = d_in[3];
    const float* WQ    = (const float*)d_in[4];
    const float* WK    = (const float*)d_in[5];
    const float* WV    = (const float*)d_in[6];
    const float* Wfc   = (const float*)d_in[7];
    const float* gamma = (const float*)d_in[8];
    const float* beta  = (const float*)d_in[9];

    float* y    = (float*)d_out;
    float* attn = y + (size_t)YSIZE;

    void *p;
    cudaGetSymbolAddress(&p, g_inf);  __half* inf  = (__half*)p;
    cudaGetSymbolAddress(&p, g_whi);  __half* whi  = (__half*)p;
    cudaGetSymbolAddress(&p, g_wlo);  __half* wlo  = (__half*)p;
    cudaGetSymbolAddress(&p, g_qh);   __half* qh   = (__half*)p;
    cudaGetSymbolAddress(&p, g_ql);   __half* ql   = (__half*)p;
    cudaGetSymbolAddress(&p, g_kf);   __half* kf   = (__half*)p;
    cudaGetSymbolAddress(&p, g_vf);   __half* vfp  = (__half*)p;
    cudaGetSymbolAddress(&p, g_resf); __half* resf = (__half*)p;
    cudaGetSymbolAddress(&p, g_outp); __half* outp = (__half*)p;

    cudaFuncSetAttribute(qkv_gemm, cudaFuncAttributeMaxDynamicSharedMemorySize, GEMM_SMEM);
    cudaFuncSetAttribute(fc_gemm,  cudaFuncAttributeMaxDynamicSharedMemorySize, FC_SMEM);
    cudaFuncSetAttribute(attn_mma, cudaFuncAttributeMaxDynamicSharedMemorySize, ATTN_SMEM);

    detect_reset<<<1, 1>>>();
    detect_scan<<<64, 256>>>((const uint4*)mask);

    const int n4 = (int)(NE_C / 4);
    conv3_kernel<<<3 * (n4 / 256), 256>>>(Q, K, V, inf, n4);
    const int w4 = (int)(WE_C / 4);
    wsplit_kernel<<<4 * (w4 / 256), 256>>>(WQ, WK, WV, Wfc, whi, wlo, w4);

    qkv_gemm<<<dim3(12, NTOK / 128), 256, GEMM_SMEM>>>(inf, whi, wlo, qh, ql, kf, vfp);

    attn_mma<<<BB * NNN * HH, 256, ATTN_SMEM>>>(qh, ql, kf, vfp, mask, attn, resf);

    fc_gemm<<<dim3(4, NTOK / 128), 256, FC_SMEM>>>(resf, whi + 3 * WE_C, outp);

    ln_kernel<<<NTOK / 8, 256>>>(outp, Q, gamma, beta, y);
}

// round 13
// speedup vs baseline: 1.5284x; 1.1760x over previous
#include <cuda_runtime.h>
#include <cuda_fp16.h>
#include <cstdint>

#define BB   16
#define NNN  32
#define SS   128
#define DD   512
#define HH   8
#define NTOK (BB*NNN*SS)          // 65536
#define YSIZE  (NTOK*DD)          // 33554432

// ---------------- scratch ----------------
__device__ __half g_inf[3ull*NTOK*DD];    // inputs Q,K,V single f16
__device__ __half g_whi[4ull*DD*DD];      // weights single f16 (hi)
__device__ __half g_qf[(size_t)NTOK*DD];  // Q proj single
__device__ __half g_kf[(size_t)NTOK*DD];  // K proj single
__device__ __half g_vf[(size_t)NTOK*DD];  // V proj single
__device__ __half g_resf[(size_t)NTOK*DD];// attn result single
__device__ __half g_outp[(size_t)NTOK*DD];// FC result f16
__device__ int    g_flag_float, g_flag_not01;

// ---------------- mask dtype detection ----------------
__global__ void detect_reset() { g_flag_float = 0; g_flag_not01 = 0; }
__global__ __launch_bounds__(256) void detect_scan(const uint4* __restrict__ mw) {
    int i = blockIdx.x * 256 + threadIdx.x;
    uint4 w = mw[i];
    int isf = (w.x == 0x3f800000u) | (w.y == 0x3f800000u) | (w.z == 0x3f800000u) | (w.w == 0x3f800000u);
    int n01 = ((w.x > 1u) & (w.x != 0x3f800000u)) | ((w.y > 1u) & (w.y != 0x3f800000u))
            | ((w.z > 1u) & (w.z != 0x3f800000u)) | ((w.w > 1u) & (w.w != 0x3f800000u));
    int bf = __syncthreads_or(isf);
    int bn = __syncthreads_or(n01);
    if (threadIdx.x == 0) {
        if (bf) atomicOr(&g_flag_float, 1);
        if (bn) atomicOr(&g_flag_not01, 1);
    }
}

// ---------------- helpers ----------------
__device__ __forceinline__ unsigned pack_f16(float lo, float hi) {
    __half2 h = __floats2half2_rn(lo, hi);
    return *(unsigned*)&h;
}
__device__ __forceinline__ float f16lo(unsigned u) { return __low2float(*(__half2*)&u); }
__device__ __forceinline__ float f16hi(unsigned u) { return __high2float(*(__half2*)&u); }

__device__ __forceinline__ void mma16816(float c[4],
    unsigned a0, unsigned a1, unsigned a2, unsigned a3, unsigned b0, unsigned b1)
{
    asm volatile(
        "mma.sync.aligned.m16n8k16.row.col.f32.f16.f16.f32 "
        "{%0,%1,%2,%3}, {%4,%5,%6,%7}, {%8,%9}, {%0,%1,%2,%3};"
        : "+f"(c[0]), "+f"(c[1]), "+f"(c[2]), "+f"(c[3])
        : "r"(a0), "r"(a1), "r"(a2), "r"(a3), "r"(b0), "r"(b1));
}
__device__ __forceinline__ void cpa16(uint32_t s, const void* g) {
    asm volatile("cp.async.cg.shared.global [%0], [%1], 16;" :: "r"(s), "l"(g));
}
__device__ __forceinline__ void ldsm4(unsigned& r0, unsigned& r1, unsigned& r2, unsigned& r3, uint32_t a) {
    asm volatile("ldmatrix.sync.aligned.m8n8.x4.shared.b16 {%0,%1,%2,%3}, [%4];"
        : "=r"(r0), "=r"(r1), "=r"(r2), "=r"(r3) : "r"(a));
}
__device__ __forceinline__ void ldsm4t(unsigned& r0, unsigned& r1, unsigned& r2, unsigned& r3, uint32_t a) {
    asm volatile("ldmatrix.sync.aligned.m8n8.x4.trans.shared.b16 {%0,%1,%2,%3}, [%4];"
        : "=r"(r0), "=r"(r1), "=r"(r2), "=r"(r3) : "r"(a));
}
__device__ __forceinline__ void stcs2(float* p, float a, float b) {
    asm volatile("st.global.cs.v2.f32 [%0], {%1,%2};" :: "l"(p), "f"(a), "f"(b) : "memory");
}

// ---------------- fp32 -> f16 single (3 inputs merged) ----------------
__global__ __launch_bounds__(256) void conv3_kernel(
    const float* __restrict__ s0, const float* __restrict__ s1, const float* __restrict__ s2,
    __half* __restrict__ dst, int n4)
{
    int b = blockIdx.x;
    int sel = b / (n4 / 256);
    int i = (b % (n4 / 256)) * 256 + threadIdx.x;
    const float* src = sel == 0 ? s0 : (sel == 1 ? s1 : s2);
    float4 v = ((const float4*)src)[i];
    ((uint2*)dst)[(size_t)sel * n4 + i] = make_uint2(pack_f16(v.x, v.y), pack_f16(v.z, v.w));
}

// ---------------- weights: 4 -> f16 single ----------------
__global__ __launch_bounds__(256) void wconv_kernel(
    const float* __restrict__ s0, const float* __restrict__ s1,
    const float* __restrict__ s2, const float* __restrict__ s3,
    __half* __restrict__ hi, int n4)
{
    int b = blockIdx.x;
    int sel = b / (n4 / 256);
    int i = (b % (n4 / 256)) * 256 + threadIdx.x;
    const float* src = sel == 0 ? s0 : (sel == 1 ? s1 : (sel == 2 ? s2 : s3));
    float4 v = ((const float4*)src)[i];
    ((uint2*)hi)[(size_t)sel * n4 + i] = make_uint2(pack_f16(v.x, v.y), pack_f16(v.z, v.w));
}

// ---------------- GEMM core: A f16, B f16, f16 out; 2-plane 3-stage ----------------
#define FSTG 16384
#define FC_SMEM (3*FSTG)
#define NE_C ((size_t)NTOK * DD)
#define WE_C ((size_t)DD * DD)

// merged QKV: grid (12, M/128); px = bx>>2, n-tile = bx&3
__global__ __launch_bounds__(256, 2) void qkv_gemm(
    const __half* __restrict__ inf, const __half* __restrict__ whi,
    __half* __restrict__ qf, __half* __restrict__ kf, __half* __restrict__ vf)
{
    extern __shared__ __half gsm[];
    const int tid = threadIdx.x;
    const int lane = tid & 31, wid = tid >> 5;
    const int wm = wid & 1, wn = wid >> 1;
    const int g = lane >> 2, q = lane & 3;
    const int lrow = (lane & 7) + ((lane >> 3) & 1) * 8;
    const int lch  = lane >> 4;
    const int px = blockIdx.x >> 2;
    const int n0 = (blockIdx.x & 3) * 128, m0 = blockIdx.y * 128;
    const int K = DD, N = DD;
    uint32_t sb = (uint32_t)__cvta_generic_to_shared(gsm);

    const __half* Af  = inf + (size_t)px * NE_C;
    const __half* Bhi = whi + (size_t)px * WE_C;

    auto issue = [&](int grp) {
        int k0 = grp << 5;
        uint32_t stg = sb + (grp % 3) * FSTG;
#pragma unroll
        for (int j = 0; j < 4; j++) {
            int idx = tid + (j & 1) * 256;
            int sub = j >> 1;
            int row = idx >> 2, ch = idx & 3;
            const __half* gp = (sub == 0 ? Af + (size_t)(m0 + row) * K
                                         : Bhi + (size_t)(n0 + row) * K) + k0 + ch * 8;
            cpa16(stg + sub * 8192 + row * 64 + (((ch ^ ((row >> 1) & 3))) << 4), gp);
        }
        asm volatile("cp.async.commit_group;");
    };

    float acc[4][4][4] = {};
    const int nIter = K >> 5;
    issue(0); issue(1);

    for (int it = 0; it < nIter; it++) {
        if (it < nIter - 1) asm volatile("cp.async.wait_group 1;");
        else                asm volatile("cp.async.wait_group 0;");
        __syncthreads();
        if (it + 2 < nIter) issue(it + 2);
        uint32_t bufb = sb + (it % 3) * FSTG;
#pragma unroll
        for (int kb = 0; kb < 32; kb += 16) {
            int c0 = kb >> 3;
            unsigned af[4][4];
#pragma unroll
            for (int i = 0; i < 4; i++) {
                int row = wm * 64 + i * 16 + lrow;
                uint32_t a = bufb + row * 64 + ((((c0 + lch) ^ ((row >> 1) & 3))) << 4);
                ldsm4(af[i][0], af[i][1], af[i][2], af[i][3], a);
            }
            unsigned bh[2][4];
#pragma unroll
            for (int p = 0; p < 2; p++) {
                int row = wn * 32 + p * 16 + lrow;
                uint32_t b = bufb + 8192 + row * 64 + ((((c0 + lch) ^ ((row >> 1) & 3))) << 4);
                ldsm4(bh[p][0], bh[p][1], bh[p][2], bh[p][3], b);
            }
#pragma unroll
            for (int j = 0; j < 4; j++) {
                int p = j >> 1, o = j & 1;
                unsigned b0 = bh[p][o], b1 = bh[p][o + 2];
#pragma unroll
                for (int i = 0; i < 4; i++)
                    mma16816(acc[i][j], af[i][0], af[i][1], af[i][2], af[i][3], b0, b1);
            }
        }
    }

    __half* Chi = px == 0 ? qf : (px == 1 ? kf : vf);
#pragma unroll
    for (int i = 0; i < 4; i++) {
#pragma unroll
        for (int j = 0; j < 4; j++) {
            int row = m0 + wm * 64 + i * 16 + g;
            int col = n0 + wn * 32 + j * 8 + 2 * q;
            *(unsigned*)&Chi[(size_t)row * N + col]       = pack_f16(acc[i][j][0], acc[i][j][1]);
            *(unsigned*)&Chi[(size_t)(row + 8) * N + col] = pack_f16(acc[i][j][2], acc[i][j][3]);
        }
    }
}

// FC GEMM (same core, single launch over resf)
__global__ __launch_bounds__(256, 2) void fc_gemm(
    const __half* __restrict__ Af, const __half* __restrict__ Bhi,
    __half* __restrict__ Chi)
{
    extern __shared__ __half gsm[];
    const int tid = threadIdx.x;
    const int lane = tid & 31, wid = tid >> 5;
    const int wm = wid & 1, wn = wid >> 1;
    const int g = lane >> 2, q = lane & 3;
    const int lrow = (lane & 7) + ((lane >> 3) & 1) * 8;
    const int lch  = lane >> 4;
    const int n0 = blockIdx.x * 128, m0 = blockIdx.y * 128;
    const int K = DD, N = DD;
    uint32_t sb = (uint32_t)__cvta_generic_to_shared(gsm);

    auto issue = [&](int grp) {
        int k0 = grp << 5;
        uint32_t stg = sb + (grp % 3) * FSTG;
#pragma unroll
        for (int j = 0; j < 4; j++) {
            int idx = tid + (j & 1) * 256;
            int sub = j >> 1;
            int row = idx >> 2, ch = idx & 3;
            const __half* gp = (sub == 0 ? Af + (size_t)(m0 + row) * K
                                         : Bhi + (size_t)(n0 + row) * K) + k0 + ch * 8;
            cpa16(stg + sub * 8192 + row * 64 + (((ch ^ ((row >> 1) & 3))) << 4), gp);
        }
        asm volatile("cp.async.commit_group;");
    };

    float acc[4][4][4] = {};
    const int nIter = K >> 5;
    issue(0); issue(1);

    for (int it = 0; it < nIter; it++) {
        if (it < nIter - 1) asm volatile("cp.async.wait_group 1;");
        else                asm volatile("cp.async.wait_group 0;");
        __syncthreads();
        if (it + 2 < nIter) issue(it + 2);
        uint32_t bufb = sb + (it % 3) * FSTG;
#pragma unroll
        for (int kb = 0; kb < 32; kb += 16) {
            int c0 = kb >> 3;
            unsigned af[4][4];
#pragma unroll
            for (int i = 0; i < 4; i++) {
                int row = wm * 64 + i * 16 + lrow;
                uint32_t a = bufb + row * 64 + ((((c0 + lch) ^ ((row >> 1) & 3))) << 4);
                ldsm4(af[i][0], af[i][1], af[i][2], af[i][3], a);
            }
            unsigned bh[2][4];
#pragma unroll
            for (int p = 0; p < 2; p++) {
                int row = wn * 32 + p * 16 + lrow;
                uint32_t b = bufb + 8192 + row * 64 + ((((c0 + lch) ^ ((row >> 1) & 3))) << 4);
                ldsm4(bh[p][0], bh[p][1], bh[p][2], bh[p][3], b);
            }
#pragma unroll
            for (int j = 0; j < 4; j++) {
                int p = j >> 1, o = j & 1;
                unsigned b0 = bh[p][o], b1 = bh[p][o + 2];
#pragma unroll
                for (int i = 0; i < 4; i++)
                    mma16816(acc[i][j], af[i][0], af[i][1], af[i][2], af[i][3], b0, b1);
            }
        }
    }

#pragma unroll
    for (int i = 0; i < 4; i++) {
#pragma unroll
        for (int j = 0; j < 4; j++) {
            int row = m0 + wm * 64 + i * 16 + g;
            int col = n0 + wn * 32 + j * 8 + 2 * q;
            *(unsigned*)&Chi[(size_t)row * N + col]       = pack_f16(acc[i][j][0], acc[i][j][1]);
            *(unsigned*)&Chi[(size_t)(row + 8) * N + col] = pack_f16(acc[i][j][2], acc[i][j][3]);
        }
    }
}

// ---------------- attention: 128 q-rows/CTA, register softmax, all-single f16 ----------------
// smem: K @0 (16KB), V @16384 (16KB), Q @32768 (16KB);
// P single f16 aliases 32768..65536 (128 x 256B rows);
// mask u8 @65536 (16KB); stM @81920; stS @83968.
#define AK_OFF  0
#define AV_OFF  16384
#define AQ_OFF  32768
#define AP_OFF  32768
#define AM_OFF  65536
#define ASTM_OFF 81920
#define ASTS_OFF 83968
#define ATTN_SMEM 86016

__global__ __launch_bounds__(256, 2) void attn_mma(
    const __half* __restrict__ qf,
    const __half* __restrict__ kf, const __half* __restrict__ vf,
    const void* __restrict__ mask, float* __restrict__ attn_out,
    __half* __restrict__ resf)
{
    extern __shared__ char smc[];
    uint32_t sb = (uint32_t)__cvta_generic_to_shared(smc);
    float* stM = (float*)(smc + ASTM_OFF);
    float* stS = (float*)(smc + ASTS_OFF);

    const int tid = threadIdx.x;
    const int lane = tid & 31, wid = tid >> 5;
    const int g = lane >> 2, q = lane & 3;
    const int lrow = (lane & 7) + ((lane >> 3) & 1) * 8;
    const int lch  = lane >> 4;
    const int h  = blockIdx.x & 7;
    const int bn = blockIdx.x >> 3;
    const int kind = g_flag_not01 ? 2 : (g_flag_float ? 1 : 0);

    const size_t base = (size_t)bn * 128 * DD + (size_t)h * 64;

    // group 0: K, Q
    {
#pragma unroll
        for (int t = 0; t < 4; t++) {
            int idx = tid + t * 256;
            int row = idx >> 3, ch = idx & 7;
            uint32_t sw = row * 128 + (((ch ^ (row & 7))) << 4);
            size_t go = base + (size_t)row * DD + ch * 8;
            cpa16(sb + AK_OFF + sw, kf + go);
            cpa16(sb + AQ_OFF + sw, qf + go);
        }
        asm volatile("cp.async.commit_group;");
    }
    // group 1: V (+ mask if u8)
    {
#pragma unroll
        for (int t = 0; t < 4; t++) {
            int idx = tid + t * 256;
            int row = idx >> 3, ch = idx & 7;
            uint32_t sw = row * 128 + (((ch ^ (row & 7))) << 4);
            cpa16(sb + AV_OFF + sw, vf + base + (size_t)row * DD + ch * 8);
        }
        if (kind == 2) {
#pragma unroll
            for (int t = 0; t < 4; t++) {
                int idx = tid + t * 256;
                int row = idx >> 3, ch = idx & 7;
                cpa16(sb + AM_OFF + row * 128 + ch * 16,
                      (const unsigned char*)mask + (size_t)bn * 16384 + (size_t)row * 128 + ch * 16);
            }
        }
        asm volatile("cp.async.commit_group;");
    }
    asm volatile("cp.async.wait_group 1;");
    __syncthreads();

    const int wm = wid & 1, wn = wid >> 1;

    // QK^T (single-precision-f16 both operands)
    float acc[4][4][4] = {};
#pragma unroll
    for (int kb = 0; kb < 64; kb += 16) {
        int c0 = kb >> 3;
        unsigned ah[4][4];
#pragma unroll
        for (int i = 0; i < 4; i++) {
            int row = wm * 64 + i * 16 + lrow;
            uint32_t a = sb + AQ_OFF + row * 128 + ((((c0 + lch) ^ (row & 7))) << 4);
            ldsm4(ah[i][0], ah[i][1], ah[i][2], ah[i][3], a);
        }
        unsigned bk[2][4];
#pragma unroll
        for (int p = 0; p < 2; p++) {
            int row = wn * 32 + p * 16 + lrow;
            uint32_t b = sb + AK_OFF + row * 128 + ((((c0 + lch) ^ (row & 7))) << 4);
            ldsm4(bk[p][0], bk[p][1], bk[p][2], bk[p][3], b);
        }
#pragma unroll
        for (int j = 0; j < 4; j++) {
            int p = j >> 1, o = j & 1;
            unsigned b0 = bk[p][o], b1 = bk[p][o + 2];
#pragma unroll
            for (int i = 0; i < 4; i++)
                mma16816(acc[i][j], ah[i][0], ah[i][1], ah[i][2], ah[i][3], b0, b1);
        }
    }

    asm volatile("cp.async.wait_group 0;");
    __syncthreads();

    // mask + scale
#pragma unroll
    for (int i = 0; i < 4; i++) {
#pragma unroll
        for (int hf = 0; hf < 2; hf++) {
            int r = wm * 64 + i * 16 + g + hf * 8;
#pragma unroll
            for (int j = 0; j < 4; j++) {
                int c = wn * 32 + j * 8 + 2 * q;
                float m0, m1;
                if (kind == 2) {
                    uchar2 mk = *(const uchar2*)(smc + AM_OFF + r * 128 + c);
                    m0 = mk.x ? 0.f : -1e9f; m1 = mk.y ? 0.f : -1e9f;
                } else if (kind == 1) {
                    float2 mk = *(const float2*)((const float*)mask + (size_t)bn * 16384 + (size_t)r * 128 + c);
                    m0 = (mk.x != 0.f) ? 0.f : -1e9f; m1 = (mk.y != 0.f) ? 0.f : -1e9f;
                } else {
                    int2 mk = *(const int2*)((const int*)mask + (size_t)bn * 16384 + (size_t)r * 128 + c);
                    m0 = mk.x ? 0.f : -1e9f; m1 = mk.y ? 0.f : -1e9f;
                }
                acc[i][j][2 * hf]     = acc[i][j][2 * hf]     * 0.125f + m0;
                acc[i][j][2 * hf + 1] = acc[i][j][2 * hf + 1] * 0.125f + m1;
            }
        }
    }

    // row max
#pragma unroll
    for (int i = 0; i < 4; i++)
#pragma unroll
        for (int hf = 0; hf < 2; hf++) {
            float m = -3.4e38f;
#pragma unroll
            for (int j = 0; j < 4; j++)
                m = fmaxf(m, fmaxf(acc[i][j][2 * hf], acc[i][j][2 * hf + 1]));
            m = fmaxf(m, __shfl_xor_sync(0xffffffffu, m, 1));
            m = fmaxf(m, __shfl_xor_sync(0xffffffffu, m, 2));
            if (q == 0) stM[(wm * 64 + i * 16 + g + hf * 8) * 4 + wn] = m;
        }
    __syncthreads();

    float inv[4][2];
#pragma unroll
    for (int i = 0; i < 4; i++)
#pragma unroll
        for (int hf = 0; hf < 2; hf++) {
            int r = wm * 64 + i * 16 + g + hf * 8;
            float gm = fmaxf(fmaxf(stM[r * 4], stM[r * 4 + 1]), fmaxf(stM[r * 4 + 2], stM[r * 4 + 3]));
            float s = 0.f;
#pragma unroll
            for (int j = 0; j < 4; j++) {
                float e0 = __expf(acc[i][j][2 * hf]     - gm);
                float e1 = __expf(acc[i][j][2 * hf + 1] - gm);
                acc[i][j][2 * hf] = e0; acc[i][j][2 * hf + 1] = e1;
                s += e0 + e1;
            }
            s += __shfl_xor_sync(0xffffffffu, s, 1);
            s += __shfl_xor_sync(0xffffffffu, s, 2);
            if (q == 0) stS[r * 4 + wn] = s;
        }
    __syncthreads();

#pragma unroll
    for (int i = 0; i < 4; i++)
#pragma unroll
        for (int hf = 0; hf < 2; hf++) {
            int r = wm * 64 + i * 16 + g + hf * 8;
            inv[i][hf] = 1.0f / (stS[r * 4] + stS[r * 4 + 1] + stS[r * 4 + 2] + stS[r * 4 + 3]);
        }

    // normalize + attn_out (streaming) + P f16 pack (aliases Q region)
    {
        float* aout = attn_out + ((size_t)(bn * 8 + h)) * 16384;
#pragma unroll
        for (int i = 0; i < 4; i++)
#pragma unroll
            for (int hf = 0; hf < 2; hf++) {
                int r = wm * 64 + i * 16 + g + hf * 8;
                float iv = inv[i][hf];
#pragma unroll
                for (int j = 0; j < 4; j++) {
                    int c = wn * 32 + j * 8 + 2 * q;
                    float p0 = acc[i][j][2 * hf] * iv;
                    float p1 = acc[i][j][2 * hf + 1] * iv;
                    stcs2(&aout[(size_t)r * 128 + c], p0, p1);
                    uint32_t off = r * 256 + ((((c >> 3) ^ (r & 7))) << 4) + (c & 7) * 2;
                    *(unsigned*)(smc + AP_OFF + off) = pack_f16(p0, p1);
                }
            }
    }
    __syncthreads();

    // P @ V
    float ao[4][2][4] = {};
#pragma unroll
    for (int kb = 0; kb < 8; kb++) {
        int c0 = kb * 2;
        unsigned ph[4][4];
#pragma unroll
        for (int i = 0; i < 4; i++) {
            int row = wm * 64 + i * 16 + lrow;
            uint32_t a = sb + AP_OFF + row * 256 + ((((c0 + lch) ^ (row & 7))) << 4);
            ldsm4(ph[i][0], ph[i][1], ph[i][2], ph[i][3], a);
        }
        int vrow = kb * 16 + lrow;
        uint32_t vb = sb + AV_OFF + vrow * 128 + ((((wn * 2 + lch) ^ (vrow & 7))) << 4);
        unsigned vv[4];
        ldsm4t(vv[0], vv[1], vv[2], vv[3], vb);
#pragma unroll
        for (int j = 0; j < 2; j++) {
            unsigned b0 = vv[2 * j], b1 = vv[2 * j + 1];
#pragma unroll
            for (int i = 0; i < 4; i++)
                mma16816(ao[i][j], ph[i][0], ph[i][1], ph[i][2], ph[i][3], b0, b1);
        }
    }

#pragma unroll
    for (int i = 0; i < 4; i++)
#pragma unroll
        for (int j = 0; j < 2; j++) {
            int row = wm * 64 + i * 16 + g;
            int col = h * 64 + wn * 16 + j * 8 + 2 * q;
            size_t o0 = ((size_t)(bn * 128 + row)) * DD + col;
            size_t o1 = o0 + 8ull * DD;
            *(unsigned*)&resf[o0] = pack_f16(ao[i][j][0], ao[i][j][1]);
            *(unsigned*)&resf[o1] = pack_f16(ao[i][j][2], ao[i][j][3]);
        }
}

// ---------------- residual + LayerNorm: warp per row ----------------
__global__ __launch_bounds__(256) void ln_kernel(
    const __half* __restrict__ O, const float* __restrict__ X,
    const float* __restrict__ gamma, const float* __restrict__ beta,
    float* __restrict__ Y)
{
    const int lane = threadIdx.x & 31, w = threadIdx.x >> 5;
    const size_t row = (size_t)blockIdx.x * 8 + w;
    const size_t base = row * DD;

    float x[16];
    float s = 0.f, s2 = 0.f;
#pragma unroll
    for (int c = 0; c < 4; c++) {
        int col = c * 128 + lane * 4;
        uint2 o2 = *(const uint2*)&O[base + col];
        float4 xf = *(const float4*)&X[base + col];
        float v0 = f16lo(o2.x) + xf.x;
        float v1 = f16hi(o2.x) + xf.y;
        float v2 = f16lo(o2.y) + xf.z;
        float v3 = f16hi(o2.y) + xf.w;
        x[c * 4 + 0] = v0; x[c * 4 + 1] = v1; x[c * 4 + 2] = v2; x[c * 4 + 3] = v3;
        s  += v0 + v1 + v2 + v3;
        s2 += v0 * v0 + v1 * v1 + v2 * v2 + v3 * v3;
    }
#pragma unroll
    for (int o = 16; o; o >>= 1) {
        s  += __shfl_xor_sync(0xffffffffu, s,  o);
        s2 += __shfl_xor_sync(0xffffffffu, s2, o);
    }
    float mean = s * (1.0f / DD);
    float var  = s2 * (1.0f / DD) - mean * mean;
    float inv  = rsqrtf(var + 1e-5f);

#pragma unroll
    for (int c = 0; c < 4; c++) {
        int col = c * 128 + lane * 4;
        float4 gm = *(const float4*)&gamma[col];
        float4 bt = *(const float4*)&beta[col];
        float4 yv;
        yv.x = (x[c * 4 + 0] - mean) * inv * gm.x + bt.x;
        yv.y = (x[c * 4 + 1] - mean) * inv * gm.y + bt.y;
        yv.z = (x[c * 4 + 2] - mean) * inv * gm.z + bt.z;
        yv.w = (x[c * 4 + 3] - mean) * inv * gm.w + bt.w;
        *(float4*)&Y[base + col] = yv;
    }
}

// ---------------- launch ----------------
extern "C" void kernel_launch(void* const* d_in, const int* in_sizes, int n_in,
                              void* d_out, int out_size)
{
    const float* Q     = (const float*)d_in[0];
    const float* K     = (const float*)d_in[1];
    const float* V     = (const float*)d_in[2];
    const void*  mask  = d_in[3];
    const float* WQ    = (const float*)d_in[4];
    const float* WK    = (const float*)d_in[5];
    const float* WV    = (const float*)d_in[6];
    const float* Wfc   = (const float*)d_in[7];
    const float* gamma = (const float*)d_in[8];
    const float* beta  = (const float*)d_in[9];

    float* y    = (float*)d_out;
    float* attn = y + (size_t)YSIZE;

    void *p;
    cudaGetSymbolAddress(&p, g_inf);  __half* inf  = (__half*)p;
    cudaGetSymbolAddress(&p, g_whi);  __half* whi  = (__half*)p;
    cudaGetSymbolAddress(&p, g_qf);   __half* qfp  = (__half*)p;
    cudaGetSymbolAddress(&p, g_kf);   __half* kfp  = (__half*)p;
    cudaGetSymbolAddress(&p, g_vf);   __half* vfp  = (__half*)p;
    cudaGetSymbolAddress(&p, g_resf); __half* resf = (__half*)p;
    cudaGetSymbolAddress(&p, g_outp); __half* outp = (__half*)p;

    cudaFuncSetAttribute(qkv_gemm, cudaFuncAttributeMaxDynamicSharedMemorySize, FC_SMEM);
    cudaFuncSetAttribute(fc_gemm,  cudaFuncAttributeMaxDynamicSharedMemorySize, FC_SMEM);
    cudaFuncSetAttribute(attn_mma, cudaFuncAttributeMaxDynamicSharedMemorySize, ATTN_SMEM);

    detect_reset<<<1, 1>>>();
    detect_scan<<<64, 256>>>((const uint4*)mask);

    const int n4 = (int)(NE_C / 4);
    conv3_kernel<<<3 * (n4 / 256), 256>>>(Q, K, V, inf, n4);
    const int w4 = (int)(WE_C / 4);
    wconv_kernel<<<4 * (w4 / 256), 256>>>(WQ, WK, WV, Wfc, whi, w4);

    qkv_gemm<<<dim3(12, NTOK / 128), 256, FC_SMEM>>>(inf, whi, qfp, kfp, vfp);

    attn_mma<<<BB * NNN * HH, 256, ATTN_SMEM>>>(qfp, kfp, vfp, mask, attn, resf);

    fc_gemm<<<dim3(4, NTOK / 128), 256, FC_SMEM>>>(resf, whi + 3 * WE_C, outp);

    ln_kernel<<<NTOK / 8, 256>>>(outp, Q, gamma, beta, y);
}

// round 14
// speedup vs baseline: 1.5417x; 1.0088x over previous
#include <cuda_runtime.h>
#include <cuda_fp16.h>
#include <cstdint>

#define BB   16
#define NNN  32
#define SS   128
#define DD   512
#define HH   8
#define NTOK (BB*NNN*SS)          // 65536
#define YSIZE  (NTOK*DD)          // 33554432

// ---------------- scratch ----------------
__device__ __half g_inf[3ull*NTOK*DD];    // inputs Q,K,V single f16
__device__ __half g_whi[4ull*DD*DD];      // weights single f16
__device__ __half g_qf[(size_t)NTOK*DD];
__device__ __half g_kf[(size_t)NTOK*DD];
__device__ __half g_vf[(size_t)NTOK*DD];
__device__ __half g_resf[(size_t)NTOK*DD];
__device__ __half g_outp[(size_t)NTOK*DD];
__device__ int    g_flag_float, g_flag_not01;

// ---------------- mask dtype detection ----------------
__global__ void detect_reset() { g_flag_float = 0; g_flag_not01 = 0; }
__global__ __launch_bounds__(256) void detect_scan(const uint4* __restrict__ mw) {
    int i = blockIdx.x * 256 + threadIdx.x;
    uint4 w = mw[i];
    int isf = (w.x == 0x3f800000u) | (w.y == 0x3f800000u) | (w.z == 0x3f800000u) | (w.w == 0x3f800000u);
    int n01 = ((w.x > 1u) & (w.x != 0x3f800000u)) | ((w.y > 1u) & (w.y != 0x3f800000u))
            | ((w.z > 1u) & (w.z != 0x3f800000u)) | ((w.w > 1u) & (w.w != 0x3f800000u));
    int bf = __syncthreads_or(isf);
    int bn = __syncthreads_or(n01);
    if (threadIdx.x == 0) {
        if (bf) atomicOr(&g_flag_float, 1);
        if (bn) atomicOr(&g_flag_not01, 1);
    }
}

// ---------------- helpers ----------------
__device__ __forceinline__ unsigned pack_f16(float lo, float hi) {
    __half2 h = __floats2half2_rn(lo, hi);
    return *(unsigned*)&h;
}
__device__ __forceinline__ float f16lo(unsigned u) { return __low2float(*(__half2*)&u); }
__device__ __forceinline__ float f16hi(unsigned u) { return __high2float(*(__half2*)&u); }

__device__ __forceinline__ void mma16816(float c[4],
    unsigned a0, unsigned a1, unsigned a2, unsigned a3, unsigned b0, unsigned b1)
{
    asm volatile(
        "mma.sync.aligned.m16n8k16.row.col.f32.f16.f16.f32 "
        "{%0,%1,%2,%3}, {%4,%5,%6,%7}, {%8,%9}, {%0,%1,%2,%3};"
        : "+f"(c[0]), "+f"(c[1]), "+f"(c[2]), "+f"(c[3])
        : "r"(a0), "r"(a1), "r"(a2), "r"(a3), "r"(b0), "r"(b1));
}
__device__ __forceinline__ void cpa16(uint32_t s, const void* g) {
    asm volatile("cp.async.cg.shared.global [%0], [%1], 16;" :: "r"(s), "l"(g));
}
__device__ __forceinline__ void ldsm4(unsigned& r0, unsigned& r1, unsigned& r2, unsigned& r3, uint32_t a) {
    asm volatile("ldmatrix.sync.aligned.m8n8.x4.shared.b16 {%0,%1,%2,%3}, [%4];"
        : "=r"(r0), "=r"(r1), "=r"(r2), "=r"(r3) : "r"(a));
}
__device__ __forceinline__ void ldsm4t(unsigned& r0, unsigned& r1, unsigned& r2, unsigned& r3, uint32_t a) {
    asm volatile("ldmatrix.sync.aligned.m8n8.x4.trans.shared.b16 {%0,%1,%2,%3}, [%4];"
        : "=r"(r0), "=r"(r1), "=r"(r2), "=r"(r3) : "r"(a));
}
__device__ __forceinline__ void stcs2(float* p, float a, float b) {
    asm volatile("st.global.cs.v2.f32 [%0], {%1,%2};" :: "l"(p), "f"(a), "f"(b) : "memory");
}

// ---------------- fp32 -> f16 single (3 inputs merged) ----------------
__global__ __launch_bounds__(256) void conv3_kernel(
    const float* __restrict__ s0, const float* __restrict__ s1, const float* __restrict__ s2,
    __half* __restrict__ dst, int n4)
{
    int b = blockIdx.x;
    int sel = b / (n4 / 256);
    int i = (b % (n4 / 256)) * 256 + threadIdx.x;
    const float* src = sel == 0 ? s0 : (sel == 1 ? s1 : s2);
    float4 v = ((const float4*)src)[i];
    ((uint2*)dst)[(size_t)sel * n4 + i] = make_uint2(pack_f16(v.x, v.y), pack_f16(v.z, v.w));
}

// ---------------- weights: 4 -> f16 single ----------------
__global__ __launch_bounds__(256) void wconv_kernel(
    const float* __restrict__ s0, const float* __restrict__ s1,
    const float* __restrict__ s2, const float* __restrict__ s3,
    __half* __restrict__ hi, int n4)
{
    int b = blockIdx.x;
    int sel = b / (n4 / 256);
    int i = (b % (n4 / 256)) * 256 + threadIdx.x;
    const float* src = sel == 0 ? s0 : (sel == 1 ? s1 : (sel == 2 ? s2 : s3));
    float4 v = ((const float4*)src)[i];
    ((uint2*)hi)[(size_t)sel * n4 + i] = make_uint2(pack_f16(v.x, v.y), pack_f16(v.z, v.w));
}

// ---------------- GEMM core: K-chunk 64 per stage, 3 stages ----------------
// Stage (32KB): A 128x64 f16 @0 (128B rows, swizzle ch^(row&7)), B 128x64 @16384.
#define GSTG 32768
#define GEMM_SMEM (3*GSTG)
#define NE_C ((size_t)NTOK * DD)
#define WE_C ((size_t)DD * DD)

// merged QKV: grid (12, M/128); px = bx>>2, n-tile = bx&3
__global__ __launch_bounds__(256, 2) void qkv_gemm(
    const __half* __restrict__ inf, const __half* __restrict__ whi,
    __half* __restrict__ qf, __half* __restrict__ kf, __half* __restrict__ vf)
{
    extern __shared__ __half gsm[];
    const int tid = threadIdx.x;
    const int lane = tid & 31, wid = tid >> 5;
    const int wm = wid & 1, wn = wid >> 1;
    const int g = lane >> 2, q = lane & 3;
    const int lrow = (lane & 7) + ((lane >> 3) & 1) * 8;
    const int lch  = lane >> 4;
    const int px = blockIdx.x >> 2;
    const int n0 = (blockIdx.x & 3) * 128, m0 = blockIdx.y * 128;
    const int K = DD, N = DD;
    uint32_t sb = (uint32_t)__cvta_generic_to_shared(gsm);

    const __half* Af  = inf + (size_t)px * NE_C;
    const __half* Bhi = whi + (size_t)px * WE_C;

    auto issue = [&](int grp) {
        int k0 = grp << 6;
        uint32_t stg = sb + (grp % 3) * GSTG;
#pragma unroll
        for (int j = 0; j < 8; j++) {
            int idx = tid + (j & 3) * 256;
            int sub = j >> 2;               // 0: A, 1: B
            int row = idx >> 3, ch = idx & 7;
            const __half* gp = (sub == 0 ? Af + (size_t)(m0 + row) * K
                                         : Bhi + (size_t)(n0 + row) * K) + k0 + ch * 8;
            cpa16(stg + sub * 16384 + row * 128 + (((ch ^ (row & 7))) << 4), gp);
        }
        asm volatile("cp.async.commit_group;");
    };

    float acc[4][4][4] = {};
    const int nIter = K >> 6;   // 8
    issue(0); issue(1);

    for (int it = 0; it < nIter; it++) {
        if (it < nIter - 1) asm volatile("cp.async.wait_group 1;");
        else                asm volatile("cp.async.wait_group 0;");
        __syncthreads();
        if (it + 2 < nIter) issue(it + 2);
        uint32_t bufb = sb + (it % 3) * GSTG;
#pragma unroll
        for (int kb = 0; kb < 64; kb += 16) {
            int c0 = kb >> 3;
            unsigned af[4][4];
#pragma unroll
            for (int i = 0; i < 4; i++) {
                int row = wm * 64 + i * 16 + lrow;
                uint32_t a = bufb + row * 128 + ((((c0 + lch) ^ (row & 7))) << 4);
                ldsm4(af[i][0], af[i][1], af[i][2], af[i][3], a);
            }
            unsigned bh[2][4];
#pragma unroll
            for (int p = 0; p < 2; p++) {
                int row = wn * 32 + p * 16 + lrow;
                uint32_t b = bufb + 16384 + row * 128 + ((((c0 + lch) ^ (row & 7))) << 4);
                ldsm4(bh[p][0], bh[p][1], bh[p][2], bh[p][3], b);
            }
#pragma unroll
            for (int j = 0; j < 4; j++) {
                int p = j >> 1, o = j & 1;
                unsigned b0 = bh[p][o], b1 = bh[p][o + 2];
#pragma unroll
                for (int i = 0; i < 4; i++)
                    mma16816(acc[i][j], af[i][0], af[i][1], af[i][2], af[i][3], b0, b1);
            }
        }
    }

    __half* Chi = px == 0 ? qf : (px == 1 ? kf : vf);
#pragma unroll
    for (int i = 0; i < 4; i++) {
#pragma unroll
        for (int j = 0; j < 4; j++) {
            int row = m0 + wm * 64 + i * 16 + g;
            int col = n0 + wn * 32 + j * 8 + 2 * q;
            *(unsigned*)&Chi[(size_t)row * N + col]       = pack_f16(acc[i][j][0], acc[i][j][1]);
            *(unsigned*)&Chi[(size_t)(row + 8) * N + col] = pack_f16(acc[i][j][2], acc[i][j][3]);
        }
    }
}

// FC GEMM: same K-chunk-64 core
__global__ __launch_bounds__(256, 2) void fc_gemm(
    const __half* __restrict__ Af, const __half* __restrict__ Bhi,
    __half* __restrict__ Chi)
{
    extern __shared__ __half gsm[];
    const int tid = threadIdx.x;
    const int lane = tid & 31, wid = tid >> 5;
    const int wm = wid & 1, wn = wid >> 1;
    const int g = lane >> 2, q = lane & 3;
    const int lrow = (lane & 7) + ((lane >> 3) & 1) * 8;
    const int lch  = lane >> 4;
    const int n0 = blockIdx.x * 128, m0 = blockIdx.y * 128;
    const int K = DD, N = DD;
    uint32_t sb = (uint32_t)__cvta_generic_to_shared(gsm);

    auto issue = [&](int grp) {
        int k0 = grp << 6;
        uint32_t stg = sb + (grp % 3) * GSTG;
#pragma unroll
        for (int j = 0; j < 8; j++) {
            int idx = tid + (j & 3) * 256;
            int sub = j >> 2;
            int row = idx >> 3, ch = idx & 7;
            const __half* gp = (sub == 0 ? Af + (size_t)(m0 + row) * K
                                         : Bhi + (size_t)(n0 + row) * K) + k0 + ch * 8;
            cpa16(stg + sub * 16384 + row * 128 + (((ch ^ (row & 7))) << 4), gp);
        }
        asm volatile("cp.async.commit_group;");
    };

    float acc[4][4][4] = {};
    const int nIter = K >> 6;
    issue(0); issue(1);

    for (int it = 0; it < nIter; it++) {
        if (it < nIter - 1) asm volatile("cp.async.wait_group 1;");
        else                asm volatile("cp.async.wait_group 0;");
        __syncthreads();
        if (it + 2 < nIter) issue(it + 2);
        uint32_t bufb = sb + (it % 3) * GSTG;
#pragma unroll
        for (int kb = 0; kb < 64; kb += 16) {
            int c0 = kb >> 3;
            unsigned af[4][4];
#pragma unroll
            for (int i = 0; i < 4; i++) {
                int row = wm * 64 + i * 16 + lrow;
                uint32_t a = bufb + row * 128 + ((((c0 + lch) ^ (row & 7))) << 4);
                ldsm4(af[i][0], af[i][1], af[i][2], af[i][3], a);
            }
            unsigned bh[2][4];
#pragma unroll
            for (int p = 0; p < 2; p++) {
                int row = wn * 32 + p * 16 + lrow;
                uint32_t b = bufb + 16384 + row * 128 + ((((c0 + lch) ^ (row & 7))) << 4);
                ldsm4(bh[p][0], bh[p][1], bh[p][2], bh[p][3], b);
            }
#pragma unroll
            for (int j = 0; j < 4; j++) {
                int p = j >> 1, o = j & 1;
                unsigned b0 = bh[p][o], b1 = bh[p][o + 2];
#pragma unroll
                for (int i = 0; i < 4; i++)
                    mma16816(acc[i][j], af[i][0], af[i][1], af[i][2], af[i][3], b0, b1);
            }
        }
    }

#pragma unroll
    for (int i = 0; i < 4; i++) {
#pragma unroll
        for (int j = 0; j < 4; j++) {
            int row = m0 + wm * 64 + i * 16 + g;
            int col = n0 + wn * 32 + j * 8 + 2 * q;
            *(unsigned*)&Chi[(size_t)row * N + col]       = pack_f16(acc[i][j][0], acc[i][j][1]);
            *(unsigned*)&Chi[(size_t)(row + 8) * N + col] = pack_f16(acc[i][j][2], acc[i][j][3]);
        }
    }
}

// ---------------- attention (unchanged from R13) ----------------
#define AK_OFF  0
#define AV_OFF  16384
#define AQ_OFF  32768
#define AP_OFF  32768
#define AM_OFF  65536
#define ASTM_OFF 81920
#define ASTS_OFF 83968
#define ATTN_SMEM 86016

__global__ __launch_bounds__(256, 2) void attn_mma(
    const __half* __restrict__ qf,
    const __half* __restrict__ kf, const __half* __restrict__ vf,
    const void* __restrict__ mask, float* __restrict__ attn_out,
    __half* __restrict__ resf)
{
    extern __shared__ char smc[];
    uint32_t sb = (uint32_t)__cvta_generic_to_shared(smc);
    float* stM = (float*)(smc + ASTM_OFF);
    float* stS = (float*)(smc + ASTS_OFF);

    const int tid = threadIdx.x;
    const int lane = tid & 31, wid = tid >> 5;
    const int g = lane >> 2, q = lane & 3;
    const int lrow = (lane & 7) + ((lane >> 3) & 1) * 8;
    const int lch  = lane >> 4;
    const int h  = blockIdx.x & 7;
    const int bn = blockIdx.x >> 3;
    const int kind = g_flag_not01 ? 2 : (g_flag_float ? 1 : 0);

    const size_t base = (size_t)bn * 128 * DD + (size_t)h * 64;

    {
#pragma unroll
        for (int t = 0; t < 4; t++) {
            int idx = tid + t * 256;
            int row = idx >> 3, ch = idx & 7;
            uint32_t sw = row * 128 + (((ch ^ (row & 7))) << 4);
            size_t go = base + (size_t)row * DD + ch * 8;
            cpa16(sb + AK_OFF + sw, kf + go);
            cpa16(sb + AQ_OFF + sw, qf + go);
        }
        asm volatile("cp.async.commit_group;");
    }
    {
#pragma unroll
        for (int t = 0; t < 4; t++) {
            int idx = tid + t * 256;
            int row = idx >> 3, ch = idx & 7;
            uint32_t sw = row * 128 + (((ch ^ (row & 7))) << 4);
            cpa16(sb + AV_OFF + sw, vf + base + (size_t)row * DD + ch * 8);
        }
        if (kind == 2) {
#pragma unroll
            for (int t = 0; t < 4; t++) {
                int idx = tid + t * 256;
                int row = idx >> 3, ch = idx & 7;
                cpa16(sb + AM_OFF + row * 128 + ch * 16,
                      (const unsigned char*)mask + (size_t)bn * 16384 + (size_t)row * 128 + ch * 16);
            }
        }
        asm volatile("cp.async.commit_group;");
    }
    asm volatile("cp.async.wait_group 1;");
    __syncthreads();

    const int wm = wid & 1, wn = wid >> 1;

    float acc[4][4][4] = {};
#pragma unroll
    for (int kb = 0; kb < 64; kb += 16) {
        int c0 = kb >> 3;
        unsigned ah[4][4];
#pragma unroll
        for (int i = 0; i < 4; i++) {
            int row = wm * 64 + i * 16 + lrow;
            uint32_t a = sb + AQ_OFF + row * 128 + ((((c0 + lch) ^ (row & 7))) << 4);
            ldsm4(ah[i][0], ah[i][1], ah[i][2], ah[i][3], a);
        }
        unsigned bk[2][4];
#pragma unroll
        for (int p = 0; p < 2; p++) {
            int row = wn * 32 + p * 16 + lrow;
            uint32_t b = sb + AK_OFF + row * 128 + ((((c0 + lch) ^ (row & 7))) << 4);
            ldsm4(bk[p][0], bk[p][1], bk[p][2], bk[p][3], b);
        }
#pragma unroll
        for (int j = 0; j < 4; j++) {
            int p = j >> 1, o = j & 1;
            unsigned b0 = bk[p][o], b1 = bk[p][o + 2];
#pragma unroll
            for (int i = 0; i < 4; i++)
                mma16816(acc[i][j], ah[i][0], ah[i][1], ah[i][2], ah[i][3], b0, b1);
        }
    }

    asm volatile("cp.async.wait_group 0;");
    __syncthreads();

#pragma unroll
    for (int i = 0; i < 4; i++) {
#pragma unroll
        for (int hf = 0; hf < 2; hf++) {
            int r = wm * 64 + i * 16 + g + hf * 8;
#pragma unroll
            for (int j = 0; j < 4; j++) {
                int c = wn * 32 + j * 8 + 2 * q;
                float m0, m1;
                if (kind == 2) {
                    uchar2 mk = *(const uchar2*)(smc + AM_OFF + r * 128 + c);
                    m0 = mk.x ? 0.f : -1e9f; m1 = mk.y ? 0.f : -1e9f;
                } else if (kind == 1) {
                    float2 mk = *(const float2*)((const float*)mask + (size_t)bn * 16384 + (size_t)r * 128 + c);
                    m0 = (mk.x != 0.f) ? 0.f : -1e9f; m1 = (mk.y != 0.f) ? 0.f : -1e9f;
                } else {
                    int2 mk = *(const int2*)((const int*)mask + (size_t)bn * 16384 + (size_t)r * 128 + c);
                    m0 = mk.x ? 0.f : -1e9f; m1 = mk.y ? 0.f : -1e9f;
                }
                acc[i][j][2 * hf]     = acc[i][j][2 * hf]     * 0.125f + m0;
                acc[i][j][2 * hf + 1] = acc[i][j][2 * hf + 1] * 0.125f + m1;
            }
        }
    }

#pragma unroll
    for (int i = 0; i < 4; i++)
#pragma unroll
        for (int hf = 0; hf < 2; hf++) {
            float m = -3.4e38f;
#pragma unroll
            for (int j = 0; j < 4; j++)
                m = fmaxf(m, fmaxf(acc[i][j][2 * hf], acc[i][j][2 * hf + 1]));
            m = fmaxf(m, __shfl_xor_sync(0xffffffffu, m, 1));
            m = fmaxf(m, __shfl_xor_sync(0xffffffffu, m, 2));
            if (q == 0) stM[(wm * 64 + i * 16 + g + hf * 8) * 4 + wn] = m;
        }
    __syncthreads();

    float inv[4][2];
#pragma unroll
    for (int i = 0; i < 4; i++)
#pragma unroll
        for (int hf = 0; hf < 2; hf++) {
            int r = wm * 64 + i * 16 + g + hf * 8;
            float gm = fmaxf(fmaxf(stM[r * 4], stM[r * 4 + 1]), fmaxf(stM[r * 4 + 2], stM[r * 4 + 3]));
            float s = 0.f;
#pragma unroll
            for (int j = 0; j < 4; j++) {
                float e0 = __expf(acc[i][j][2 * hf]     - gm);
                float e1 = __expf(acc[i][j][2 * hf + 1] - gm);
                acc[i][j][2 * hf] = e0; acc[i][j][2 * hf + 1] = e1;
                s += e0 + e1;
            }
            s += __shfl_xor_sync(0xffffffffu, s, 1);
            s += __shfl_xor_sync(0xffffffffu, s, 2);
            if (q == 0) stS[r * 4 + wn] = s;
        }
    __syncthreads();

#pragma unroll
    for (int i = 0; i < 4; i++)
#pragma unroll
        for (int hf = 0; hf < 2; hf++) {
            int r = wm * 64 + i * 16 + g + hf * 8;
            inv[i][hf] = 1.0f / (stS[r * 4] + stS[r * 4 + 1] + stS[r * 4 + 2] + stS[r * 4 + 3]);
        }

    {
        float* aout = attn_out + ((size_t)(bn * 8 + h)) * 16384;
#pragma unroll
        for (int i = 0; i < 4; i++)
#pragma unroll
            for (int hf = 0; hf < 2; hf++) {
                int r = wm * 64 + i * 16 + g + hf * 8;
                float iv = inv[i][hf];
#pragma unroll
                for (int j = 0; j < 4; j++) {
                    int c = wn * 32 + j * 8 + 2 * q;
                    float p0 = acc[i][j][2 * hf] * iv;
                    float p1 = acc[i][j][2 * hf + 1] * iv;
                    stcs2(&aout[(size_t)r * 128 + c], p0, p1);
                    uint32_t off = r * 256 + ((((c >> 3) ^ (r & 7))) << 4) + (c & 7) * 2;
                    *(unsigned*)(smc + AP_OFF + off) = pack_f16(p0, p1);
                }
            }
    }
    __syncthreads();

    float ao[4][2][4] = {};
#pragma unroll
    for (int kb = 0; kb < 8; kb++) {
        int c0 = kb * 2;
        unsigned ph[4][4];
#pragma unroll
        for (int i = 0; i < 4; i++) {
            int row = wm * 64 + i * 16 + lrow;
            uint32_t a = sb + AP_OFF + row * 256 + ((((c0 + lch) ^ (row & 7))) << 4);
            ldsm4(ph[i][0], ph[i][1], ph[i][2], ph[i][3], a);
        }
        int vrow = kb * 16 + lrow;
        uint32_t vb = sb + AV_OFF + vrow * 128 + ((((wn * 2 + lch) ^ (vrow & 7))) << 4);
        unsigned vv[4];
        ldsm4t(vv[0], vv[1], vv[2], vv[3], vb);
#pragma unroll
        for (int j = 0; j < 2; j++) {
            unsigned b0 = vv[2 * j], b1 = vv[2 * j + 1];
#pragma unroll
            for (int i = 0; i < 4; i++)
                mma16816(ao[i][j], ph[i][0], ph[i][1], ph[i][2], ph[i][3], b0, b1);
        }
    }

#pragma unroll
    for (int i = 0; i < 4; i++)
#pragma unroll
        for (int j = 0; j < 2; j++) {
            int row = wm * 64 + i * 16 + g;
            int col = h * 64 + wn * 16 + j * 8 + 2 * q;
            size_t o0 = ((size_t)(bn * 128 + row)) * DD + col;
            size_t o1 = o0 + 8ull * DD;
            *(unsigned*)&resf[o0] = pack_f16(ao[i][j][0], ao[i][j][1]);
            *(unsigned*)&resf[o1] = pack_f16(ao[i][j][2], ao[i][j][3]);
        }
}

// ---------------- residual + LayerNorm: warp per row ----------------
__global__ __launch_bounds__(256) void ln_kernel(
    const __half* __restrict__ O, const float* __restrict__ X,
    const float* __restrict__ gamma, const float* __restrict__ beta,
    float* __restrict__ Y)
{
    const int lane = threadIdx.x & 31, w = threadIdx.x >> 5;
    const size_t row = (size_t)blockIdx.x * 8 + w;
    const size_t base = row * DD;

    float x[16];
    float s = 0.f, s2 = 0.f;
#pragma unroll
    for (int c = 0; c < 4; c++) {
        int col = c * 128 + lane * 4;
        uint2 o2 = *(const uint2*)&O[base + col];
        float4 xf = *(const float4*)&X[base + col];
        float v0 = f16lo(o2.x) + xf.x;
        float v1 = f16hi(o2.x) + xf.y;
        float v2 = f16lo(o2.y) + xf.z;
        float v3 = f16hi(o2.y) + xf.w;
        x[c * 4 + 0] = v0; x[c * 4 + 1] = v1; x[c * 4 + 2] = v2; x[c * 4 + 3] = v3;
        s  += v0 + v1 + v2 + v3;
        s2 += v0 * v0 + v1 * v1 + v2 * v2 + v3 * v3;
    }
#pragma unroll
    for (int o = 16; o; o >>= 1) {
        s  += __shfl_xor_sync(0xffffffffu, s,  o);
        s2 += __shfl_xor_sync(0xffffffffu, s2, o);
    }
    float mean = s * (1.0f / DD);
    float var  = s2 * (1.0f / DD) - mean * mean;
    float inv  = rsqrtf(var + 1e-5f);

#pragma unroll
    for (int c = 0; c < 4; c++) {
        int col = c * 128 + lane * 4;
        float4 gm = *(const float4*)&gamma[col];
        float4 bt = *(const float4*)&beta[col];
        float4 yv;
        yv.x = (x[c * 4 + 0] - mean) * inv * gm.x + bt.x;
        yv.y = (x[c * 4 + 1] - mean) * inv * gm.y + bt.y;
        yv.z = (x[c * 4 + 2] - mean) * inv * gm.z + bt.z;
        yv.w = (x[c * 4 + 3] - mean) * inv * gm.w + bt.w;
        *(float4*)&Y[base + col] = yv;
    }
}

// ---------------- launch ----------------
extern "C" void kernel_launch(void* const* d_in, const int* in_sizes, int n_in,
                              void* d_out, int out_size)
{
    const float* Q     = (const float*)d_in[0];
    const float* K     = (const float*)d_in[1];
    const float* V     = (const float*)d_in[2];
    const void*  mask  = d_in[3];
    const float* WQ    = (const float*)d_in[4];
    const float* WK    = (const float*)d_in[5];
    const float* WV    = (const float*)d_in[6];
    const float* Wfc   = (const float*)d_in[7];
    const float* gamma = (const float*)d_in[8];
    const float* beta  = (const float*)d_in[9];

    float* y    = (float*)d_out;
    float* attn = y + (size_t)YSIZE;

    void *p;
    cudaGetSymbolAddress(&p, g_inf);  __half* inf  = (__half*)p;
    cudaGetSymbolAddress(&p, g_whi);  __half* whi  = (__half*)p;
    cudaGetSymbolAddress(&p, g_qf);   __half* qfp  = (__half*)p;
    cudaGetSymbolAddress(&p, g_kf);   __half* kfp  = (__half*)p;
    cudaGetSymbolAddress(&p, g_vf);   __half* vfp  = (__half*)p;
    cudaGetSymbolAddress(&p, g_resf); __half* resf = (__half*)p;
    cudaGetSymbolAddress(&p, g_outp); __half* outp = (__half*)p;

    cudaFuncSetAttribute(qkv_gemm, cudaFuncAttributeMaxDynamicSharedMemorySize, GEMM_SMEM);
    cudaFuncSetAttribute(fc_gemm,  cudaFuncAttributeMaxDynamicSharedMemorySize, GEMM_SMEM);
    cudaFuncSetAttribute(attn_mma, cudaFuncAttributeMaxDynamicSharedMemorySize, ATTN_SMEM);

    detect_reset<<<1, 1>>>();
    detect_scan<<<64, 256>>>((const uint4*)mask);

    const int n4 = (int)(NE_C / 4);
    conv3_kernel<<<3 * (n4 / 256), 256>>>(Q, K, V, inf, n4);
    const int w4 = (int)(WE_C / 4);
    wconv_kernel<<<4 * (w4 / 256), 256>>>(WQ, WK, WV, Wfc, whi, w4);

    qkv_gemm<<<dim3(12, NTOK / 128), 256, GEMM_SMEM>>>(inf, whi, qfp, kfp, vfp);

    attn_mma<<<BB * NNN * HH, 256, ATTN_SMEM>>>(qfp, kfp, vfp, mask, attn, resf);

    fc_gemm<<<dim3(4, NTOK / 128), 256, GEMM_SMEM>>>(resf, whi + 3 * WE_C, outp);

    ln_kernel<<<NTOK / 8, 256>>>(outp, Q, gamma, beta, y);
}

// round 15
// speedup vs baseline: 1.5623x; 1.0133x over previous
#include <cuda_runtime.h>
#include <cuda_fp16.h>
#include <cstdint>

#define BB   16
#define NNN  32
#define SS   128
#define DD   512
#define HH   8
#define NTOK (BB*NNN*SS)          // 65536
#define YSIZE  (NTOK*DD)          // 33554432

// ---------------- scratch ----------------
__device__ __half g_inf[3ull*NTOK*DD];    // inputs Q,K,V single f16
__device__ __half g_whi[4ull*DD*DD];      // weights single f16
__device__ __half g_qf[(size_t)NTOK*DD];
__device__ __half g_kf[(size_t)NTOK*DD];
__device__ __half g_vf[(size_t)NTOK*DD];
__device__ __half g_resf[(size_t)NTOK*DD];
__device__ __half g_outp[(size_t)NTOK*DD];
__device__ int    g_flag_float, g_flag_not01;

// ---------------- mask dtype detection ----------------
__global__ void detect_reset() { g_flag_float = 0; g_flag_not01 = 0; }
__global__ __launch_bounds__(256) void detect_scan(const uint4* __restrict__ mw) {
    int i = blockIdx.x * 256 + threadIdx.x;
    uint4 w = mw[i];
    int isf = (w.x == 0x3f800000u) | (w.y == 0x3f800000u) | (w.z == 0x3f800000u) | (w.w == 0x3f800000u);
    int n01 = ((w.x > 1u) & (w.x != 0x3f800000u)) | ((w.y > 1u) & (w.y != 0x3f800000u))
            | ((w.z > 1u) & (w.z != 0x3f800000u)) | ((w.w > 1u) & (w.w != 0x3f800000u));
    int bf = __syncthreads_or(isf);
    int bn = __syncthreads_or(n01);
    if (threadIdx.x == 0) {
        if (bf) atomicOr(&g_flag_float, 1);
        if (bn) atomicOr(&g_flag_not01, 1);
    }
}

// ---------------- helpers ----------------
__device__ __forceinline__ unsigned pack_f16(float lo, float hi) {
    __half2 h = __floats2half2_rn(lo, hi);
    return *(unsigned*)&h;
}
__device__ __forceinline__ float f16lo(unsigned u) { return __low2float(*(__half2*)&u); }
__device__ __forceinline__ float f16hi(unsigned u) { return __high2float(*(__half2*)&u); }

__device__ __forceinline__ void mma16816(float c[4],
    unsigned a0, unsigned a1, unsigned a2, unsigned a3, unsigned b0, unsigned b1)
{
    asm volatile(
        "mma.sync.aligned.m16n8k16.row.col.f32.f16.f16.f32 "
        "{%0,%1,%2,%3}, {%4,%5,%6,%7}, {%8,%9}, {%0,%1,%2,%3};"
        : "+f"(c[0]), "+f"(c[1]), "+f"(c[2]), "+f"(c[3])
        : "r"(a0), "r"(a1), "r"(a2), "r"(a3), "r"(b0), "r"(b1));
}
__device__ __forceinline__ void cpa16(uint32_t s, const void* g) {
    asm volatile("cp.async.cg.shared.global [%0], [%1], 16;" :: "r"(s), "l"(g));
}
__device__ __forceinline__ void ldsm4(unsigned& r0, unsigned& r1, unsigned& r2, unsigned& r3, uint32_t a) {
    asm volatile("ldmatrix.sync.aligned.m8n8.x4.shared.b16 {%0,%1,%2,%3}, [%4];"
        : "=r"(r0), "=r"(r1), "=r"(r2), "=r"(r3) : "r"(a));
}
__device__ __forceinline__ void ldsm4t(unsigned& r0, unsigned& r1, unsigned& r2, unsigned& r3, uint32_t a) {
    asm volatile("ldmatrix.sync.aligned.m8n8.x4.trans.shared.b16 {%0,%1,%2,%3}, [%4];"
        : "=r"(r0), "=r"(r1), "=r"(r2), "=r"(r3) : "r"(a));
}
__device__ __forceinline__ void stcs2(float* p, float a, float b) {
    asm volatile("st.global.cs.v2.f32 [%0], {%1,%2};" :: "l"(p), "f"(a), "f"(b) : "memory");
}

// ---------------- fp32 -> f16 single (3 inputs merged) ----------------
__global__ __launch_bounds__(256) void conv3_kernel(
    const float* __restrict__ s0, const float* __restrict__ s1, const float* __restrict__ s2,
    __half* __restrict__ dst, int n4)
{
    int b = blockIdx.x;
    int sel = b / (n4 / 256);
    int i = (b % (n4 / 256)) * 256 + threadIdx.x;
    const float* src = sel == 0 ? s0 : (sel == 1 ? s1 : s2);
    float4 v = ((const float4*)src)[i];
    ((uint2*)dst)[(size_t)sel * n4 + i] = make_uint2(pack_f16(v.x, v.y), pack_f16(v.z, v.w));
}

// ---------------- weights: 4 -> f16 single ----------------
__global__ __launch_bounds__(256) void wconv_kernel(
    const float* __restrict__ s0, const float* __restrict__ s1,
    const float* __restrict__ s2, const float* __restrict__ s3,
    __half* __restrict__ hi, int n4)
{
    int b = blockIdx.x;
    int sel = b / (n4 / 256);
    int i = (b % (n4 / 256)) * 256 + threadIdx.x;
    const float* src = sel == 0 ? s0 : (sel == 1 ? s1 : (sel == 2 ? s2 : s3));
    float4 v = ((const float4*)src)[i];
    ((uint2*)hi)[(size_t)sel * n4 + i] = make_uint2(pack_f16(v.x, v.y), pack_f16(v.z, v.w));
}

// ---------------- GEMM core: K-chunk 64 per stage, 3 stages, A-frag pipelined ----------------
#define GSTG 32768
#define GEMM_SMEM (3*GSTG)
#define NE_C ((size_t)NTOK * DD)
#define WE_C ((size_t)DD * DD)

__global__ __launch_bounds__(256, 2) void qkv_gemm(
    const __half* __restrict__ inf, const __half* __restrict__ whi,
    __half* __restrict__ qf, __half* __restrict__ kf, __half* __restrict__ vf)
{
    extern __shared__ __half gsm[];
    const int tid = threadIdx.x;
    const int lane = tid & 31, wid = tid >> 5;
    const int wm = wid & 1, wn = wid >> 1;
    const int g = lane >> 2, q = lane & 3;
    const int lrow = (lane & 7) + ((lane >> 3) & 1) * 8;
    const int lch  = lane >> 4;
    const int px = blockIdx.x >> 2;
    const int n0 = (blockIdx.x & 3) * 128, m0 = blockIdx.y * 128;
    const int K = DD, N = DD;
    uint32_t sb = (uint32_t)__cvta_generic_to_shared(gsm);

    const __half* Af  = inf + (size_t)px * NE_C;
    const __half* Bhi = whi + (size_t)px * WE_C;

    auto issue = [&](int grp) {
        int k0 = grp << 6;
        uint32_t stg = sb + (grp % 3) * GSTG;
#pragma unroll
        for (int j = 0; j < 8; j++) {
            int idx = tid + (j & 3) * 256;
            int sub = j >> 2;
            int row = idx >> 3, ch = idx & 7;
            const __half* gp = (sub == 0 ? Af + (size_t)(m0 + row) * K
                                         : Bhi + (size_t)(n0 + row) * K) + k0 + ch * 8;
            cpa16(stg + sub * 16384 + row * 128 + (((ch ^ (row & 7))) << 4), gp);
        }
        asm volatile("cp.async.commit_group;");
    };

    float acc[4][4][4] = {};
    const int nIter = K >> 6;   // 8
    issue(0); issue(1);

    for (int it = 0; it < nIter; it++) {
        if (it < nIter - 1) asm volatile("cp.async.wait_group 1;");
        else                asm volatile("cp.async.wait_group 0;");
        __syncthreads();
        if (it + 2 < nIter) issue(it + 2);
        uint32_t bufb = sb + (it % 3) * GSTG;

        unsigned af[2][4][4];
        // prime A fragments for kb=0
#pragma unroll
        for (int i = 0; i < 4; i++) {
            int row = wm * 64 + i * 16 + lrow;
            uint32_t a = bufb + row * 128 + ((((0 + lch) ^ (row & 7))) << 4);
            ldsm4(af[0][i][0], af[0][i][1], af[0][i][2], af[0][i][3], a);
        }
#pragma unroll
        for (int kbi = 0; kbi < 4; kbi++) {
            int cur = kbi & 1, nxt = cur ^ 1;
            if (kbi < 3) {
                int c0n = (kbi + 1) * 2;
#pragma unroll
                for (int i = 0; i < 4; i++) {
                    int row = wm * 64 + i * 16 + lrow;
                    uint32_t a = bufb + row * 128 + ((((c0n + lch) ^ (row & 7))) << 4);
                    ldsm4(af[nxt][i][0], af[nxt][i][1], af[nxt][i][2], af[nxt][i][3], a);
                }
            }
            int c0 = kbi * 2;
            unsigned bh[2][4];
#pragma unroll
            for (int p = 0; p < 2; p++) {
                int row = wn * 32 + p * 16 + lrow;
                uint32_t b = bufb + 16384 + row * 128 + ((((c0 + lch) ^ (row & 7))) << 4);
                ldsm4(bh[p][0], bh[p][1], bh[p][2], bh[p][3], b);
            }
#pragma unroll
            for (int j = 0; j < 4; j++) {
                int p = j >> 1, o = j & 1;
                unsigned b0 = bh[p][o], b1 = bh[p][o + 2];
#pragma unroll
                for (int i = 0; i < 4; i++)
                    mma16816(acc[i][j], af[cur][i][0], af[cur][i][1], af[cur][i][2], af[cur][i][3], b0, b1);
            }
        }
    }

    __half* Chi = px == 0 ? qf : (px == 1 ? kf : vf);
#pragma unroll
    for (int i = 0; i < 4; i++) {
#pragma unroll
        for (int j = 0; j < 4; j++) {
            int row = m0 + wm * 64 + i * 16 + g;
            int col = n0 + wn * 32 + j * 8 + 2 * q;
            *(unsigned*)&Chi[(size_t)row * N + col]       = pack_f16(acc[i][j][0], acc[i][j][1]);
            *(unsigned*)&Chi[(size_t)(row + 8) * N + col] = pack_f16(acc[i][j][2], acc[i][j][3]);
        }
    }
}

// FC GEMM: same core
__global__ __launch_bounds__(256, 2) void fc_gemm(
    const __half* __restrict__ Af, const __half* __restrict__ Bhi,
    __half* __restrict__ Chi)
{
    extern __shared__ __half gsm[];
    const int tid = threadIdx.x;
    const int lane = tid & 31, wid = tid >> 5;
    const int wm = wid & 1, wn = wid >> 1;
    const int g = lane >> 2, q = lane & 3;
    const int lrow = (lane & 7) + ((lane >> 3) & 1) * 8;
    const int lch  = lane >> 4;
    const int n0 = blockIdx.x * 128, m0 = blockIdx.y * 128;
    const int K = DD, N = DD;
    uint32_t sb = (uint32_t)__cvta_generic_to_shared(gsm);

    auto issue = [&](int grp) {
        int k0 = grp << 6;
        uint32_t stg = sb + (grp % 3) * GSTG;
#pragma unroll
        for (int j = 0; j < 8; j++) {
            int idx = tid + (j & 3) * 256;
            int sub = j >> 2;
            int row = idx >> 3, ch = idx & 7;
            const __half* gp = (sub == 0 ? Af + (size_t)(m0 + row) * K
                                         : Bhi + (size_t)(n0 + row) * K) + k0 + ch * 8;
            cpa16(stg + sub * 16384 + row * 128 + (((ch ^ (row & 7))) << 4), gp);
        }
        asm volatile("cp.async.commit_group;");
    };

    float acc[4][4][4] = {};
    const int nIter = K >> 6;
    issue(0); issue(1);

    for (int it = 0; it < nIter; it++) {
        if (it < nIter - 1) asm volatile("cp.async.wait_group 1;");
        else                asm volatile("cp.async.wait_group 0;");
        __syncthreads();
        if (it + 2 < nIter) issue(it + 2);
        uint32_t bufb = sb + (it % 3) * GSTG;

        unsigned af[2][4][4];
#pragma unroll
        for (int i = 0; i < 4; i++) {
            int row = wm * 64 + i * 16 + lrow;
            uint32_t a = bufb + row * 128 + ((((0 + lch) ^ (row & 7))) << 4);
            ldsm4(af[0][i][0], af[0][i][1], af[0][i][2], af[0][i][3], a);
        }
#pragma unroll
        for (int kbi = 0; kbi < 4; kbi++) {
            int cur = kbi & 1, nxt = cur ^ 1;
            if (kbi < 3) {
                int c0n = (kbi + 1) * 2;
#pragma unroll
                for (int i = 0; i < 4; i++) {
                    int row = wm * 64 + i * 16 + lrow;
                    uint32_t a = bufb + row * 128 + ((((c0n + lch) ^ (row & 7))) << 4);
                    ldsm4(af[nxt][i][0], af[nxt][i][1], af[nxt][i][2], af[nxt][i][3], a);
                }
            }
            int c0 = kbi * 2;
            unsigned bh[2][4];
#pragma unroll
            for (int p = 0; p < 2; p++) {
                int row = wn * 32 + p * 16 + lrow;
                uint32_t b = bufb + 16384 + row * 128 + ((((c0 + lch) ^ (row & 7))) << 4);
                ldsm4(bh[p][0], bh[p][1], bh[p][2], bh[p][3], b);
            }
#pragma unroll
            for (int j = 0; j < 4; j++) {
                int p = j >> 1, o = j & 1;
                unsigned b0 = bh[p][o], b1 = bh[p][o + 2];
#pragma unroll
                for (int i = 0; i < 4; i++)
                    mma16816(acc[i][j], af[cur][i][0], af[cur][i][1], af[cur][i][2], af[cur][i][3], b0, b1);
            }
        }
    }

#pragma unroll
    for (int i = 0; i < 4; i++) {
#pragma unroll
        for (int j = 0; j < 4; j++) {
            int row = m0 + wm * 64 + i * 16 + g;
            int col = n0 + wn * 32 + j * 8 + 2 * q;
            *(unsigned*)&Chi[(size_t)row * N + col]       = pack_f16(acc[i][j][0], acc[i][j][1]);
            *(unsigned*)&Chi[(size_t)(row + 8) * N + col] = pack_f16(acc[i][j][2], acc[i][j][3]);
        }
    }
}

// ---------------- attention (unchanged) ----------------
#define AK_OFF  0
#define AV_OFF  16384
#define AQ_OFF  32768
#define AP_OFF  32768
#define AM_OFF  65536
#define ASTM_OFF 81920
#define ASTS_OFF 83968
#define ATTN_SMEM 86016

__global__ __launch_bounds__(256, 2) void attn_mma(
    const __half* __restrict__ qf,
    const __half* __restrict__ kf, const __half* __restrict__ vf,
    const void* __restrict__ mask, float* __restrict__ attn_out,
    __half* __restrict__ resf)
{
    extern __shared__ char smc[];
    uint32_t sb = (uint32_t)__cvta_generic_to_shared(smc);
    float* stM = (float*)(smc + ASTM_OFF);
    float* stS = (float*)(smc + ASTS_OFF);

    const int tid = threadIdx.x;
    const int lane = tid & 31, wid = tid >> 5;
    const int g = lane >> 2, q = lane & 3;
    const int lrow = (lane & 7) + ((lane >> 3) & 1) * 8;
    const int lch  = lane >> 4;
    const int h  = blockIdx.x & 7;
    const int bn = blockIdx.x >> 3;
    const int kind = g_flag_not01 ? 2 : (g_flag_float ? 1 : 0);

    const size_t base = (size_t)bn * 128 * DD + (size_t)h * 64;

    {
#pragma unroll
        for (int t = 0; t < 4; t++) {
            int idx = tid + t * 256;
            int row = idx >> 3, ch = idx & 7;
            uint32_t sw = row * 128 + (((ch ^ (row & 7))) << 4);
            size_t go = base + (size_t)row * DD + ch * 8;
            cpa16(sb + AK_OFF + sw, kf + go);
            cpa16(sb + AQ_OFF + sw, qf + go);
        }
        asm volatile("cp.async.commit_group;");
    }
    {
#pragma unroll
        for (int t = 0; t < 4; t++) {
            int idx = tid + t * 256;
            int row = idx >> 3, ch = idx & 7;
            uint32_t sw = row * 128 + (((ch ^ (row & 7))) << 4);
            cpa16(sb + AV_OFF + sw, vf + base + (size_t)row * DD + ch * 8);
        }
        if (kind == 2) {
#pragma unroll
            for (int t = 0; t < 4; t++) {
                int idx = tid + t * 256;
                int row = idx >> 3, ch = idx & 7;
                cpa16(sb + AM_OFF + row * 128 + ch * 16,
                      (const unsigned char*)mask + (size_t)bn * 16384 + (size_t)row * 128 + ch * 16);
            }
        }
        asm volatile("cp.async.commit_group;");
    }
    asm volatile("cp.async.wait_group 1;");
    __syncthreads();

    const int wm = wid & 1, wn = wid >> 1;

    float acc[4][4][4] = {};
#pragma unroll
    for (int kb = 0; kb < 64; kb += 16) {
        int c0 = kb >> 3;
        unsigned ah[4][4];
#pragma unroll
        for (int i = 0; i < 4; i++) {
            int row = wm * 64 + i * 16 + lrow;
            uint32_t a = sb + AQ_OFF + row * 128 + ((((c0 + lch) ^ (row & 7))) << 4);
            ldsm4(ah[i][0], ah[i][1], ah[i][2], ah[i][3], a);
        }
        unsigned bk[2][4];
#pragma unroll
        for (int p = 0; p < 2; p++) {
            int row = wn * 32 + p * 16 + lrow;
            uint32_t b = sb + AK_OFF + row * 128 + ((((c0 + lch) ^ (row & 7))) << 4);
            ldsm4(bk[p][0], bk[p][1], bk[p][2], bk[p][3], b);
        }
#pragma unroll
        for (int j = 0; j < 4; j++) {
            int p = j >> 1, o = j & 1;
            unsigned b0 = bk[p][o], b1 = bk[p][o + 2];
#pragma unroll
            for (int i = 0; i < 4; i++)
                mma16816(acc[i][j], ah[i][0], ah[i][1], ah[i][2], ah[i][3], b0, b1);
        }
    }

    asm volatile("cp.async.wait_group 0;");
    __syncthreads();

#pragma unroll
    for (int i = 0; i < 4; i++) {
#pragma unroll
        for (int hf = 0; hf < 2; hf++) {
            int r = wm * 64 + i * 16 + g + hf * 8;
#pragma unroll
            for (int j = 0; j < 4; j++) {
                int c = wn * 32 + j * 8 + 2 * q;
                float m0, m1;
                if (kind == 2) {
                    uchar2 mk = *(const uchar2*)(smc + AM_OFF + r * 128 + c);
                    m0 = mk.x ? 0.f : -1e9f; m1 = mk.y ? 0.f : -1e9f;
                } else if (kind == 1) {
                    float2 mk = *(const float2*)((const float*)mask + (size_t)bn * 16384 + (size_t)r * 128 + c);
                    m0 = (mk.x != 0.f) ? 0.f : -1e9f; m1 = (mk.y != 0.f) ? 0.f : -1e9f;
                } else {
                    int2 mk = *(const int2*)((const int*)mask + (size_t)bn * 16384 + (size_t)r * 128 + c);
                    m0 = mk.x ? 0.f : -1e9f; m1 = mk.y ? 0.f : -1e9f;
                }
                acc[i][j][2 * hf]     = acc[i][j][2 * hf]     * 0.125f + m0;
                acc[i][j][2 * hf + 1] = acc[i][j][2 * hf + 1] * 0.125f + m1;
            }
        }
    }

#pragma unroll
    for (int i = 0; i < 4; i++)
#pragma unroll
        for (int hf = 0; hf < 2; hf++) {
            float m = -3.4e38f;
#pragma unroll
            for (int j = 0; j < 4; j++)
                m = fmaxf(m, fmaxf(acc[i][j][2 * hf], acc[i][j][2 * hf + 1]));
            m = fmaxf(m, __shfl_xor_sync(0xffffffffu, m, 1));
            m = fmaxf(m, __shfl_xor_sync(0xffffffffu, m, 2));
            if (q == 0) stM[(wm * 64 + i * 16 + g + hf * 8) * 4 + wn] = m;
        }
    __syncthreads();

    float inv[4][2];
#pragma unroll
    for (int i = 0; i < 4; i++)
#pragma unroll
        for (int hf = 0; hf < 2; hf++) {
            int r = wm * 64 + i * 16 + g + hf * 8;
            float gm = fmaxf(fmaxf(stM[r * 4], stM[r * 4 + 1]), fmaxf(stM[r * 4 + 2], stM[r * 4 + 3]));
            float s = 0.f;
#pragma unroll
            for (int j = 0; j < 4; j++) {
                float e0 = __expf(acc[i][j][2 * hf]     - gm);
                float e1 = __expf(acc[i][j][2 * hf + 1] - gm);
                acc[i][j][2 * hf] = e0; acc[i][j][2 * hf + 1] = e1;
                s += e0 + e1;
            }
            s += __shfl_xor_sync(0xffffffffu, s, 1);
            s += __shfl_xor_sync(0xffffffffu, s, 2);
            if (q == 0) stS[r * 4 + wn] = s;
        }
    __syncthreads();

#pragma unroll
    for (int i = 0; i < 4; i++)
#pragma unroll
        for (int hf = 0; hf < 2; hf++) {
            int r = wm * 64 + i * 16 + g + hf * 8;
            inv[i][hf] = 1.0f / (stS[r * 4] + stS[r * 4 + 1] + stS[r * 4 + 2] + stS[r * 4 + 3]);
        }

    {
        float* aout = attn_out + ((size_t)(bn * 8 + h)) * 16384;
#pragma unroll
        for (int i = 0; i < 4; i++)
#pragma unroll
            for (int hf = 0; hf < 2; hf++) {
                int r = wm * 64 + i * 16 + g + hf * 8;
                float iv = inv[i][hf];
#pragma unroll
                for (int j = 0; j < 4; j++) {
                    int c = wn * 32 + j * 8 + 2 * q;
                    float p0 = acc[i][j][2 * hf] * iv;
                    float p1 = acc[i][j][2 * hf + 1] * iv;
                    stcs2(&aout[(size_t)r * 128 + c], p0, p1);
                    uint32_t off = r * 256 + ((((c >> 3) ^ (r & 7))) << 4) + (c & 7) * 2;
                    *(unsigned*)(smc + AP_OFF + off) = pack_f16(p0, p1);
                }
            }
    }
    __syncthreads();

    float ao[4][2][4] = {};
#pragma unroll
    for (int kb = 0; kb < 8; kb++) {
        int c0 = kb * 2;
        unsigned ph[4][4];
#pragma unroll
        for (int i = 0; i < 4; i++) {
            int row = wm * 64 + i * 16 + lrow;
            uint32_t a = sb + AP_OFF + row * 256 + ((((c0 + lch) ^ (row & 7))) << 4);
            ldsm4(ph[i][0], ph[i][1], ph[i][2], ph[i][3], a);
        }
        int vrow = kb * 16 + lrow;
        uint32_t vb = sb + AV_OFF + vrow * 128 + ((((wn * 2 + lch) ^ (vrow & 7))) << 4);
        unsigned vv[4];
        ldsm4t(vv[0], vv[1], vv[2], vv[3], vb);
#pragma unroll
        for (int j = 0; j < 2; j++) {
            unsigned b0 = vv[2 * j], b1 = vv[2 * j + 1];
#pragma unroll
            for (int i = 0; i < 4; i++)
                mma16816(ao[i][j], ph[i][0], ph[i][1], ph[i][2], ph[i][3], b0, b1);
        }
    }

#pragma unroll
    for (int i = 0; i < 4; i++)
#pragma unroll
        for (int j = 0; j < 2; j++) {
            int row = wm * 64 + i * 16 + g;
            int col = h * 64 + wn * 16 + j * 8 + 2 * q;
            size_t o0 = ((size_t)(bn * 128 + row)) * DD + col;
            size_t o1 = o0 + 8ull * DD;
            *(unsigned*)&resf[o0] = pack_f16(ao[i][j][0], ao[i][j][1]);
            *(unsigned*)&resf[o1] = pack_f16(ao[i][j][2], ao[i][j][3]);
        }
}

// ---------------- residual + LayerNorm: warp per row, f16 residual input ----------------
__global__ __launch_bounds__(256) void ln_kernel(
    const __half* __restrict__ O, const __half* __restrict__ Xh,
    const float* __restrict__ gamma, const float* __restrict__ beta,
    float* __restrict__ Y)
{
    const int lane = threadIdx.x & 31, w = threadIdx.x >> 5;
    const size_t row = (size_t)blockIdx.x * 8 + w;
    const size_t base = row * DD;

    float x[16];
    float s = 0.f, s2 = 0.f;
#pragma unroll
    for (int c = 0; c < 4; c++) {
        int col = c * 128 + lane * 4;
        uint2 o2 = *(const uint2*)&O[base + col];
        uint2 x2 = *(const uint2*)&Xh[base + col];
        float v0 = f16lo(o2.x) + f16lo(x2.x);
        float v1 = f16hi(o2.x) + f16hi(x2.x);
        float v2 = f16lo(o2.y) + f16lo(x2.y);
        float v3 = f16hi(o2.y) + f16hi(x2.y);
        x[c * 4 + 0] = v0; x[c * 4 + 1] = v1; x[c * 4 + 2] = v2; x[c * 4 + 3] = v3;
        s  += v0 + v1 + v2 + v3;
        s2 += v0 * v0 + v1 * v1 + v2 * v2 + v3 * v3;
    }
#pragma unroll
    for (int o = 16; o; o >>= 1) {
        s  += __shfl_xor_sync(0xffffffffu, s,  o);
        s2 += __shfl_xor_sync(0xffffffffu, s2, o);
    }
    float mean = s * (1.0f / DD);
    float var  = s2 * (1.0f / DD) - mean * mean;
    float inv  = rsqrtf(var + 1e-5f);

#pragma unroll
    for (int c = 0; c < 4; c++) {
        int col = c * 128 + lane * 4;
        float4 gm = *(const float4*)&gamma[col];
        float4 bt = *(const float4*)&beta[col];
        float4 yv;
        yv.x = (x[c * 4 + 0] - mean) * inv * gm.x + bt.x;
        yv.y = (x[c * 4 + 1] - mean) * inv * gm.y + bt.y;
        yv.z = (x[c * 4 + 2] - mean) * inv * gm.z + bt.z;
        yv.w = (x[c * 4 + 3] - mean) * inv * gm.w + bt.w;
        *(float4*)&Y[base + col] = yv;
    }
}

// ---------------- launch ----------------
extern "C" void kernel_launch(void* const* d_in, const int* in_sizes, int n_in,
                              void* d_out, int out_size)
{
    const float* Q     = (const float*)d_in[0];
    const float* K     = (const float*)d_in[1];
    const float* V     = (const float*)d_in[2];
    const void*  mask  = d_in[3];
    const float* WQ    = (const float*)d_in[4];
    const float* WK    = (const float*)d_in[5];
    const float* WV    = (const float*)d_in[6];
    const float* Wfc   = (const float*)d_in[7];
    const float* gamma = (const float*)d_in[8];
    const float* beta  = (const float*)d_in[9];

    float* y    = (float*)d_out;
    float* attn = y + (size_t)YSIZE;

    void *p;
    cudaGetSymbolAddress(&p, g_inf);  __half* inf  = (__half*)p;
    cudaGetSymbolAddress(&p, g_whi);  __half* whi  = (__half*)p;
    cudaGetSymbolAddress(&p, g_qf);   __half* qfp  = (__half*)p;
    cudaGetSymbolAddress(&p, g_kf);   __half* kfp  = (__half*)p;
    cudaGetSymbolAddress(&p, g_vf);   __half* vfp  = (__half*)p;
    cudaGetSymbolAddress(&p, g_resf); __half* resf = (__half*)p;
    cudaGetSymbolAddress(&p, g_outp); __half* outp = (__half*)p;

    cudaFuncSetAttribute(qkv_gemm, cudaFuncAttributeMaxDynamicSharedMemorySize, GEMM_SMEM);
    cudaFuncSetAttribute(fc_gemm,  cudaFuncAttributeMaxDynamicSharedMemorySize, GEMM_SMEM);
    cudaFuncSetAttribute(attn_mma, cudaFuncAttributeMaxDynamicSharedMemorySize, ATTN_SMEM);

    detect_reset<<<1, 1>>>();
    detect_scan<<<64, 256>>>((const uint4*)mask);

    const int n4 = (int)(NE_C / 4);
    conv3_kernel<<<3 * (n4 / 256), 256>>>(Q, K, V, inf, n4);
    const int w4 = (int)(WE_C / 4);
    wconv_kernel<<<4 * (w4 / 256), 256>>>(WQ, WK, WV, Wfc, whi, w4);

    qkv_gemm<<<dim3(12, NTOK / 128), 256, GEMM_SMEM>>>(inf, whi, qfp, kfp, vfp);

    attn_mma<<<BB * NNN * HH, 256, ATTN_SMEM>>>(qfp, kfp, vfp, mask, attn, resf);

    fc_gemm<<<dim3(4, NTOK / 128), 256, GEMM_SMEM>>>(resf, whi + 3 * WE_C, outp);

    ln_kernel<<<NTOK / 8, 256>>>(outp, inf, gamma, beta, y);
}

// round 16
// speedup vs baseline: 1.5668x; 1.0028x over previous
#include <cuda_runtime.h>
#include <cuda_fp16.h>
#include <cstdint>

#define BB   16
#define NNN  32
#define SS   128
#define DD   512
#define HH   8
#define NTOK (BB*NNN*SS)          // 65536
#define YSIZE  (NTOK*DD)          // 33554432

// ---------------- scratch ----------------
__device__ __half g_inf[3ull*NTOK*DD];    // inputs Q,K,V single f16
__device__ __half g_whi[4ull*DD*DD];      // weights single f16
__device__ __half g_qf[(size_t)NTOK*DD];
__device__ __half g_kf[(size_t)NTOK*DD];
__device__ __half g_vf[(size_t)NTOK*DD];
__device__ __half g_resf[(size_t)NTOK*DD];
__device__ __half g_outp[(size_t)NTOK*DD];
__device__ int    g_flag_float, g_flag_not01;

// ---------------- mask dtype detection ----------------
__global__ void detect_reset() { g_flag_float = 0; g_flag_not01 = 0; }
__global__ __launch_bounds__(256) void detect_scan(const uint4* __restrict__ mw) {
    int i = blockIdx.x * 256 + threadIdx.x;
    uint4 w = __ldcs(&mw[i]);
    int isf = (w.x == 0x3f800000u) | (w.y == 0x3f800000u) | (w.z == 0x3f800000u) | (w.w == 0x3f800000u);
    int n01 = ((w.x > 1u) & (w.x != 0x3f800000u)) | ((w.y > 1u) & (w.y != 0x3f800000u))
            | ((w.z > 1u) & (w.z != 0x3f800000u)) | ((w.w > 1u) & (w.w != 0x3f800000u));
    int bf = __syncthreads_or(isf);
    int bn = __syncthreads_or(n01);
    if (threadIdx.x == 0) {
        if (bf) atomicOr(&g_flag_float, 1);
        if (bn) atomicOr(&g_flag_not01, 1);
    }
}

// ---------------- helpers ----------------
__device__ __forceinline__ unsigned pack_f16(float lo, float hi) {
    __half2 h = __floats2half2_rn(lo, hi);
    return *(unsigned*)&h;
}
__device__ __forceinline__ float f16lo(unsigned u) { return __low2float(*(__half2*)&u); }
__device__ __forceinline__ float f16hi(unsigned u) { return __high2float(*(__half2*)&u); }

__device__ __forceinline__ void mma16816(float c[4],
    unsigned a0, unsigned a1, unsigned a2, unsigned a3, unsigned b0, unsigned b1)
{
    asm volatile(
        "mma.sync.aligned.m16n8k16.row.col.f32.f16.f16.f32 "
        "{%0,%1,%2,%3}, {%4,%5,%6,%7}, {%8,%9}, {%0,%1,%2,%3};"
        : "+f"(c[0]), "+f"(c[1]), "+f"(c[2]), "+f"(c[3])
        : "r"(a0), "r"(a1), "r"(a2), "r"(a3), "r"(b0), "r"(b1));
}
__device__ __forceinline__ void cpa16(uint32_t s, const void* g) {
    asm volatile("cp.async.cg.shared.global [%0], [%1], 16;" :: "r"(s), "l"(g));
}
__device__ __forceinline__ void ldsm4(unsigned& r0, unsigned& r1, unsigned& r2, unsigned& r3, uint32_t a) {
    asm volatile("ldmatrix.sync.aligned.m8n8.x4.shared.b16 {%0,%1,%2,%3}, [%4];"
        : "=r"(r0), "=r"(r1), "=r"(r2), "=r"(r3) : "r"(a));
}
__device__ __forceinline__ void ldsm4t(unsigned& r0, unsigned& r1, unsigned& r2, unsigned& r3, uint32_t a) {
    asm volatile("ldmatrix.sync.aligned.m8n8.x4.trans.shared.b16 {%0,%1,%2,%3}, [%4];"
        : "=r"(r0), "=r"(r1), "=r"(r2), "=r"(r3) : "r"(a));
}
__device__ __forceinline__ void stcs2(float* p, float a, float b) {
    asm volatile("st.global.cs.v2.f32 [%0], {%1,%2};" :: "l"(p), "f"(a), "f"(b) : "memory");
}
__device__ __forceinline__ void stcs_u32(__half* p, unsigned v) {
    asm volatile("st.global.cs.b32 [%0], %1;" :: "l"(p), "r"(v) : "memory");
}

// ---------------- fp32 -> f16 single (3 inputs merged) ----------------
__global__ __launch_bounds__(256) void conv3_kernel(
    const float* __restrict__ s0, const float* __restrict__ s1, const float* __restrict__ s2,
    __half* __restrict__ dst, int n4)
{
    int b = blockIdx.x;
    int sel = b / (n4 / 256);
    int i = (b % (n4 / 256)) * 256 + threadIdx.x;
    const float* src = sel == 0 ? s0 : (sel == 1 ? s1 : s2);
    float4 v = __ldcs(&((const float4*)src)[i]);
    ((uint2*)dst)[(size_t)sel * n4 + i] = make_uint2(pack_f16(v.x, v.y), pack_f16(v.z, v.w));
}

// ---------------- weights: 4 -> f16 single ----------------
__global__ __launch_bounds__(256) void wconv_kernel(
    const float* __restrict__ s0, const float* __restrict__ s1,
    const float* __restrict__ s2, const float* __restrict__ s3,
    __half* __restrict__ hi, int n4)
{
    int b = blockIdx.x;
    int sel = b / (n4 / 256);
    int i = (b % (n4 / 256)) * 256 + threadIdx.x;
    const float* src = sel == 0 ? s0 : (sel == 1 ? s1 : (sel == 2 ? s2 : s3));
    float4 v = __ldcs(&((const float4*)src)[i]);
    ((uint2*)hi)[(size_t)sel * n4 + i] = make_uint2(pack_f16(v.x, v.y), pack_f16(v.z, v.w));
}

// ---------------- GEMM core: K-chunk 64 per stage, 3 stages ----------------
#define GSTG 32768
#define GEMM_SMEM (3*GSTG)
#define NE_C ((size_t)NTOK * DD)
#define WE_C ((size_t)DD * DD)

__global__ __launch_bounds__(256, 2) void qkv_gemm(
    const __half* __restrict__ inf, const __half* __restrict__ whi,
    __half* __restrict__ qf, __half* __restrict__ kf, __half* __restrict__ vf)
{
    extern __shared__ __half gsm[];
    const int tid = threadIdx.x;
    const int lane = tid & 31, wid = tid >> 5;
    const int wm = wid & 1, wn = wid >> 1;
    const int g = lane >> 2, q = lane & 3;
    const int lrow = (lane & 7) + ((lane >> 3) & 1) * 8;
    const int lch  = lane >> 4;
    const int px = blockIdx.x >> 2;
    const int n0 = (blockIdx.x & 3) * 128, m0 = blockIdx.y * 128;
    const int K = DD, N = DD;
    uint32_t sb = (uint32_t)__cvta_generic_to_shared(gsm);

    const __half* Af  = inf + (size_t)px * NE_C;
    const __half* Bhi = whi + (size_t)px * WE_C;

    auto issue = [&](int grp) {
        int k0 = grp << 6;
        uint32_t stg = sb + (grp % 3) * GSTG;
#pragma unroll
        for (int j = 0; j < 8; j++) {
            int idx = tid + (j & 3) * 256;
            int sub = j >> 2;
            int row = idx >> 3, ch = idx & 7;
            const __half* gp = (sub == 0 ? Af + (size_t)(m0 + row) * K
                                         : Bhi + (size_t)(n0 + row) * K) + k0 + ch * 8;
            cpa16(stg + sub * 16384 + row * 128 + (((ch ^ (row & 7))) << 4), gp);
        }
        asm volatile("cp.async.commit_group;");
    };

    float acc[4][4][4] = {};
    const int nIter = K >> 6;   // 8
    issue(0); issue(1);

    for (int it = 0; it < nIter; it++) {
        if (it < nIter - 1) asm volatile("cp.async.wait_group 1;");
        else                asm volatile("cp.async.wait_group 0;");
        __syncthreads();
        if (it + 2 < nIter) issue(it + 2);
        uint32_t bufb = sb + (it % 3) * GSTG;
#pragma unroll
        for (int kb = 0; kb < 64; kb += 16) {
            int c0 = kb >> 3;
            unsigned af[4][4];
#pragma unroll
            for (int i = 0; i < 4; i++) {
                int row = wm * 64 + i * 16 + lrow;
                uint32_t a = bufb + row * 128 + ((((c0 + lch) ^ (row & 7))) << 4);
                ldsm4(af[i][0], af[i][1], af[i][2], af[i][3], a);
            }
            unsigned bh[2][4];
#pragma unroll
            for (int p = 0; p < 2; p++) {
                int row = wn * 32 + p * 16 + lrow;
                uint32_t b = bufb + 16384 + row * 128 + ((((c0 + lch) ^ (row & 7))) << 4);
                ldsm4(bh[p][0], bh[p][1], bh[p][2], bh[p][3], b);
            }
#pragma unroll
            for (int j = 0; j < 4; j++) {
                int p = j >> 1, o = j & 1;
                unsigned b0 = bh[p][o], b1 = bh[p][o + 2];
#pragma unroll
                for (int i = 0; i < 4; i++)
                    mma16816(acc[i][j], af[i][0], af[i][1], af[i][2], af[i][3], b0, b1);
            }
        }
    }

    __half* Chi = px == 0 ? qf : (px == 1 ? kf : vf);
#pragma unroll
    for (int i = 0; i < 4; i++) {
#pragma unroll
        for (int j = 0; j < 4; j++) {
            int row = m0 + wm * 64 + i * 16 + g;
            int col = n0 + wn * 32 + j * 8 + 2 * q;
            stcs_u32(&Chi[(size_t)row * N + col],       pack_f16(acc[i][j][0], acc[i][j][1]));
            stcs_u32(&Chi[(size_t)(row + 8) * N + col], pack_f16(acc[i][j][2], acc[i][j][3]));
        }
    }
}

// FC GEMM: same core; outp stores stay normal (L2-resident for LN)
__global__ __launch_bounds__(256, 2) void fc_gemm(
    const __half* __restrict__ Af, const __half* __restrict__ Bhi,
    __half* __restrict__ Chi)
{
    extern __shared__ __half gsm[];
    const int tid = threadIdx.x;
    const int lane = tid & 31, wid = tid >> 5;
    const int wm = wid & 1, wn = wid >> 1;
    const int g = lane >> 2, q = lane & 3;
    const int lrow = (lane & 7) + ((lane >> 3) & 1) * 8;
    const int lch  = lane >> 4;
    const int n0 = blockIdx.x * 128, m0 = blockIdx.y * 128;
    const int K = DD, N = DD;
    uint32_t sb = (uint32_t)__cvta_generic_to_shared(gsm);

    auto issue = [&](int grp) {
        int k0 = grp << 6;
        uint32_t stg = sb + (grp % 3) * GSTG;
#pragma unroll
        for (int j = 0; j < 8; j++) {
            int idx = tid + (j & 3) * 256;
            int sub = j >> 2;
            int row = idx >> 3, ch = idx & 7;
            const __half* gp = (sub == 0 ? Af + (size_t)(m0 + row) * K
                                         : Bhi + (size_t)(n0 + row) * K) + k0 + ch * 8;
            cpa16(stg + sub * 16384 + row * 128 + (((ch ^ (row & 7))) << 4), gp);
        }
        asm volatile("cp.async.commit_group;");
    };

    float acc[4][4][4] = {};
    const int nIter = K >> 6;
    issue(0); issue(1);

    for (int it = 0; it < nIter; it++) {
        if (it < nIter - 1) asm volatile("cp.async.wait_group 1;");
        else                asm volatile("cp.async.wait_group 0;");
        __syncthreads();
        if (it + 2 < nIter) issue(it + 2);
        uint32_t bufb = sb + (it % 3) * GSTG;
#pragma unroll
        for (int kb = 0; kb < 64; kb += 16) {
            int c0 = kb >> 3;
            unsigned af[4][4];
#pragma unroll
            for (int i = 0; i < 4; i++) {
                int row = wm * 64 + i * 16 + lrow;
                uint32_t a = bufb + row * 128 + ((((c0 + lch) ^ (row & 7))) << 4);
                ldsm4(af[i][0], af[i][1], af[i][2], af[i][3], a);
            }
            unsigned bh[2][4];
#pragma unroll
            for (int p = 0; p < 2; p++) {
                int row = wn * 32 + p * 16 + lrow;
                uint32_t b = bufb + 16384 + row * 128 + ((((c0 + lch) ^ (row & 7))) << 4);
                ldsm4(bh[p][0], bh[p][1], bh[p][2], bh[p][3], b);
            }
#pragma unroll
            for (int j = 0; j < 4; j++) {
                int p = j >> 1, o = j & 1;
                unsigned b0 = bh[p][o], b1 = bh[p][o + 2];
#pragma unroll
                for (int i = 0; i < 4; i++)
                    mma16816(acc[i][j], af[i][0], af[i][1], af[i][2], af[i][3], b0, b1);
            }
        }
    }

#pragma unroll
    for (int i = 0; i < 4; i++) {
#pragma unroll
        for (int j = 0; j < 4; j++) {
            int row = m0 + wm * 64 + i * 16 + g;
            int col = n0 + wn * 32 + j * 8 + 2 * q;
            *(unsigned*)&Chi[(size_t)row * N + col]       = pack_f16(acc[i][j][0], acc[i][j][1]);
            *(unsigned*)&Chi[(size_t)(row + 8) * N + col] = pack_f16(acc[i][j][2], acc[i][j][3]);
        }
    }
}

// ---------------- attention (unchanged) ----------------
#define AK_OFF  0
#define AV_OFF  16384
#define AQ_OFF  32768
#define AP_OFF  32768
#define AM_OFF  65536
#define ASTM_OFF 81920
#define ASTS_OFF 83968
#define ATTN_SMEM 86016

__global__ __launch_bounds__(256, 2) void attn_mma(
    const __half* __restrict__ qf,
    const __half* __restrict__ kf, const __half* __restrict__ vf,
    const void* __restrict__ mask, float* __restrict__ attn_out,
    __half* __restrict__ resf)
{
    extern __shared__ char smc[];
    uint32_t sb = (uint32_t)__cvta_generic_to_shared(smc);
    float* stM = (float*)(smc + ASTM_OFF);
    float* stS = (float*)(smc + ASTS_OFF);

    const int tid = threadIdx.x;
    const int lane = tid & 31, wid = tid >> 5;
    const int g = lane >> 2, q = lane & 3;
    const int lrow = (lane & 7) + ((lane >> 3) & 1) * 8;
    const int lch  = lane >> 4;
    const int h  = blockIdx.x & 7;
    const int bn = blockIdx.x >> 3;
    const int kind = g_flag_not01 ? 2 : (g_flag_float ? 1 : 0);

    const size_t base = (size_t)bn * 128 * DD + (size_t)h * 64;

    {
#pragma unroll
        for (int t = 0; t < 4; t++) {
            int idx = tid + t * 256;
            int row = idx >> 3, ch = idx & 7;
            uint32_t sw = row * 128 + (((ch ^ (row & 7))) << 4);
            size_t go = base + (size_t)row * DD + ch * 8;
            cpa16(sb + AK_OFF + sw, kf + go);
            cpa16(sb + AQ_OFF + sw, qf + go);
        }
        asm volatile("cp.async.commit_group;");
    }
    {
#pragma unroll
        for (int t = 0; t < 4; t++) {
            int idx = tid + t * 256;
            int row = idx >> 3, ch = idx & 7;
            uint32_t sw = row * 128 + (((ch ^ (row & 7))) << 4);
            cpa16(sb + AV_OFF + sw, vf + base + (size_t)row * DD + ch * 8);
        }
        if (kind == 2) {
#pragma unroll
            for (int t = 0; t < 4; t++) {
                int idx = tid + t * 256;
                int row = idx >> 3, ch = idx & 7;
                cpa16(sb + AM_OFF + row * 128 + ch * 16,
                      (const unsigned char*)mask + (size_t)bn * 16384 + (size_t)row * 128 + ch * 16);
            }
        }
        asm volatile("cp.async.commit_group;");
    }
    asm volatile("cp.async.wait_group 1;");
    __syncthreads();

    const int wm = wid & 1, wn = wid >> 1;

    float acc[4][4][4] = {};
#pragma unroll
    for (int kb = 0; kb < 64; kb += 16) {
        int c0 = kb >> 3;
        unsigned ah[4][4];
#pragma unroll
        for (int i = 0; i < 4; i++) {
            int row = wm * 64 + i * 16 + lrow;
            uint32_t a = sb + AQ_OFF + row * 128 + ((((c0 + lch) ^ (row & 7))) << 4);
            ldsm4(ah[i][0], ah[i][1], ah[i][2], ah[i][3], a);
        }
        unsigned bk[2][4];
#pragma unroll
        for (int p = 0; p < 2; p++) {
            int row = wn * 32 + p * 16 + lrow;
            uint32_t b = sb + AK_OFF + row * 128 + ((((c0 + lch) ^ (row & 7))) << 4);
            ldsm4(bk[p][0], bk[p][1], bk[p][2], bk[p][3], b);
        }
#pragma unroll
        for (int j = 0; j < 4; j++) {
            int p = j >> 1, o = j & 1;
            unsigned b0 = bk[p][o], b1 = bk[p][o + 2];
#pragma unroll
            for (int i = 0; i < 4; i++)
                mma16816(acc[i][j], ah[i][0], ah[i][1], ah[i][2], ah[i][3], b0, b1);
        }
    }

    asm volatile("cp.async.wait_group 0;");
    __syncthreads();

#pragma unroll
    for (int i = 0; i < 4; i++) {
#pragma unroll
        for (int hf = 0; hf < 2; hf++) {
            int r = wm * 64 + i * 16 + g + hf * 8;
#pragma unroll
            for (int j = 0; j < 4; j++) {
                int c = wn * 32 + j * 8 + 2 * q;
                float m0, m1;
                if (kind == 2) {
                    uchar2 mk = *(const uchar2*)(smc + AM_OFF + r * 128 + c);
                    m0 = mk.x ? 0.f : -1e9f; m1 = mk.y ? 0.f : -1e9f;
                } else if (kind == 1) {
                    float2 mk = *(const float2*)((const float*)mask + (size_t)bn * 16384 + (size_t)r * 128 + c);
                    m0 = (mk.x != 0.f) ? 0.f : -1e9f; m1 = (mk.y != 0.f) ? 0.f : -1e9f;
                } else {
                    int2 mk = *(const int2*)((const int*)mask + (size_t)bn * 16384 + (size_t)r * 128 + c);
                    m0 = mk.x ? 0.f : -1e9f; m1 = mk.y ? 0.f : -1e9f;
                }
                acc[i][j][2 * hf]     = acc[i][j][2 * hf]     * 0.125f + m0;
                acc[i][j][2 * hf + 1] = acc[i][j][2 * hf + 1] * 0.125f + m1;
            }
        }
    }

#pragma unroll
    for (int i = 0; i < 4; i++)
#pragma unroll
        for (int hf = 0; hf < 2; hf++) {
            float m = -3.4e38f;
#pragma unroll
            for (int j = 0; j < 4; j++)
                m = fmaxf(m, fmaxf(acc[i][j][2 * hf], acc[i][j][2 * hf + 1]));
            m = fmaxf(m, __shfl_xor_sync(0xffffffffu, m, 1));
            m = fmaxf(m, __shfl_xor_sync(0xffffffffu, m, 2));
            if (q == 0) stM[(wm * 64 + i * 16 + g + hf * 8) * 4 + wn] = m;
        }
    __syncthreads();

    float inv[4][2];
#pragma unroll
    for (int i = 0; i < 4; i++)
#pragma unroll
        for (int hf = 0; hf < 2; hf++) {
            int r = wm * 64 + i * 16 + g + hf * 8;
            float gm = fmaxf(fmaxf(stM[r * 4], stM[r * 4 + 1]), fmaxf(stM[r * 4 + 2], stM[r * 4 + 3]));
            float s = 0.f;
#pragma unroll
            for (int j = 0; j < 4; j++) {
                float e0 = __expf(acc[i][j][2 * hf]     - gm);
                float e1 = __expf(acc[i][j][2 * hf + 1] - gm);
                acc[i][j][2 * hf] = e0; acc[i][j][2 * hf + 1] = e1;
                s += e0 + e1;
            }
            s += __shfl_xor_sync(0xffffffffu, s, 1);
            s += __shfl_xor_sync(0xffffffffu, s, 2);
            if (q == 0) stS[r * 4 + wn] = s;
        }
    __syncthreads();

#pragma unroll
    for (int i = 0; i < 4; i++)
#pragma unroll
        for (int hf = 0; hf < 2; hf++) {
            int r = wm * 64 + i * 16 + g + hf * 8;
            inv[i][hf] = 1.0f / (stS[r * 4] + stS[r * 4 + 1] + stS[r * 4 + 2] + stS[r * 4 + 3]);
        }

    {
        float* aout = attn_out + ((size_t)(bn * 8 + h)) * 16384;
#pragma unroll
        for (int i = 0; i < 4; i++)
#pragma unroll
            for (int hf = 0; hf < 2; hf++) {
                int r = wm * 64 + i * 16 + g + hf * 8;
                float iv = inv[i][hf];
#pragma unroll
                for (int j = 0; j < 4; j++) {
                    int c = wn * 32 + j * 8 + 2 * q;
                    float p0 = acc[i][j][2 * hf] * iv;
                    float p1 = acc[i][j][2 * hf + 1] * iv;
                    stcs2(&aout[(size_t)r * 128 + c], p0, p1);
                    uint32_t off = r * 256 + ((((c >> 3) ^ (r & 7))) << 4) + (c & 7) * 2;
                    *(unsigned*)(smc + AP_OFF + off) = pack_f16(p0, p1);
                }
            }
    }
    __syncthreads();

    float ao[4][2][4] = {};
#pragma unroll
    for (int kb = 0; kb < 8; kb++) {
        int c0 = kb * 2;
        unsigned ph[4][4];
#pragma unroll
        for (int i = 0; i < 4; i++) {
            int row = wm * 64 + i * 16 + lrow;
            uint32_t a = sb + AP_OFF + row * 256 + ((((c0 + lch) ^ (row & 7))) << 4);
            ldsm4(ph[i][0], ph[i][1], ph[i][2], ph[i][3], a);
        }
        int vrow = kb * 16 + lrow;
        uint32_t vb = sb + AV_OFF + vrow * 128 + ((((wn * 2 + lch) ^ (vrow & 7))) << 4);
        unsigned vv[4];
        ldsm4t(vv[0], vv[1], vv[2], vv[3], vb);
#pragma unroll
        for (int j = 0; j < 2; j++) {
            unsigned b0 = vv[2 * j], b1 = vv[2 * j + 1];
#pragma unroll
            for (int i = 0; i < 4; i++)
                mma16816(ao[i][j], ph[i][0], ph[i][1], ph[i][2], ph[i][3], b0, b1);
        }
    }

#pragma unroll
    for (int i = 0; i < 4; i++)
#pragma unroll
        for (int j = 0; j < 2; j++) {
            int row = wm * 64 + i * 16 + g;
            int col = h * 64 + wn * 16 + j * 8 + 2 * q;
            size_t o0 = ((size_t)(bn * 128 + row)) * DD + col;
            size_t o1 = o0 + 8ull * DD;
            *(unsigned*)&resf[o0] = pack_f16(ao[i][j][0], ao[i][j][1]);
            *(unsigned*)&resf[o1] = pack_f16(ao[i][j][2], ao[i][j][3]);
        }
}

// ---------------- residual + LayerNorm: warp per row, f16 residual ----------------
__global__ __launch_bounds__(256) void ln_kernel(
    const __half* __restrict__ O, const __half* __restrict__ Xh,
    const float* __restrict__ gamma, const float* __restrict__ beta,
    float* __restrict__ Y)
{
    const int lane = threadIdx.x & 31, w = threadIdx.x >> 5;
    const size_t row = (size_t)blockIdx.x * 8 + w;
    const size_t base = row * DD;

    float x[16];
    float s = 0.f, s2 = 0.f;
#pragma unroll
    for (int c = 0; c < 4; c++) {
        int col = c * 128 + lane * 4;
        uint2 o2 = *(const uint2*)&O[base + col];
        uint2 x2 = *(const uint2*)&Xh[base + col];
        float v0 = f16lo(o2.x) + f16lo(x2.x);
        float v1 = f16hi(o2.x) + f16hi(x2.x);
        float v2 = f16lo(o2.y) + f16lo(x2.y);
        float v3 = f16hi(o2.y) + f16hi(x2.y);
        x[c * 4 + 0] = v0; x[c * 4 + 1] = v1; x[c * 4 + 2] = v2; x[c * 4 + 3] = v3;
        s  += v0 + v1 + v2 + v3;
        s2 += v0 * v0 + v1 * v1 + v2 * v2 + v3 * v3;
    }
#pragma unroll
    for (int o = 16; o; o >>= 1) {
        s  += __shfl_xor_sync(0xffffffffu, s,  o);
        s2 += __shfl_xor_sync(0xffffffffu, s2, o);
    }
    float mean = s * (1.0f / DD);
    float var  = s2 * (1.0f / DD) - mean * mean;
    float inv  = rsqrtf(var + 1e-5f);

#pragma unroll
    for (int c = 0; c < 4; c++) {
        int col = c * 128 + lane * 4;
        float4 gm = *(const float4*)&gamma[col];
        float4 bt = *(const float4*)&beta[col];
        float4 yv;
        yv.x = (x[c * 4 + 0] - mean) * inv * gm.x + bt.x;
        yv.y = (x[c * 4 + 1] - mean) * inv * gm.y + bt.y;
        yv.z = (x[c * 4 + 2] - mean) * inv * gm.z + bt.z;
        yv.w = (x[c * 4 + 3] - mean) * inv * gm.w + bt.w;
        *(float4*)&Y[base + col] = yv;
    }
}

// ---------------- launch ----------------
extern "C" void kernel_launch(void* const* d_in, const int* in_sizes, int n_in,
                              void* d_out, int out_size)
{
    const float* Q     = (const float*)d_in[0];
    const float* K     = (const float*)d_in[1];
    const float* V     = (const float*)d_in[2];
    const void*  mask  = d_in[3];
    const float* WQ    = (const float*)d_in[4];
    const float* WK    = (const float*)d_in[5];
    const float* WV    = (const float*)d_in[6];
    const float* Wfc   = (const float*)d_in[7];
    const float* gamma = (const float*)d_in[8];
    const float* beta  = (const float*)d_in[9];

    float* y    = (float*)d_out;
    float* attn = y + (size_t)YSIZE;

    void *p;
    cudaGetSymbolAddress(&p, g_inf);  __half* inf  = (__half*)p;
    cudaGetSymbolAddress(&p, g_whi);  __half* whi  = (__half*)p;
    cudaGetSymbolAddress(&p, g_qf);   __half* qfp  = (__half*)p;
    cudaGetSymbolAddress(&p, g_kf);   __half* kfp  = (__half*)p;
    cudaGetSymbolAddress(&p, g_vf);   __half* vfp  = (__half*)p;
    cudaGetSymbolAddress(&p, g_resf); __half* resf = (__half*)p;
    cudaGetSymbolAddress(&p, g_outp); __half* outp = (__half*)p;

    cudaFuncSetAttribute(qkv_gemm, cudaFuncAttributeMaxDynamicSharedMemorySize, GEMM_SMEM);
    cudaFuncSetAttribute(fc_gemm,  cudaFuncAttributeMaxDynamicSharedMemorySize, GEMM_SMEM);
    cudaFuncSetAttribute(attn_mma, cudaFuncAttributeMaxDynamicSharedMemorySize, ATTN_SMEM);

    detect_reset<<<1, 1>>>();
    detect_scan<<<64, 256>>>((const uint4*)mask);

    const int n4 = (int)(NE_C / 4);
    conv3_kernel<<<3 * (n4 / 256), 256>>>(Q, K, V, inf, n4);
    const int w4 = (int)(WE_C / 4);
    wconv_kernel<<<4 * (w4 / 256), 256>>>(WQ, WK, WV, Wfc, whi, w4);

    qkv_gemm<<<dim3(12, NTOK / 128), 256, GEMM_SMEM>>>(inf, whi, qfp, kfp, vfp);

    attn_mma<<<BB * NNN * HH, 256, ATTN_SMEM>>>(qfp, kfp, vfp, mask, attn, resf);

    fc_gemm<<<dim3(4, NTOK / 128), 256, GEMM_SMEM>>>(resf, whi + 3 * WE_C, outp);

    ln_kernel<<<NTOK / 8, 256>>>(outp, inf, gamma, beta, y);
}

// round 17
// speedup vs baseline: 1.5725x; 1.0037x over previous
#include <cuda_runtime.h>
#include <cuda_fp16.h>
#include <cstdint>

#define BB   16
#define NNN  32
#define SS   128
#define DD   512
#define HH   8
#define NTOK (BB*NNN*SS)          // 65536
#define YSIZE  (NTOK*DD)          // 33554432

// ---------------- scratch ----------------
__device__ __half g_inf[3ull*NTOK*DD];    // inputs Q,K,V single f16
__device__ __half g_whi[4ull*DD*DD];      // weights single f16
__device__ __half g_qf[(size_t)NTOK*DD];
__device__ __half g_kf[(size_t)NTOK*DD];
__device__ __half g_vf[(size_t)NTOK*DD];
__device__ __half g_resf[(size_t)NTOK*DD];
__device__ __half g_outp[(size_t)NTOK*DD];
__device__ int    g_flag_float = 0, g_flag_not01 = 0;   // set idempotently

// ---------------- helpers ----------------
__device__ __forceinline__ unsigned pack_f16(float lo, float hi) {
    __half2 h = __floats2half2_rn(lo, hi);
    return *(unsigned*)&h;
}
__device__ __forceinline__ float f16lo(unsigned u) { return __low2float(*(__half2*)&u); }
__device__ __forceinline__ float f16hi(unsigned u) { return __high2float(*(__half2*)&u); }

__device__ __forceinline__ void mma16816(float c[4],
    unsigned a0, unsigned a1, unsigned a2, unsigned a3, unsigned b0, unsigned b1)
{
    asm volatile(
        "mma.sync.aligned.m16n8k16.row.col.f32.f16.f16.f32 "
        "{%0,%1,%2,%3}, {%4,%5,%6,%7}, {%8,%9}, {%0,%1,%2,%3};"
        : "+f"(c[0]), "+f"(c[1]), "+f"(c[2]), "+f"(c[3])
        : "r"(a0), "r"(a1), "r"(a2), "r"(a3), "r"(b0), "r"(b1));
}
__device__ __forceinline__ void cpa16(uint32_t s, const void* g) {
    asm volatile("cp.async.cg.shared.global [%0], [%1], 16;" :: "r"(s), "l"(g));
}
__device__ __forceinline__ void ldsm4(unsigned& r0, unsigned& r1, unsigned& r2, unsigned& r3, uint32_t a) {
    asm volatile("ldmatrix.sync.aligned.m8n8.x4.shared.b16 {%0,%1,%2,%3}, [%4];"
        : "=r"(r0), "=r"(r1), "=r"(r2), "=r"(r3) : "r"(a));
}
__device__ __forceinline__ void ldsm4t(unsigned& r0, unsigned& r1, unsigned& r2, unsigned& r3, uint32_t a) {
    asm volatile("ldmatrix.sync.aligned.m8n8.x4.trans.shared.b16 {%0,%1,%2,%3}, [%4];"
        : "=r"(r0), "=r"(r1), "=r"(r2), "=r"(r3) : "r"(a));
}
__device__ __forceinline__ void stcs2(float* p, float a, float b) {
    asm volatile("st.global.cs.v2.f32 [%0], {%1,%2};" :: "l"(p), "f"(a), "f"(b) : "memory");
}
__device__ __forceinline__ void stcs_u32(__half* p, unsigned v) {
    asm volatile("st.global.cs.b32 [%0], %1;" :: "l"(p), "r"(v) : "memory");
}

// ---------------- fp32 -> f16 single (3 inputs merged) ----------------
__global__ __launch_bounds__(256) void conv3_kernel(
    const float* __restrict__ s0, const float* __restrict__ s1, const float* __restrict__ s2,
    __half* __restrict__ dst, int n4)
{
    int b = blockIdx.x;
    int sel = b / (n4 / 256);
    int i = (b % (n4 / 256)) * 256 + threadIdx.x;
    const float* src = sel == 0 ? s0 : (sel == 1 ? s1 : s2);
    float4 v = __ldcs(&((const float4*)src)[i]);
    ((uint2*)dst)[(size_t)sel * n4 + i] = make_uint2(pack_f16(v.x, v.y), pack_f16(v.z, v.w));
}

// ---------------- weights: 4 -> f16 single; first 64 blocks also scan mask ----------------
__global__ __launch_bounds__(256) void wconv_kernel(
    const float* __restrict__ s0, const float* __restrict__ s1,
    const float* __restrict__ s2, const float* __restrict__ s3,
    __half* __restrict__ hi, const uint4* __restrict__ mw, int n4)
{
    int b = blockIdx.x;
    int sel = b / (n4 / 256);
    int i = (b % (n4 / 256)) * 256 + threadIdx.x;
    const float* src = sel == 0 ? s0 : (sel == 1 ? s1 : (sel == 2 ? s2 : s3));
    float4 v = __ldcs(&((const float4*)src)[i]);
    ((uint2*)hi)[(size_t)sel * n4 + i] = make_uint2(pack_f16(v.x, v.y), pack_f16(v.z, v.w));

    if (b < 64) {
        uint4 w = __ldcs(&mw[b * 256 + threadIdx.x]);
        int isf = (w.x == 0x3f800000u) | (w.y == 0x3f800000u) | (w.z == 0x3f800000u) | (w.w == 0x3f800000u);
        int n01 = ((w.x > 1u) & (w.x != 0x3f800000u)) | ((w.y > 1u) & (w.y != 0x3f800000u))
                | ((w.z > 1u) & (w.z != 0x3f800000u)) | ((w.w > 1u) & (w.w != 0x3f800000u));
        int bf = __syncthreads_or(isf);
        int bn = __syncthreads_or(n01);
        if (threadIdx.x == 0) {
            if (bf) atomicOr(&g_flag_float, 1);
            if (bn) atomicOr(&g_flag_not01, 1);
        }
    }
}

// ---------------- GEMM core: K-chunk 64 per stage, 3 stages ----------------
#define GSTG 32768
#define GEMM_SMEM (3*GSTG)
#define NE_C ((size_t)NTOK * DD)
#define WE_C ((size_t)DD * DD)

__global__ __launch_bounds__(256, 2) void qkv_gemm(
    const __half* __restrict__ inf, const __half* __restrict__ whi,
    __half* __restrict__ qf, __half* __restrict__ kf, __half* __restrict__ vf)
{
    extern __shared__ __half gsm[];
    const int tid = threadIdx.x;
    const int lane = tid & 31, wid = tid >> 5;
    const int wm = wid & 1, wn = wid >> 1;
    const int g = lane >> 2, q = lane & 3;
    const int lrow = (lane & 7) + ((lane >> 3) & 1) * 8;
    const int lch  = lane >> 4;
    const int px = blockIdx.x >> 2;
    const int n0 = (blockIdx.x & 3) * 128, m0 = blockIdx.y * 128;
    const int K = DD, N = DD;
    uint32_t sb = (uint32_t)__cvta_generic_to_shared(gsm);

    const __half* Af  = inf + (size_t)px * NE_C;
    const __half* Bhi = whi + (size_t)px * WE_C;

    auto issue = [&](int grp) {
        int k0 = grp << 6;
        uint32_t stg = sb + (grp % 3) * GSTG;
#pragma unroll
        for (int j = 0; j < 8; j++) {
            int idx = tid + (j & 3) * 256;
            int sub = j >> 2;
            int row = idx >> 3, ch = idx & 7;
            const __half* gp = (sub == 0 ? Af + (size_t)(m0 + row) * K
                                         : Bhi + (size_t)(n0 + row) * K) + k0 + ch * 8;
            cpa16(stg + sub * 16384 + row * 128 + (((ch ^ (row & 7))) << 4), gp);
        }
        asm volatile("cp.async.commit_group;");
    };

    float acc[4][4][4] = {};
    const int nIter = K >> 6;   // 8
    issue(0); issue(1);

    for (int it = 0; it < nIter; it++) {
        if (it < nIter - 1) asm volatile("cp.async.wait_group 1;");
        else                asm volatile("cp.async.wait_group 0;");
        __syncthreads();
        if (it + 2 < nIter) issue(it + 2);
        uint32_t bufb = sb + (it % 3) * GSTG;
#pragma unroll
        for (int kb = 0; kb < 64; kb += 16) {
            int c0 = kb >> 3;
            unsigned af[4][4];
#pragma unroll
            for (int i = 0; i < 4; i++) {
                int row = wm * 64 + i * 16 + lrow;
                uint32_t a = bufb + row * 128 + ((((c0 + lch) ^ (row & 7))) << 4);
                ldsm4(af[i][0], af[i][1], af[i][2], af[i][3], a);
            }
            unsigned bh[2][4];
#pragma unroll
            for (int p = 0; p < 2; p++) {
                int row = wn * 32 + p * 16 + lrow;
                uint32_t b = bufb + 16384 + row * 128 + ((((c0 + lch) ^ (row & 7))) << 4);
                ldsm4(bh[p][0], bh[p][1], bh[p][2], bh[p][3], b);
            }
#pragma unroll
            for (int j = 0; j < 4; j++) {
                int p = j >> 1, o = j & 1;
                unsigned b0 = bh[p][o], b1 = bh[p][o + 2];
#pragma unroll
                for (int i = 0; i < 4; i++)
                    mma16816(acc[i][j], af[i][0], af[i][1], af[i][2], af[i][3], b0, b1);
            }
        }
    }

    __half* Chi = px == 0 ? qf : (px == 1 ? kf : vf);
#pragma unroll
    for (int i = 0; i < 4; i++) {
#pragma unroll
        for (int j = 0; j < 4; j++) {
            int row = m0 + wm * 64 + i * 16 + g;
            int col = n0 + wn * 32 + j * 8 + 2 * q;
            stcs_u32(&Chi[(size_t)row * N + col],       pack_f16(acc[i][j][0], acc[i][j][1]));
            stcs_u32(&Chi[(size_t)(row + 8) * N + col], pack_f16(acc[i][j][2], acc[i][j][3]));
        }
    }
}

// FC GEMM
__global__ __launch_bounds__(256, 2) void fc_gemm(
    const __half* __restrict__ Af, const __half* __restrict__ Bhi,
    __half* __restrict__ Chi)
{
    extern __shared__ __half gsm[];
    const int tid = threadIdx.x;
    const int lane = tid & 31, wid = tid >> 5;
    const int wm = wid & 1, wn = wid >> 1;
    const int g = lane >> 2, q = lane & 3;
    const int lrow = (lane & 7) + ((lane >> 3) & 1) * 8;
    const int lch  = lane >> 4;
    const int n0 = blockIdx.x * 128, m0 = blockIdx.y * 128;
    const int K = DD, N = DD;
    uint32_t sb = (uint32_t)__cvta_generic_to_shared(gsm);

    auto issue = [&](int grp) {
        int k0 = grp << 6;
        uint32_t stg = sb + (grp % 3) * GSTG;
#pragma unroll
        for (int j = 0; j < 8; j++) {
            int idx = tid + (j & 3) * 256;
            int sub = j >> 2;
            int row = idx >> 3, ch = idx & 7;
            const __half* gp = (sub == 0 ? Af + (size_t)(m0 + row) * K
                                         : Bhi + (size_t)(n0 + row) * K) + k0 + ch * 8;
            cpa16(stg + sub * 16384 + row * 128 + (((ch ^ (row & 7))) << 4), gp);
        }
        asm volatile("cp.async.commit_group;");
    };

    float acc[4][4][4] = {};
    const int nIter = K >> 6;
    issue(0); issue(1);

    for (int it = 0; it < nIter; it++) {
        if (it < nIter - 1) asm volatile("cp.async.wait_group 1;");
        else                asm volatile("cp.async.wait_group 0;");
        __syncthreads();
        if (it + 2 < nIter) issue(it + 2);
        uint32_t bufb = sb + (it % 3) * GSTG;
#pragma unroll
        for (int kb = 0; kb < 64; kb += 16) {
            int c0 = kb >> 3;
            unsigned af[4][4];
#pragma unroll
            for (int i = 0; i < 4; i++) {
                int row = wm * 64 + i * 16 + lrow;
                uint32_t a = bufb + row * 128 + ((((c0 + lch) ^ (row & 7))) << 4);
                ldsm4(af[i][0], af[i][1], af[i][2], af[i][3], a);
            }
            unsigned bh[2][4];
#pragma unroll
            for (int p = 0; p < 2; p++) {
                int row = wn * 32 + p * 16 + lrow;
                uint32_t b = bufb + 16384 + row * 128 + ((((c0 + lch) ^ (row & 7))) << 4);
                ldsm4(bh[p][0], bh[p][1], bh[p][2], bh[p][3], b);
            }
#pragma unroll
            for (int j = 0; j < 4; j++) {
                int p = j >> 1, o = j & 1;
                unsigned b0 = bh[p][o], b1 = bh[p][o + 2];
#pragma unroll
                for (int i = 0; i < 4; i++)
                    mma16816(acc[i][j], af[i][0], af[i][1], af[i][2], af[i][3], b0, b1);
            }
        }
    }

#pragma unroll
    for (int i = 0; i < 4; i++) {
#pragma unroll
        for (int j = 0; j < 4; j++) {
            int row = m0 + wm * 64 + i * 16 + g;
            int col = n0 + wn * 32 + j * 8 + 2 * q;
            *(unsigned*)&Chi[(size_t)row * N + col]       = pack_f16(acc[i][j][0], acc[i][j][1]);
            *(unsigned*)&Chi[(size_t)(row + 8) * N + col] = pack_f16(acc[i][j][2], acc[i][j][3]);
        }
    }
}

// ---------------- attention: V-wait deferred past softmax, mask direct-global ----------------
// smem: K @0 (16KB), V @16384 (16KB), Q @32768 (16KB);
// P single f16 aliases 32768..65536; stM @65536; stS @67584.
#define AK_OFF  0
#define AV_OFF  16384
#define AQ_OFF  32768
#define AP_OFF  32768
#define ASTM_OFF 65536
#define ASTS_OFF 67584
#define ATTN_SMEM 69632

__global__ __launch_bounds__(256, 2) void attn_mma(
    const __half* __restrict__ qf,
    const __half* __restrict__ kf, const __half* __restrict__ vf,
    const void* __restrict__ mask, float* __restrict__ attn_out,
    __half* __restrict__ resf)
{
    extern __shared__ char smc[];
    uint32_t sb = (uint32_t)__cvta_generic_to_shared(smc);
    float* stM = (float*)(smc + ASTM_OFF);
    float* stS = (float*)(smc + ASTS_OFF);

    const int tid = threadIdx.x;
    const int lane = tid & 31, wid = tid >> 5;
    const int g = lane >> 2, q = lane & 3;
    const int lrow = (lane & 7) + ((lane >> 3) & 1) * 8;
    const int lch  = lane >> 4;
    const int h  = blockIdx.x & 7;
    const int bn = blockIdx.x >> 3;
    const int kind = g_flag_not01 ? 2 : (g_flag_float ? 1 : 0);

    const size_t base = (size_t)bn * 128 * DD + (size_t)h * 64;

    // group 0: K, Q
    {
#pragma unroll
        for (int t = 0; t < 4; t++) {
            int idx = tid + t * 256;
            int row = idx >> 3, ch = idx & 7;
            uint32_t sw = row * 128 + (((ch ^ (row & 7))) << 4);
            size_t go = base + (size_t)row * DD + ch * 8;
            cpa16(sb + AK_OFF + sw, kf + go);
            cpa16(sb + AQ_OFF + sw, qf + go);
        }
        asm volatile("cp.async.commit_group;");
    }
    // group 1: V only (arrives under QK + softmax)
    {
#pragma unroll
        for (int t = 0; t < 4; t++) {
            int idx = tid + t * 256;
            int row = idx >> 3, ch = idx & 7;
            uint32_t sw = row * 128 + (((ch ^ (row & 7))) << 4);
            cpa16(sb + AV_OFF + sw, vf + base + (size_t)row * DD + ch * 8);
        }
        asm volatile("cp.async.commit_group;");
    }
    asm volatile("cp.async.wait_group 1;");
    __syncthreads();

    const int wm = wid & 1, wn = wid >> 1;

    // QK^T
    float acc[4][4][4] = {};
#pragma unroll
    for (int kb = 0; kb < 64; kb += 16) {
        int c0 = kb >> 3;
        unsigned ah[4][4];
#pragma unroll
        for (int i = 0; i < 4; i++) {
            int row = wm * 64 + i * 16 + lrow;
            uint32_t a = sb + AQ_OFF + row * 128 + ((((c0 + lch) ^ (row & 7))) << 4);
            ldsm4(ah[i][0], ah[i][1], ah[i][2], ah[i][3], a);
        }
        unsigned bk[2][4];
#pragma unroll
        for (int p = 0; p < 2; p++) {
            int row = wn * 32 + p * 16 + lrow;
            uint32_t b = sb + AK_OFF + row * 128 + ((((c0 + lch) ^ (row & 7))) << 4);
            ldsm4(bk[p][0], bk[p][1], bk[p][2], bk[p][3], b);
        }
#pragma unroll
        for (int j = 0; j < 4; j++) {
            int p = j >> 1, o = j & 1;
            unsigned b0 = bk[p][o], b1 = bk[p][o + 2];
#pragma unroll
            for (int i = 0; i < 4; i++)
                mma16816(acc[i][j], ah[i][0], ah[i][1], ah[i][2], ah[i][3], b0, b1);
        }
    }

    // mask (direct global, L2-resident) + scale — no V dependency
#pragma unroll
    for (int i = 0; i < 4; i++) {
#pragma unroll
        for (int hf = 0; hf < 2; hf++) {
            int r = wm * 64 + i * 16 + g + hf * 8;
            size_t mb = (size_t)bn * 16384 + (size_t)r * 128;
#pragma unroll
            for (int j = 0; j < 4; j++) {
                int c = wn * 32 + j * 8 + 2 * q;
                float m0, m1;
                if (kind == 2) {
                    uchar2 mk = *(const uchar2*)((const unsigned char*)mask + mb + c);
                    m0 = mk.x ? 0.f : -1e9f; m1 = mk.y ? 0.f : -1e9f;
                } else if (kind == 1) {
                    float2 mk = *(const float2*)((const float*)mask + mb + c);
                    m0 = (mk.x != 0.f) ? 0.f : -1e9f; m1 = (mk.y != 0.f) ? 0.f : -1e9f;
                } else {
                    int2 mk = *(const int2*)((const int*)mask + mb + c);
                    m0 = mk.x ? 0.f : -1e9f; m1 = mk.y ? 0.f : -1e9f;
                }
                acc[i][j][2 * hf]     = acc[i][j][2 * hf]     * 0.125f + m0;
                acc[i][j][2 * hf + 1] = acc[i][j][2 * hf + 1] * 0.125f + m1;
            }
        }
    }

    // row max (the stM barrier also separates QK's Q-reads from the later P-pack writes)
#pragma unroll
    for (int i = 0; i < 4; i++)
#pragma unroll
        for (int hf = 0; hf < 2; hf++) {
            float m = -3.4e38f;
#pragma unroll
            for (int j = 0; j < 4; j++)
                m = fmaxf(m, fmaxf(acc[i][j][2 * hf], acc[i][j][2 * hf + 1]));
            m = fmaxf(m, __shfl_xor_sync(0xffffffffu, m, 1));
            m = fmaxf(m, __shfl_xor_sync(0xffffffffu, m, 2));
            if (q == 0) stM[(wm * 64 + i * 16 + g + hf * 8) * 4 + wn] = m;
        }
    __syncthreads();

    float inv[4][2];
#pragma unroll
    for (int i = 0; i < 4; i++)
#pragma unroll
        for (int hf = 0; hf < 2; hf++) {
            int r = wm * 64 + i * 16 + g + hf * 8;
            float gm = fmaxf(fmaxf(stM[r * 4], stM[r * 4 + 1]), fmaxf(stM[r * 4 + 2], stM[r * 4 + 3]));
            float s = 0.f;
#pragma unroll
            for (int j = 0; j < 4; j++) {
                float e0 = __expf(acc[i][j][2 * hf]     - gm);
                float e1 = __expf(acc[i][j][2 * hf + 1] - gm);
                acc[i][j][2 * hf] = e0; acc[i][j][2 * hf + 1] = e1;
                s += e0 + e1;
            }
            s += __shfl_xor_sync(0xffffffffu, s, 1);
            s += __shfl_xor_sync(0xffffffffu, s, 2);
            if (q == 0) stS[r * 4 + wn] = s;
        }
    __syncthreads();

#pragma unroll
    for (int i = 0; i < 4; i++)
#pragma unroll
        for (int hf = 0; hf < 2; hf++) {
            int r = wm * 64 + i * 16 + g + hf * 8;
            inv[i][hf] = 1.0f / (stS[r * 4] + stS[r * 4 + 1] + stS[r * 4 + 2] + stS[r * 4 + 3]);
        }

    // normalize + attn_out (streaming) + P f16 pack (aliases Q region; safe post-barriers)
    {
        float* aout = attn_out + ((size_t)(bn * 8 + h)) * 16384;
#pragma unroll
        for (int i = 0; i < 4; i++)
#pragma unroll
            for (int hf = 0; hf < 2; hf++) {
                int r = wm * 64 + i * 16 + g + hf * 8;
                float iv = inv[i][hf];
#pragma unroll
                for (int j = 0; j < 4; j++) {
                    int c = wn * 32 + j * 8 + 2 * q;
                    float p0 = acc[i][j][2 * hf] * iv;
                    float p1 = acc[i][j][2 * hf + 1] * iv;
                    stcs2(&aout[(size_t)r * 128 + c], p0, p1);
                    uint32_t off = r * 256 + ((((c >> 3) ^ (r & 7))) << 4) + (c & 7) * 2;
                    *(unsigned*)(smc + AP_OFF + off) = pack_f16(p0, p1);
                }
            }
    }
    // V completion + make P-pack visible to all warps
    asm volatile("cp.async.wait_group 0;");
    __syncthreads();

    // P @ V
    float ao[4][2][4] = {};
#pragma unroll
    for (int kb = 0; kb < 8; kb++) {
        int c0 = kb * 2;
        unsigned ph[4][4];
#pragma unroll
        for (int i = 0; i < 4; i++) {
            int row = wm * 64 + i * 16 + lrow;
            uint32_t a = sb + AP_OFF + row * 256 + ((((c0 + lch) ^ (row & 7))) << 4);
            ldsm4(ph[i][0], ph[i][1], ph[i][2], ph[i][3], a);
        }
        int vrow = kb * 16 + lrow;
        uint32_t vb = sb + AV_OFF + vrow * 128 + ((((wn * 2 + lch) ^ (vrow & 7))) << 4);
        unsigned vv[4];
        ldsm4t(vv[0], vv[1], vv[2], vv[3], vb);
#pragma unroll
        for (int j = 0; j < 2; j++) {
            unsigned b0 = vv[2 * j], b1 = vv[2 * j + 1];
#pragma unroll
            for (int i = 0; i < 4; i++)
                mma16816(ao[i][j], ph[i][0], ph[i][1], ph[i][2], ph[i][3], b0, b1);
        }
    }

#pragma unroll
    for (int i = 0; i < 4; i++)
#pragma unroll
        for (int j = 0; j < 2; j++) {
            int row = wm * 64 + i * 16 + g;
            int col = h * 64 + wn * 16 + j * 8 + 2 * q;
            size_t o0 = ((size_t)(bn * 128 + row)) * DD + col;
            size_t o1 = o0 + 8ull * DD;
            *(unsigned*)&resf[o0] = pack_f16(ao[i][j][0], ao[i][j][1]);
            *(unsigned*)&resf[o1] = pack_f16(ao[i][j][2], ao[i][j][3]);
        }
}

// ---------------- residual + LayerNorm: warp per row, f16 residual ----------------
__global__ __launch_bounds__(256) void ln_kernel(
    const __half* __restrict__ O, const __half* __restrict__ Xh,
    const float* __restrict__ gamma, const float* __restrict__ beta,
    float* __restrict__ Y)
{
    const int lane = threadIdx.x & 31, w = threadIdx.x >> 5;
    const size_t row = (size_t)blockIdx.x * 8 + w;
    const size_t base = row * DD;

    float x[16];
    float s = 0.f, s2 = 0.f;
#pragma unroll
    for (int c = 0; c < 4; c++) {
        int col = c * 128 + lane * 4;
        uint2 o2 = *(const uint2*)&O[base + col];
        uint2 x2 = *(const uint2*)&Xh[base + col];
        float v0 = f16lo(o2.x) + f16lo(x2.x);
        float v1 = f16hi(o2.x) + f16hi(x2.x);
        float v2 = f16lo(o2.y) + f16lo(x2.y);
        float v3 = f16hi(o2.y) + f16hi(x2.y);
        x[c * 4 + 0] = v0; x[c * 4 + 1] = v1; x[c * 4 + 2] = v2; x[c * 4 + 3] = v3;
        s  += v0 + v1 + v2 + v3;
        s2 += v0 * v0 + v1 * v1 + v2 * v2 + v3 * v3;
    }
#pragma unroll
    for (int o = 16; o; o >>= 1) {
        s  += __shfl_xor_sync(0xffffffffu, s,  o);
        s2 += __shfl_xor_sync(0xffffffffu, s2, o);
    }
    float mean = s * (1.0f / DD);
    float var  = s2 * (1.0f / DD) - mean * mean;
    float inv  = rsqrtf(var + 1e-5f);

#pragma unroll
    for (int c = 0; c < 4; c++) {
        int col = c * 128 + lane * 4;
        float4 gm = *(const float4*)&gamma[col];
        float4 bt = *(const float4*)&beta[col];
        float4 yv;
        yv.x = (x[c * 4 + 0] - mean) * inv * gm.x + bt.x;
        yv.y = (x[c * 4 + 1] - mean) * inv * gm.y + bt.y;
        yv.z = (x[c * 4 + 2] - mean) * inv * gm.z + bt.z;
        yv.w = (x[c * 4 + 3] - mean) * inv * gm.w + bt.w;
        *(float4*)&Y[base + col] = yv;
    }
}

// ---------------- launch ----------------
extern "C" void kernel_launch(void* const* d_in, const int* in_sizes, int n_in,
                              void* d_out, int out_size)
{
    const float* Q     = (const float*)d_in[0];
    const float* K     = (const float*)d_in[1];
    const float* V     = (const float*)d_in[2];
    const void*  mask  = d_in[3];
    const float* WQ    = (const float*)d_in[4];
    const float* WK    = (const float*)d_in[5];
    const float* WV    = (const float*)d_in[6];
    const float* Wfc   = (const float*)d_in[7];
    const float* gamma = (const float*)d_in[8];
    const float* beta  = (const float*)d_in[9];

    float* y    = (float*)d_out;
    float* attn = y + (size_t)YSIZE;

    void *p;
    cudaGetSymbolAddress(&p, g_inf);  __half* inf  = (__half*)p;
    cudaGetSymbolAddress(&p, g_whi);  __half* whi  = (__half*)p;
    cudaGetSymbolAddress(&p, g_qf);   __half* qfp  = (__half*)p;
    cudaGetSymbolAddress(&p, g_kf);   __half* kfp  = (__half*)p;
    cudaGetSymbolAddress(&p, g_vf);   __half* vfp  = (__half*)p;
    cudaGetSymbolAddress(&p, g_resf); __half* resf = (__half*)p;
    cudaGetSymbolAddress(&p, g_outp); __half* outp = (__half*)p;

    cudaFuncSetAttribute(qkv_gemm, cudaFuncAttributeMaxDynamicSharedMemorySize, GEMM_SMEM);
    cudaFuncSetAttribute(fc_gemm,  cudaFuncAttributeMaxDynamicSharedMemorySize, GEMM_SMEM);
    cudaFuncSetAttribute(attn_mma, cudaFuncAttributeMaxDynamicSharedMemorySize, ATTN_SMEM);

    const int n4 = (int)(NE_C / 4);
    conv3_kernel<<<3 * (n4 / 256), 256>>>(Q, K, V, inf, n4);
    const int w4 = (int)(WE_C / 4);
    wconv_kernel<<<4 * (w4 / 256), 256>>>(WQ, WK, WV, Wfc, whi, (const uint4*)mask, w4);

    qkv_gemm<<<dim3(12, NTOK / 128), 256, GEMM_SMEM>>>(inf, whi, qfp, kfp, vfp);

    attn_mma<<<BB * NNN * HH, 256, ATTN_SMEM>>>(qfp, kfp, vfp, mask, attn, resf);

    fc_gemm<<<dim3(4, NTOK / 128), 256, GEMM_SMEM>>>(resf, whi + 3 * WE_C, outp);

    ln_kernel<<<NTOK / 8, 256>>>(outp, inf, gamma, beta, y);
}